// round 10
// baseline (speedup 1.0000x reference)
#include <cuda_runtime.h>
#include <cuda_bf16.h>
#include <math.h>
#include <stdint.h>

#define E_CONST 320000
#define N_CONST 10000
typedef __nv_bfloat16 bf16;

// ---------------- scratch (no allocations allowed) ----------------
static __device__ float    g_vff [(size_t)E_CONST * 64];   // fp32 [sincos48|dist16]
static __device__ float    g_hVW [N_CONST * 128];          // hV @ Wb1_top (fp32, per node)
static __device__ bf16     g_hgh [N_CONST * 128];
static __device__ bf16     g_hgl [N_CONST * 128];
static __device__ bf16     g_wh  [262144];                 // all weights, [n][k]
static __device__ bf16     g_wl  [262144];
static __device__ float    g_sum [N_CONST * 4];
static __device__ float    g_hagg[N_CONST * 128];
static __device__ double   g_bnacc[32];
static __device__ float    g_bnst[32];

// weight plane offsets (elements)
#define OW_RED 0        // 256 x 320
#define OW_B1  81920    // 128 x 384
#define OW_B2  131072   // 128 x 128
#define OW_V1  147456   // 128 x 256
#define OW_V2  180224   // 128 x 128
#define OW_V3  196608   // 128 x 128
#define OW_O   212992   // 128 x 128
#define W_TOTAL 229376

// mega smem tail (beyond the 224KB working set)
#define ATT_OFF 229376
#define CEN_OFF 231424
#define SMEM_MEGA 231936

// ---------------- helpers ----------------
__device__ __forceinline__ uint32_t smem_u32(const void* p) {
    uint32_t a;
    asm("{ .reg .u64 t; cvta.to.shared.u64 t, %1; cvt.u32.u64 %0, t; }" : "=r"(a) : "l"(p));
    return a;
}
__device__ __forceinline__ void cp16(uint32_t dst, const void* src) {
    asm volatile("cp.async.cg.shared.global [%0], [%1], 16;"
        :: "r"(dst), "l"(__cvta_generic_to_global(src)) : "memory");
}
#define CP_COMMIT() asm volatile("cp.async.commit_group;" ::: "memory")
#define CP_WAIT(n)  asm volatile("cp.async.wait_group %0;" :: "n"(n) : "memory")

__device__ __forceinline__ void ldsm4(uint32_t* r, uint32_t addr) {
    asm volatile("ldmatrix.sync.aligned.m8n8.x4.shared.b16 {%0,%1,%2,%3}, [%4];"
        : "=r"(r[0]), "=r"(r[1]), "=r"(r[2]), "=r"(r[3]) : "r"(addr));
}
__device__ __forceinline__ void mma16816(float* d, const uint32_t* a, const uint32_t* b) {
    asm volatile(
        "mma.sync.aligned.m16n8k16.row.col.f32.bf16.bf16.f32 "
        "{%0,%1,%2,%3}, {%4,%5,%6,%7}, {%8,%9}, {%0,%1,%2,%3};"
        : "+f"(d[0]), "+f"(d[1]), "+f"(d[2]), "+f"(d[3])
        : "r"(a[0]), "r"(a[1]), "r"(a[2]), "r"(a[3]), "r"(b[0]), "r"(b[1]));
}
__device__ __forceinline__ void red2(float* addr, float x, float y) {
    asm volatile("red.global.v2.f32.add [%0], {%1, %2};"
        :: "l"(__cvta_generic_to_global(addr)), "f"(x), "f"(y) : "memory");
}
__device__ __forceinline__ float gelu_f(float x) {
    return 0.5f * x * (1.f + erff(x * 0.70710678118654752f));
}

// ---------------- init ----------------
__global__ void init_kernel(float* gsum, float* hagg, double* bnacc, int N)
{
    int i = blockIdx.x * 256 + threadIdx.x;
    if (i < N * 128) hagg[i] = 0.f;
    if (i < N * 4) gsum[i] = 0.f;
    if (i < 32) bnacc[i] = 0.0;
}

// ---------------- geometry + BN stats ----------------
__global__ __launch_bounds__(256)
void geom_kernel(const int* __restrict__ eidx, const float* __restrict__ hvv,
                 const float* __restrict__ frame, const float* __restrict__ Wvec,
                 float* __restrict__ vff, double* __restrict__ bnacc, int E)
{
    __shared__ float Ws[512];
    __shared__ float bsum[16], bsq[16];
    int tid = threadIdx.x;
    for (int i = tid; i < 512; i += 256) Ws[i] = Wvec[i];
    if (tid < 16) { bsum[tid] = 0.f; bsq[tid] = 0.f; }
    __syncthreads();

    int e = blockIdx.x * 256 + tid;
    float dloc[16];
#pragma unroll
    for (int o = 0; o < 16; o++) dloc[o] = 0.f;

    if (e < E) {
        int c = eidx[e];
        int d = eidx[E + e];
        float F[9];
#pragma unroll
        for (int i = 0; i < 9; i++) F[i] = frame[e * 9 + i];
        float vdt[48], vsrc[48];
#pragma unroll
        for (int v = 0; v < 16; v++) {
            float x = hvv[d * 48 + v * 3 + 0];
            float y = hvv[d * 48 + v * 3 + 1];
            float z = hvv[d * 48 + v * 3 + 2];
            vdt[v * 3 + 0] = F[0] * x + F[1] * y + F[2] * z;
            vdt[v * 3 + 1] = F[3] * x + F[4] * y + F[5] * z;
            vdt[v * 3 + 2] = F[6] * x + F[7] * y + F[8] * z;
        }
#pragma unroll
        for (int i = 0; i < 48; i++) vsrc[i] = hvv[c * 48 + i];

#pragma unroll
        for (int o = 0; o < 16; o++) {
            float v0 = vdt[o * 3 + 0], v1 = vdt[o * 3 + 1], v2 = vdt[o * 3 + 2];
#pragma unroll
            for (int v = 0; v < 16; v++) {
                float wa = Ws[o * 32 + v], wb = Ws[o * 32 + 16 + v];
                v0 += wa * vdt[v * 3 + 0] + wb * vsrc[v * 3 + 0];
                v1 += wa * vdt[v * 3 + 1] + wb * vsrc[v * 3 + 1];
                v2 += wa * vdt[v * 3 + 2] + wb * vsrc[v * 3 + 2];
            }
            float dist = sqrtf(v0 * v0 + v1 * v1 + v2 * v2) + 1e-6f;
            float inv = 1.f / dist;
            vff[e * 64 + o * 3 + 0] = v0 * inv;
            vff[e * 64 + o * 3 + 1] = v1 * inv;
            vff[e * 64 + o * 3 + 2] = v2 * inv;
            vff[e * 64 + 48 + o] = dist;
            dloc[o] = dist;
        }
    }

#pragma unroll
    for (int o = 0; o < 16; o++) {
        float v = dloc[o], v2 = v * v;
#pragma unroll
        for (int off = 16; off; off >>= 1) {
            v  += __shfl_down_sync(0xffffffffu, v, off);
            v2 += __shfl_down_sync(0xffffffffu, v2, off);
        }
        if ((tid & 31) == 0) { atomicAdd(&bsum[o], v); atomicAdd(&bsq[o], v2); }
    }
    __syncthreads();
    if (tid < 16) {
        atomicAdd(&bnacc[tid], (double)bsum[tid]);
        atomicAdd(&bnacc[16 + tid], (double)bsq[tid]);
    }
}

__global__ void bn_finalize(const double* __restrict__ acc, const float* __restrict__ g,
                            const float* __restrict__ b, float* __restrict__ st, int E)
{
    int i = threadIdx.x;
    if (i >= 16) return;
    double mean = acc[i] / (double)E;
    double var  = acc[16 + i] / (double)E - mean * mean;
    float s = (float)((double)g[i] / sqrt(var + 1e-5));
    st[i] = s;
    st[16 + i] = b[i] - (float)mean * s;
}

// ---------------- conversion passes ----------------
__global__ void wprep_all(const float* __restrict__ W0, const float* __restrict__ W1,
                          const float* __restrict__ W2, const float* __restrict__ W3,
                          const float* __restrict__ W4, const float* __restrict__ W5,
                          const float* __restrict__ W6,
                          bf16* __restrict__ hi, bf16* __restrict__ lo)
{
    int idx = blockIdx.x * 256 + threadIdx.x;
    if (idx >= W_TOTAL) return;
    const float* src; int K, NT, start;
    if      (idx < OW_B1)  { src = W0; K = 320; NT = 256; start = OW_RED; }
    else if (idx < OW_B2)  { src = W1; K = 384; NT = 128; start = OW_B1; }
    else if (idx < OW_V1)  { src = W2; K = 128; NT = 128; start = OW_B2; }
    else if (idx < OW_V2)  { src = W3; K = 256; NT = 128; start = OW_V1; }
    else if (idx < OW_V3)  { src = W4; K = 128; NT = 128; start = OW_V2; }
    else if (idx < OW_O)   { src = W5; K = 128; NT = 128; start = OW_V3; }
    else                   { src = W6; K = 128; NT = 128; start = OW_O; }
    int local = idx - start;
    int k = local / NT, n = local % NT;
    float v = src[local];
    bf16 h = __float2bfloat16_rn(v);
    hi[start + (size_t)n * K + k] = h;
    lo[start + (size_t)n * K + k] = __float2bfloat16_rn(v - __bfloat162float(h));
}

// hVW = hV @ Wb1[0:128,:]  (exact fp32, per-node)
__global__ __launch_bounds__(256)
void hvw_kernel(const float* __restrict__ hV, const float* __restrict__ Wb1,
                float* __restrict__ hVW, int N)
{
    __shared__ float xs[2][128];
    const int t = threadIdx.x;
    const int which = t >> 7, c = t & 127;
    const int node = blockIdx.x * 2 + which;
    if (node < N) xs[which][c] = hV[(size_t)node * 128 + c];
    __syncthreads();
    if (node >= N) return;
    float s = 0.f;
#pragma unroll 8
    for (int k = 0; k < 128; k++) s += xs[which][k] * Wb1[k * 128 + c];
    hVW[(size_t)node * 128 + c] = s;
}

// hagg -> planes with softmax normalization folded in
__global__ void c2planes_norm(const float* __restrict__ x, const float* __restrict__ gsum,
                              bf16* __restrict__ hi, bf16* __restrict__ lo, int N)
{
    int i = blockIdx.x * 256 + threadIdx.x;
    if (i >= N * 128) return;
    int node = i >> 7, col = i & 127;
    float s = gsum[node * 4 + (col >> 5)];
    float v = x[i] / (s > 0.f ? s : 1.f);
    bf16 h = __float2bfloat16_rn(v);
    hi[i] = h;
    lo[i] = __float2bfloat16_rn(v - __bfloat162float(h));
}

// ================= GEMM building blocks (512 threads, 16 warps = 4m x 4n) =================
template<int NT>
__device__ __forceinline__ void mma_half512(
    float (&acc)[2][NT][4], uint32_t aHi, uint32_t aLo,
    uint32_t bHi, uint32_t bLo, int ks0, int tid)
{
    const int wid = tid >> 5, lane = tid & 31;
    const int wm = wid >> 2, wn = wid & 3;
    const int a_row = wm * 32 + (lane & 7) + ((lane & 8) ? 8 : 0);
    const int a_ub  = (lane & 16) ? 1 : 0;
    const int b_row0 = wn * (NT * 8) + (lane & 7) + ((lane & 16) ? 8 : 0);
    const int b_ub  = (lane & 8) ? 1 : 0;
#pragma unroll
    for (int kss = 0; kss < 2; kss++) {
        const int ks = ks0 + kss;
        uint32_t ahi[2][4], alo[2][4];
#pragma unroll
        for (int mt = 0; mt < 2; mt++) {
            const int r = a_row + mt * 16;
            const int u = ks * 2 + a_ub;
            const uint32_t off = r * 128 + (uint32_t)(((u ^ (r & 7))) << 4);
            ldsm4(ahi[mt], aHi + off);
            ldsm4(alo[mt], aLo + off);
        }
        uint32_t bhi[NT / 2][4], blo[NT / 2][4];
#pragma unroll
        for (int g = 0; g < NT / 2; g++) {
            const int n = b_row0 + g * 16;
            const int u = ks * 2 + b_ub;
            const uint32_t off = n * 128 + (uint32_t)(((u ^ (n & 7))) << 4);
            ldsm4(bhi[g], bHi + off);
            ldsm4(blo[g], bLo + off);
        }
#pragma unroll
        for (int mt = 0; mt < 2; mt++)
#pragma unroll
            for (int ntl = 0; ntl < NT; ntl++) {
                float* a_ = acc[mt][ntl];
                const uint32_t* bh = &bhi[ntl >> 1][(ntl & 1) * 2];
                const uint32_t* bl = &blo[ntl >> 1][(ntl & 1) * 2];
                mma16816(a_, ahi[mt], bh);
                mma16816(a_, ahi[mt], bl);
                mma16816(a_, alo[mt], bh);
            }
    }
}

__device__ __forceinline__ void stage_half(uint32_t dstHi, uint32_t dstLo,
                                           const bf16* __restrict__ Whi,
                                           const bf16* __restrict__ Wlo,
                                           int K, int k0, int half, int rows, int tid)
{
    for (int i = tid; i < rows * 4; i += 512) {
        const int r = i >> 2, u = (i & 3) + half * 4;
        const uint32_t d = r * 128 + (uint32_t)(((u ^ (r & 7))) << 4);
        cp16(dstHi + d, (const char*)(Whi + (size_t)r * K + k0) + u * 16);
        cp16(dstLo + d, (const char*)(Wlo + (size_t)r * K + k0) + u * 16);
    }
    CP_COMMIT();
}

// stage 2 full 64-K chunks (128 rows) of weight planes into dst (hi: +0, lo: +32K)
__device__ __forceinline__ void stage_chunks2(uint32_t dst,
                                              const bf16* __restrict__ Whi,
                                              const bf16* __restrict__ Wlo,
                                              int K, int k0, int tid)
{
    for (int i = tid; i < 2048; i += 512) {
        const int ch = i >> 10, rem = i & 1023;
        const int r = rem >> 3, u = rem & 7;
        const uint32_t d = ch * 16384 + r * 128 + (uint32_t)(((u ^ (r & 7))) << 4);
        cp16(dst + d,         (const char*)(Whi + (size_t)r * K + k0 + ch * 64) + u * 16);
        cp16(dst + 32768 + d, (const char*)(Wlo + (size_t)r * K + k0 + ch * 64) + u * 16);
    }
    CP_COMMIT();
}

template<int NT, typename FA>
__device__ __forceinline__ void run_phase(float (&acc)[2][NT][4], FA addrA,
                                          const bf16* __restrict__ Wh, const bf16* __restrict__ Wl,
                                          int K, int k0base, int nch,
                                          uint32_t bHi, uint32_t bLo, int tid)
{
    stage_half(bHi, bLo, Wh, Wl, K, k0base, 0, 128, tid);
    const int H = nch * 2;
    for (int h = 0; h < H; h++) {
        if (h + 1 < H) {
            stage_half(bHi, bLo, Wh, Wl, K, k0base + ((h + 1) >> 1) * 64, (h + 1) & 1, 128, tid);
            CP_WAIT(1);
        } else {
            CP_WAIT(0);
        }
        __syncthreads();
        uint32_t aHi, aLo;
        addrA(h >> 1, aHi, aLo);
        mma_half512<NT>(acc, aHi, aLo, bHi, bLo, (h & 1) * 2, tid);
        __syncthreads();
    }
}

template<int NT, int ACT>
__device__ __forceinline__ void store_planes512(const float (&acc)[2][NT][4],
                                                char* smemp, uint32_t baseHi, uint32_t baseLo,
                                                const float* __restrict__ bias, int tid)
{
    const int wid = tid >> 5, lane = tid & 31;
    const int wm = wid >> 2, wn = wid & 3;
#pragma unroll
    for (int mt = 0; mt < 2; mt++)
#pragma unroll
        for (int nt = 0; nt < NT; nt++) {
            const int c = wn * (NT * 8) + nt * 8 + (lane & 3) * 2;
            const int kc = c >> 6, kk = c & 63, u = kk >> 3;
            const float b0 = bias ? bias[c] : 0.f;
            const float b1 = bias ? bias[c + 1] : 0.f;
#pragma unroll
            for (int half = 0; half < 2; half++) {
                const int r = wm * 32 + mt * 16 + (lane >> 2) + half * 8;
                float e0 = acc[mt][nt][half * 2] + b0;
                float e1 = acc[mt][nt][half * 2 + 1] + b1;
                if (ACT == 1) { e0 = fmaxf(e0, 0.f); e1 = fmaxf(e1, 0.f); }
                if (ACT == 2) { e0 = gelu_f(e0); e1 = gelu_f(e1); }
                bf16 h0 = __float2bfloat16_rn(e0);
                bf16 h1 = __float2bfloat16_rn(e1);
                __nv_bfloat162 hp; hp.x = h0; hp.y = h1;
                __nv_bfloat162 lp;
                lp.x = __float2bfloat16_rn(e0 - __bfloat162float(h0));
                lp.y = __float2bfloat16_rn(e1 - __bfloat162float(h1));
                const uint32_t ad = kc * 16384 + r * 128 +
                                    (uint32_t)(((u ^ (r & 7))) << 4) + (kk & 7) * 2;
                *(__nv_bfloat162*)(smemp + baseHi + ad) = hp;
                *(__nv_bfloat162*)(smemp + baseLo + ad) = lp;
            }
        }
}

// ---------------- MEGA kernel (512 threads) ----------------
// smem: [0,64K) heHi, [64K,128K) heLo, [128K,192K) xv, [192K,224K) stg,
//       [224K,226K) att (e values), [226K,226.5K) cen
__global__ __launch_bounds__(512, 1)
void mega_kernel(const float* __restrict__ Vff, const float* __restrict__ HE,
                 const float* __restrict__ bn_st,
                 const float* __restrict__ hVW,
                 const int* __restrict__ eidx,
                 const bf16* __restrict__ wredh, const bf16* __restrict__ wredl,
                 const bf16* __restrict__ wb1h, const bf16* __restrict__ wb1l,
                 const float* __restrict__ bb1,
                 const bf16* __restrict__ wb2h, const bf16* __restrict__ wb2l,
                 const float* __restrict__ bb2,
                 const float* __restrict__ Wb3, const float* __restrict__ bb3,
                 const bf16* __restrict__ wv1h, const bf16* __restrict__ wv1l,
                 const float* __restrict__ bv1,
                 const bf16* __restrict__ wv2h, const bf16* __restrict__ wv2l,
                 const float* __restrict__ bv2,
                 const bf16* __restrict__ wv3h, const bf16* __restrict__ wv3l,
                 const float* __restrict__ bv3,
                 float* __restrict__ gsum, float* __restrict__ hagg, int M)
{
    extern __shared__ char smem[];
    const uint32_t sb = smem_u32(smem);
    const uint32_t heHi = sb;
    const uint32_t heLo = sb + 65536;
    const uint32_t xv   = sb + 131072;
    const uint32_t stg  = sb + 196608;
    const int tid = threadIdx.x;
    const int wid = tid >> 5, lane = tid & 31;
    const int row0 = blockIdx.x * 128;

    const int lr = tid >> 2;              // 4 threads per row
    const int arow = (row0 + lr < M) ? (row0 + lr) : (M - 1);
    const int cu0 = (tid & 3) * 4;        // fp32 16B-unit base for A convert

    // ================= P0: hE = [vff_bn | h_E] @ W_red (K=320, N=256) =================
    {
        float acc0[2][8][4];
#pragma unroll
        for (int i = 0; i < 2; i++)
#pragma unroll
            for (int j = 0; j < 8; j++)
#pragma unroll
                for (int q = 0; q < 4; q++) acc0[i][j][q] = 0.f;

        float4 areg[4];
        {
            const float4* pa = (const float4*)(Vff + (size_t)arow * 64);
#pragma unroll
            for (int jj = 0; jj < 4; jj++) areg[jj] = pa[cu0 + jj];
        }
        stage_half(xv + 32768, stg, wredh, wredl, 320, 0, 0, 256, tid);

        for (int kc = 0; kc < 5; kc++) {
            {
                float4 f[4];
#pragma unroll
                for (int jj = 0; jj < 4; jj++) f[jj] = areg[jj];
                if (kc == 0 && cu0 >= 12) {
#pragma unroll
                    for (int jj = 0; jj < 4; jj++) {
                        const int u = cu0 + jj;
                        if (u >= 12) {
                            const int col = u * 4;
                            f[jj].x = fmaf(f[jj].x, bn_st[col - 48], bn_st[col - 32]);
                            f[jj].y = fmaf(f[jj].y, bn_st[col - 47], bn_st[col - 31]);
                            f[jj].z = fmaf(f[jj].z, bn_st[col - 46], bn_st[col - 30]);
                            f[jj].w = fmaf(f[jj].w, bn_st[col - 45], bn_st[col - 29]);
                        }
                    }
                }
#pragma unroll
                for (int jj = 0; jj < 2; jj++) {
                    float v[8] = {f[2 * jj].x, f[2 * jj].y, f[2 * jj].z, f[2 * jj].w,
                                  f[2 * jj + 1].x, f[2 * jj + 1].y, f[2 * jj + 1].z, f[2 * jj + 1].w};
                    uint32_t ph[4], pl[4];
#pragma unroll
                    for (int j = 0; j < 4; j++) {
                        float a = v[2 * j], b = v[2 * j + 1];
                        bf16 ha = __float2bfloat16_rn(a);
                        bf16 hb = __float2bfloat16_rn(b);
                        __nv_bfloat162 hp; hp.x = ha; hp.y = hb;
                        __nv_bfloat162 lp;
                        lp.x = __float2bfloat16_rn(a - __bfloat162float(ha));
                        lp.y = __float2bfloat16_rn(b - __bfloat162float(hb));
                        ph[j] = reinterpret_cast<uint32_t&>(hp);
                        pl[j] = reinterpret_cast<uint32_t&>(lp);
                    }
                    const int un = (cu0 >> 1) + jj;
                    const uint32_t ad = lr * 128 + (uint32_t)(((un ^ (lr & 7))) << 4);
                    *(uint4*)(smem + 131072 + ad)         = make_uint4(ph[0], ph[1], ph[2], ph[3]);
                    *(uint4*)(smem + 131072 + 16384 + ad) = make_uint4(pl[0], pl[1], pl[2], pl[3]);
                }
            }
            if (kc < 4) {
                const float4* pa = (const float4*)(HE + (size_t)arow * 256 + kc * 64);
#pragma unroll
                for (int jj = 0; jj < 4; jj++) areg[jj] = pa[cu0 + jj];
            }
#pragma unroll
            for (int hh = 0; hh < 2; hh++) {
                const int h = kc * 2 + hh;
                if (h + 1 < 10) {
                    stage_half(xv + 32768, stg, wredh, wredl, 320,
                               ((h + 1) >> 1) * 64, (h + 1) & 1, 256, tid);
                    CP_WAIT(1);
                } else {
                    CP_WAIT(0);
                }
                __syncthreads();
                mma_half512<8>(acc0, xv, xv + 16384, xv + 32768, stg, hh * 2, tid);
                __syncthreads();
            }
        }

        store_planes512<8, 0>(acc0, smem, 0, 65536, nullptr, tid);
    }
    __syncthreads();

    // ================= P1: x1 = relu(hVW[center] + hE @ Wb1_bot + bb1), K=256 =================
    float acc1[2][4][4];
#pragma unroll
    for (int i = 0; i < 2; i++)
#pragma unroll
        for (int j = 0; j < 4; j++)
#pragma unroll
            for (int q = 0; q < 4; q++) acc1[i][j][q] = 0.f;
    {
        // stage gathered hVW rows (fp32, 64KB) into xv
        for (int i = tid; i < 4096; i += 512) {
            const int r = i >> 5, u = i & 31;
            int er = row0 + r; if (er >= M) er = M - 1;
            const int cen = eidx[er];
            cp16(xv + r * 512 + u * 16, (const char*)(hVW + (size_t)cen * 128) + u * 16);
        }
        CP_COMMIT();

        run_phase<4>(acc1,
            [&](int kc, uint32_t& aHi, uint32_t& aLo) {
                aHi = heHi + kc * 16384; aLo = heLo + kc * 16384;
            },
            wb1h, wb1l, 384, 128, 4, stg, stg + 16384, tid);

        // epilogue: read hvw into regs, then store x1 planes into xv
        const float* hvws = (const float*)(smem + 131072);
        const int wm = wid >> 2, wn = wid & 3;
        float hv[2][4][2][2];
#pragma unroll
        for (int mt = 0; mt < 2; mt++)
#pragma unroll
            for (int nt = 0; nt < 4; nt++) {
                const int c = wn * 32 + nt * 8 + (lane & 3) * 2;
#pragma unroll
                for (int half = 0; half < 2; half++) {
                    const int r = wm * 32 + mt * 16 + (lane >> 2) + half * 8;
                    hv[mt][nt][half][0] = hvws[r * 128 + c];
                    hv[mt][nt][half][1] = hvws[r * 128 + c + 1];
                }
            }
        __syncthreads();
#pragma unroll
        for (int mt = 0; mt < 2; mt++)
#pragma unroll
            for (int nt = 0; nt < 4; nt++) {
                const int c = wn * 32 + nt * 8 + (lane & 3) * 2;
                const int kc = c >> 6, kk = c & 63, u = kk >> 3;
                const float b0 = bb1[c], b1 = bb1[c + 1];
#pragma unroll
                for (int half = 0; half < 2; half++) {
                    const int r = wm * 32 + mt * 16 + (lane >> 2) + half * 8;
                    float e0 = fmaxf(acc1[mt][nt][half * 2] + b0 + hv[mt][nt][half][0], 0.f);
                    float e1 = fmaxf(acc1[mt][nt][half * 2 + 1] + b1 + hv[mt][nt][half][1], 0.f);
                    bf16 h0 = __float2bfloat16_rn(e0);
                    bf16 h1 = __float2bfloat16_rn(e1);
                    __nv_bfloat162 hp; hp.x = h0; hp.y = h1;
                    __nv_bfloat162 lp;
                    lp.x = __float2bfloat16_rn(e0 - __bfloat162float(h0));
                    lp.y = __float2bfloat16_rn(e1 - __bfloat162float(h1));
                    const uint32_t ad = kc * 16384 + r * 128 +
                                        (uint32_t)(((u ^ (r & 7))) << 4) + (kk & 7) * 2;
                    *(__nv_bfloat162*)(smem + 131072 + ad) = hp;
                    *(__nv_bfloat162*)(smem + 131072 + 32768 + ad) = lp;
                }
            }
    }
    __syncthreads();

    // ================= P2: x2 = relu(x1 @ Wb2 + bb2) =================
    float acc2[2][4][4];
#pragma unroll
    for (int i = 0; i < 2; i++)
#pragma unroll
        for (int j = 0; j < 4; j++)
#pragma unroll
            for (int q = 0; q < 4; q++) acc2[i][j][q] = 0.f;
    run_phase<4>(acc2,
        [&](int kc, uint32_t& aHi, uint32_t& aLo) {
            aHi = xv + kc * 16384; aLo = xv + 32768 + kc * 16384;
        },
        wb2h, wb2l, 128, 0, 2, stg, stg + 16384, tid);

    // x2 fp32 -> xv (x1 dead)
    {
        const int wm = wid >> 2, wn = wid & 3;
#pragma unroll
        for (int mt = 0; mt < 2; mt++)
#pragma unroll
            for (int nt = 0; nt < 4; nt++) {
                const int c = wn * 32 + nt * 8 + (lane & 3) * 2;
                const float b0 = bb2[c], b1 = bb2[c + 1];
#pragma unroll
                for (int half = 0; half < 2; half++) {
                    const int r = wm * 32 + mt * 16 + (lane >> 2) + half * 8;
                    float e0 = fmaxf(acc2[mt][nt][half * 2] + b0, 0.f);
                    float e1 = fmaxf(acc2[mt][nt][half * 2 + 1] + b1, 0.f);
                    *(float2*)(smem + 131072 + ((size_t)r * 128 + c) * 4) = make_float2(e0, e1);
                }
            }
    }
    // Wb3 transposed into stg
    {
        float* wb3s = (float*)(smem + 196608);
        if (tid < 128) {
#pragma unroll
            for (int h = 0; h < 4; h++) wb3s[h * 128 + tid] = Wb3[tid * 8 + h];
        }
    }
    __syncthreads();

    // ================= P3: e = exp(logits), segment sum =================
    {
        const float* x2s = (const float*)(smem + 131072);
        const float* wb3s = (const float*)(smem + 196608);
        float* atts = (float*)(smem + ATT_OFF);
        int* cens = (int*)(smem + CEN_OFF);
        for (int rr = wid * 8; rr < wid * 8 + 8; rr++) {
            const int e = row0 + rr;
            if (e >= M) break;
            float p0 = 0.f, p1 = 0.f, p2 = 0.f, p3 = 0.f;
#pragma unroll
            for (int j = 0; j < 4; j++) {
                const int c = lane + j * 32;
                const float x = x2s[rr * 128 + c];
                p0 += x * wb3s[c];
                p1 += x * wb3s[128 + c];
                p2 += x * wb3s[256 + c];
                p3 += x * wb3s[384 + c];
            }
#pragma unroll
            for (int off = 16; off; off >>= 1) {
                p0 += __shfl_xor_sync(0xffffffffu, p0, off);
                p1 += __shfl_xor_sync(0xffffffffu, p1, off);
                p2 += __shfl_xor_sync(0xffffffffu, p2, off);
                p3 += __shfl_xor_sync(0xffffffffu, p3, off);
            }
            if (lane < 4) {
                const float p = (lane == 0) ? p0 : (lane == 1) ? p1 : (lane == 2) ? p2 : p3;
                const float l = (p + bb3[lane]) * 0.17677669529663687f;
                const float ex = expf(l);
                atts[rr * 4 + lane] = ex;
                const int c = eidx[e];
                if (lane == 0) cens[rr] = c;
                atomicAdd(&gsum[c * 4 + lane], ex);
            }
        }
    }
    __syncthreads();

    // ================= P4: v1 = gelu(hE @ Wv1 + bv1), batched weights in xv =================
    float acc3[2][4][4];
#pragma unroll
    for (int i = 0; i < 2; i++)
#pragma unroll
        for (int j = 0; j < 4; j++)
#pragma unroll
            for (int q = 0; q < 4; q++) acc3[i][j][q] = 0.f;
    stage_chunks2(xv, wv1h, wv1l, 256, 0, tid);
    CP_WAIT(0);
    __syncthreads();
#pragma unroll
    for (int h = 0; h < 4; h++)
        mma_half512<4>(acc3, heHi + (h >> 1) * 16384, heLo + (h >> 1) * 16384,
                       xv + (h >> 1) * 16384, xv + 32768 + (h >> 1) * 16384, (h & 1) * 2, tid);
    __syncthreads();
    stage_chunks2(xv, wv1h, wv1l, 256, 128, tid);
    CP_WAIT(0);
    __syncthreads();
#pragma unroll
    for (int h = 0; h < 4; h++)
        mma_half512<4>(acc3, heHi + (2 + (h >> 1)) * 16384, heLo + (2 + (h >> 1)) * 16384,
                       xv + (h >> 1) * 16384, xv + 32768 + (h >> 1) * 16384, (h & 1) * 2, tid);
    __syncthreads();
    // overlap: stage Wv2 -> heLo region (hE dead after P4) while storing v1 planes -> xv
    stage_chunks2(heLo, wv2h, wv2l, 128, 0, tid);
    store_planes512<4, 2>(acc3, smem, 131072, 131072 + 32768, bv1, tid);  // v1 -> xv
    CP_WAIT(0);
    __syncthreads();

    // ================= P5: v2 = gelu(v1 @ Wv2 + bv2) =================
    float acc4[2][4][4];
#pragma unroll
    for (int i = 0; i < 2; i++)
#pragma unroll
        for (int j = 0; j < 4; j++)
#pragma unroll
            for (int q = 0; q < 4; q++) acc4[i][j][q] = 0.f;
#pragma unroll
    for (int h = 0; h < 4; h++)
        mma_half512<4>(acc4, xv + (h >> 1) * 16384, xv + 32768 + (h >> 1) * 16384,
                       heLo + (h >> 1) * 16384, heLo + 32768 + (h >> 1) * 16384, (h & 1) * 2, tid);
    __syncthreads();
    // overlap: stage Wv3 -> xv (v1 dead) while storing v2 planes -> heHi region
    stage_chunks2(xv, wv3h, wv3l, 128, 0, tid);
    store_planes512<4, 2>(acc4, smem, 0, 32768, bv2, tid);   // v2 -> heHi region (hE dead)
    CP_WAIT(0);
    __syncthreads();

    // ================= P6: V = v2 @ Wv3 + bv3; hagg[center] += e * V =================
    float acc5[2][4][4];
#pragma unroll
    for (int i = 0; i < 2; i++)
#pragma unroll
        for (int j = 0; j < 4; j++)
#pragma unroll
            for (int q = 0; q < 4; q++) acc5[i][j][q] = 0.f;
#pragma unroll
    for (int h = 0; h < 4; h++)
        mma_half512<4>(acc5, heHi + (h >> 1) * 16384, heHi + 32768 + (h >> 1) * 16384,
                       xv + (h >> 1) * 16384, xv + 32768 + (h >> 1) * 16384, (h & 1) * 2, tid);
    {
        const float* atts = (const float*)(smem + ATT_OFF);
        const int* cens = (const int*)(smem + CEN_OFF);
        const int wm = wid >> 2, wn = wid & 3;
#pragma unroll
        for (int mt = 0; mt < 2; mt++) {
#pragma unroll
            for (int nt = 0; nt < 4; nt++) {
                const int c = wn * 32 + nt * 8 + (lane & 3) * 2;
                const int h = c >> 5;
                const float b0 = bv3[c], b1 = bv3[c + 1];
#pragma unroll
                for (int half = 0; half < 2; half++) {
                    const int rl = wm * 32 + mt * 16 + (lane >> 2) + half * 8;
                    if (row0 + rl < M) {
                        const float a = atts[rl * 4 + h];
                        float* dst = hagg + (size_t)cens[rl] * 128 + c;
                        red2(dst, (acc5[mt][nt][half * 2] + b0) * a,
                                  (acc5[mt][nt][half * 2 + 1] + b1) * a);
                    }
                }
            }
        }
    }
}

// ---------------- standalone GEMM (W_O), 256 threads ----------------
__device__ __forceinline__ void ldsm_mma8(float (&acc)[2][8][4], uint32_t aB, uint32_t bB, int tid)
{
    const int wid = tid >> 5, lane = tid & 31;
    const int wm = wid >> 1, wn = wid & 1;
    const int a_row = wm * 32 + (lane & 7) + ((lane & 8) ? 8 : 0);
    const int a_ub  = (lane & 16) ? 1 : 0;
    const int b_row0 = wn * 64 + (lane & 7) + ((lane & 16) ? 8 : 0);
    const int b_ub  = (lane & 8) ? 1 : 0;
#pragma unroll
    for (int ks = 0; ks < 4; ks++) {
        uint32_t ahi[2][4], alo[2][4];
#pragma unroll
        for (int mt = 0; mt < 2; mt++) {
            const int r = a_row + mt * 16;
            const int u = ks * 2 + a_ub;
            const uint32_t off = r * 128 + (uint32_t)(((u ^ (r & 7))) << 4);
            ldsm4(ahi[mt], aB + off);
            ldsm4(alo[mt], aB + 16384 + off);
        }
        uint32_t bhi[4][4], blo[4][4];
#pragma unroll
        for (int g = 0; g < 4; g++) {
            const int n = b_row0 + g * 16;
            const int u = ks * 2 + b_ub;
            const uint32_t off = n * 128 + (uint32_t)(((u ^ (n & 7))) << 4);
            ldsm4(bhi[g], bB + off);
            ldsm4(blo[g], bB + 16384 + off);
        }
#pragma unroll
        for (int mt = 0; mt < 2; mt++)
#pragma unroll
            for (int ntl = 0; ntl < 8; ntl++) {
                float* a_ = acc[mt][ntl];
                const uint32_t* bh = &bhi[ntl >> 1][(ntl & 1) * 2];
                const uint32_t* bl = &blo[ntl >> 1][(ntl & 1) * 2];
                mma16816(a_, ahi[mt], bh);
                mma16816(a_, ahi[mt], bl);
                mma16816(a_, alo[mt], bh);
            }
    }
}

__global__ __launch_bounds__(256, 1)
void hmma_gemm_o(const bf16* __restrict__ Ahi, const bf16* __restrict__ Alo,
                 const bf16* __restrict__ Bhi, const bf16* __restrict__ Blo,
                 float* __restrict__ Cf, int M)
{
    extern __shared__ char smem[];
    const uint32_t sb = smem_u32(smem);
    const int tid = threadIdx.x;
    const int wid = tid >> 5, lane = tid & 31;
    const int row0 = blockIdx.x * 128;

    const int lr = tid >> 1;
    const int arow = (row0 + lr < M) ? (row0 + lr) : (M - 1);

    float acc[2][8][4];
#pragma unroll
    for (int i = 0; i < 2; i++)
#pragma unroll
        for (int j = 0; j < 8; j++)
#pragma unroll
            for (int q = 0; q < 4; q++) acc[i][j][q] = 0.f;

    for (int kc = 0; kc < 2; kc++) {
        const int k0 = kc * 64;
#pragma unroll
        for (int i = 0; i < 4; i++) {
            const int u = (tid & 1) * 4 + i;
            const uint32_t d = lr * 128 + (uint32_t)(((u ^ (lr & 7))) << 4);
            cp16(sb + d,         (const char*)(Ahi + (size_t)arow * 128 + k0) + u * 16);
            cp16(sb + 16384 + d, (const char*)(Alo + (size_t)arow * 128 + k0) + u * 16);
        }
        for (int i = tid; i < 128 * 8; i += 256) {
            const int r = i >> 3, u = i & 7;
            const uint32_t d = r * 128 + (uint32_t)(((u ^ (r & 7))) << 4);
            cp16(sb + 32768 + d, (const char*)(Bhi + (size_t)r * 128 + k0) + u * 16);
            cp16(sb + 49152 + d, (const char*)(Blo + (size_t)r * 128 + k0) + u * 16);
        }
        CP_COMMIT();
        CP_WAIT(0);
        __syncthreads();
        ldsm_mma8(acc, sb, sb + 32768, tid);
        __syncthreads();
    }

    const int wm = wid >> 1, wn = wid & 1;
#pragma unroll
    for (int mt = 0; mt < 2; mt++) {
        const int r = row0 + wm * 32 + mt * 16 + (lane >> 2);
#pragma unroll
        for (int nt = 0; nt < 8; nt++) {
            const int c = wn * 64 + nt * 8 + (lane & 3) * 2;
#pragma unroll
            for (int half = 0; half < 2; half++) {
                const int rr = r + half * 8;
                if (rr >= M) continue;
                *(float2*)(Cf + (size_t)rr * 128 + c) =
                    make_float2(acc[mt][nt][half * 2], acc[mt][nt][half * 2 + 1]);
            }
        }
    }
}

// ---------------- host launch ----------------
extern "C" void kernel_launch(void* const* d_in, const int* in_sizes, int n_in,
                              void* d_out, int out_size)
{
    const float* h_V   = (const float*)d_in[0];
    const float* h_E   = (const float*)d_in[1];
    const int*   eidx  = (const int*)  d_in[2];
    const float* hvv   = (const float*)d_in[3];
    const float* frame = (const float*)d_in[4];
    const float* W_vec = (const float*)d_in[5];
    const float* W_red = (const float*)d_in[6];
    const float* Wb1   = (const float*)d_in[7];
    const float* bb1   = (const float*)d_in[8];
    const float* Wb2   = (const float*)d_in[9];
    const float* bb2   = (const float*)d_in[10];
    const float* Wb3   = (const float*)d_in[11];
    const float* bb3   = (const float*)d_in[12];
    const float* Wv1   = (const float*)d_in[13];
    const float* bv1   = (const float*)d_in[14];
    const float* Wv2   = (const float*)d_in[15];
    const float* bv2   = (const float*)d_in[16];
    const float* Wv3   = (const float*)d_in[17];
    const float* bv3   = (const float*)d_in[18];
    const float* W_O   = (const float*)d_in[19];
    const float* bn_g  = (const float*)d_in[20];
    const float* bn_b  = (const float*)d_in[21];

    int E = in_sizes[2] / 2;
    int N = in_sizes[0] / 128;
    float* out = (float*)d_out;

    float *vff, *hVW, *gsum, *hagg, *bnst;
    bf16 *hgh, *hgl, *wh, *wl;
    double* bnacc;
    cudaGetSymbolAddress((void**)&vff,   g_vff);
    cudaGetSymbolAddress((void**)&hVW,   g_hVW);
    cudaGetSymbolAddress((void**)&hgh,   g_hgh);
    cudaGetSymbolAddress((void**)&hgl,   g_hgl);
    cudaGetSymbolAddress((void**)&wh,    g_wh);
    cudaGetSymbolAddress((void**)&wl,    g_wl);
    cudaGetSymbolAddress((void**)&gsum,  g_sum);
    cudaGetSymbolAddress((void**)&hagg,  g_hagg);
    cudaGetSymbolAddress((void**)&bnacc, g_bnacc);
    cudaGetSymbolAddress((void**)&bnst,  g_bnst);

    const int SMEM_O = 65536;
    cudaFuncSetAttribute(mega_kernel, cudaFuncAttributeMaxDynamicSharedMemorySize, SMEM_MEGA);
    cudaFuncSetAttribute(hmma_gemm_o, cudaFuncAttributeMaxDynamicSharedMemorySize, SMEM_O);

    int Mt = (E + 127) / 128;
    int Mo = (N + 127) / 128;

    init_kernel<<<(N * 128 + 255) / 256, 256>>>(gsum, hagg, bnacc, N);
    geom_kernel<<<(E + 255) / 256, 256>>>(eidx, hvv, frame, W_vec, vff, bnacc, E);
    bn_finalize<<<1, 32>>>(bnacc, bn_g, bn_b, bnst, E);

    wprep_all<<<(W_TOTAL + 255) / 256, 256>>>(W_red, Wb1, Wb2, Wv1, Wv2, Wv3, W_O, wh, wl);
    hvw_kernel<<<(N + 1) / 2, 256>>>(h_V, Wb1, hVW, N);

    mega_kernel<<<Mt, 512, SMEM_MEGA>>>(
        vff, h_E, bnst, hVW, eidx,
        wh + OW_RED, wl + OW_RED,
        wh + OW_B1, wl + OW_B1, bb1,
        wh + OW_B2, wl + OW_B2, bb2,
        Wb3, bb3,
        wh + OW_V1, wl + OW_V1, bv1,
        wh + OW_V2, wl + OW_V2, bv2,
        wh + OW_V3, wl + OW_V3, bv3,
        gsum, hagg, E);

    // hagg normalized by segment sums -> planes, then out = hagg @ W_O
    c2planes_norm<<<(N * 128 + 255) / 256, 256>>>(hagg, gsum, hgh, hgl, N);
    hmma_gemm_o<<<Mo, 256, SMEM_O>>>(hgh, hgl, wh + OW_O, wl + OW_O, out, N);
}

// round 11
// speedup vs baseline: 1.0596x; 1.0596x over previous
#include <cuda_runtime.h>
#include <cuda_bf16.h>
#include <math.h>
#include <stdint.h>

#define E_CONST 320000
#define N_CONST 10000
typedef __nv_bfloat16 bf16;

// ---------------- scratch (no allocations allowed) ----------------
static __device__ float    g_vff [(size_t)E_CONST * 64];   // fp32 [sincos48|dist16]
static __device__ float    g_hVW [N_CONST * 128];          // hV @ Wb1_top (fp32, per node)
static __device__ bf16     g_hgh [N_CONST * 128];
static __device__ bf16     g_hgl [N_CONST * 128];
static __device__ bf16     g_wh  [262144];                 // all weights, [n][k]
static __device__ bf16     g_wl  [262144];
static __device__ float    g_sum [N_CONST * 4];
static __device__ float    g_hagg[N_CONST * 128];
static __device__ double   g_bnacc[32];
static __device__ float    g_bnst[32];

// weight plane offsets (elements)
#define OW_RED 0        // 256 x 320
#define OW_B1  81920    // 128 x 384
#define OW_B2  131072   // 128 x 128
#define OW_V1  147456   // 128 x 256
#define OW_V2  180224   // 128 x 128
#define OW_V3  196608   // 128 x 128
#define OW_O   212992   // 128 x 128
#define W_TOTAL 229376

// mega smem tail (beyond the 224KB working set)
#define ATT_OFF 229376
#define CEN_OFF 231424
#define SMEM_MEGA 231936

// ---------------- helpers ----------------
__device__ __forceinline__ uint32_t smem_u32(const void* p) {
    uint32_t a;
    asm("{ .reg .u64 t; cvta.to.shared.u64 t, %1; cvt.u32.u64 %0, t; }" : "=r"(a) : "l"(p));
    return a;
}
__device__ __forceinline__ void cp16(uint32_t dst, const void* src) {
    asm volatile("cp.async.cg.shared.global [%0], [%1], 16;"
        :: "r"(dst), "l"(__cvta_generic_to_global(src)) : "memory");
}
#define CP_COMMIT() asm volatile("cp.async.commit_group;" ::: "memory")
#define CP_WAIT(n)  asm volatile("cp.async.wait_group %0;" :: "n"(n) : "memory")

__device__ __forceinline__ void ldsm4(uint32_t* r, uint32_t addr) {
    asm volatile("ldmatrix.sync.aligned.m8n8.x4.shared.b16 {%0,%1,%2,%3}, [%4];"
        : "=r"(r[0]), "=r"(r[1]), "=r"(r[2]), "=r"(r[3]) : "r"(addr));
}
__device__ __forceinline__ void mma16816(float* d, const uint32_t* a, const uint32_t* b) {
    asm volatile(
        "mma.sync.aligned.m16n8k16.row.col.f32.bf16.bf16.f32 "
        "{%0,%1,%2,%3}, {%4,%5,%6,%7}, {%8,%9}, {%0,%1,%2,%3};"
        : "+f"(d[0]), "+f"(d[1]), "+f"(d[2]), "+f"(d[3])
        : "r"(a[0]), "r"(a[1]), "r"(a[2]), "r"(a[3]), "r"(b[0]), "r"(b[1]));
}
__device__ __forceinline__ void red2(float* addr, float x, float y) {
    asm volatile("red.global.v2.f32.add [%0], {%1, %2};"
        :: "l"(__cvta_generic_to_global(addr)), "f"(x), "f"(y) : "memory");
}
__device__ __forceinline__ float gelu_f(float x) {
    return 0.5f * x * (1.f + erff(x * 0.70710678118654752f));
}

// ---------------- init ----------------
__global__ void init_kernel(float* gsum, float* hagg, double* bnacc, int N)
{
    int i = blockIdx.x * 256 + threadIdx.x;
    if (i < N * 128) hagg[i] = 0.f;
    if (i < N * 4) gsum[i] = 0.f;
    if (i < 32) bnacc[i] = 0.0;
}

// ---------------- geometry + BN stats ----------------
__global__ __launch_bounds__(256)
void geom_kernel(const int* __restrict__ eidx, const float* __restrict__ hvv,
                 const float* __restrict__ frame, const float* __restrict__ Wvec,
                 float* __restrict__ vff, double* __restrict__ bnacc, int E)
{
    __shared__ float Ws[512];
    __shared__ float bsum[16], bsq[16];
    int tid = threadIdx.x;
    for (int i = tid; i < 512; i += 256) Ws[i] = Wvec[i];
    if (tid < 16) { bsum[tid] = 0.f; bsq[tid] = 0.f; }
    __syncthreads();

    int e = blockIdx.x * 256 + tid;
    float dloc[16];
#pragma unroll
    for (int o = 0; o < 16; o++) dloc[o] = 0.f;

    if (e < E) {
        int c = eidx[e];
        int d = eidx[E + e];
        float F[9];
#pragma unroll
        for (int i = 0; i < 9; i++) F[i] = frame[e * 9 + i];
        float vdt[48], vsrc[48];
#pragma unroll
        for (int v = 0; v < 16; v++) {
            float x = hvv[d * 48 + v * 3 + 0];
            float y = hvv[d * 48 + v * 3 + 1];
            float z = hvv[d * 48 + v * 3 + 2];
            vdt[v * 3 + 0] = F[0] * x + F[1] * y + F[2] * z;
            vdt[v * 3 + 1] = F[3] * x + F[4] * y + F[5] * z;
            vdt[v * 3 + 2] = F[6] * x + F[7] * y + F[8] * z;
        }
#pragma unroll
        for (int i = 0; i < 48; i++) vsrc[i] = hvv[c * 48 + i];

#pragma unroll
        for (int o = 0; o < 16; o++) {
            float v0 = vdt[o * 3 + 0], v1 = vdt[o * 3 + 1], v2 = vdt[o * 3 + 2];
#pragma unroll
            for (int v = 0; v < 16; v++) {
                float wa = Ws[o * 32 + v], wb = Ws[o * 32 + 16 + v];
                v0 += wa * vdt[v * 3 + 0] + wb * vsrc[v * 3 + 0];
                v1 += wa * vdt[v * 3 + 1] + wb * vsrc[v * 3 + 1];
                v2 += wa * vdt[v * 3 + 2] + wb * vsrc[v * 3 + 2];
            }
            float dist = sqrtf(v0 * v0 + v1 * v1 + v2 * v2) + 1e-6f;
            float inv = 1.f / dist;
            vff[e * 64 + o * 3 + 0] = v0 * inv;
            vff[e * 64 + o * 3 + 1] = v1 * inv;
            vff[e * 64 + o * 3 + 2] = v2 * inv;
            vff[e * 64 + 48 + o] = dist;
            dloc[o] = dist;
        }
    }

#pragma unroll
    for (int o = 0; o < 16; o++) {
        float v = dloc[o], v2 = v * v;
#pragma unroll
        for (int off = 16; off; off >>= 1) {
            v  += __shfl_down_sync(0xffffffffu, v, off);
            v2 += __shfl_down_sync(0xffffffffu, v2, off);
        }
        if ((tid & 31) == 0) { atomicAdd(&bsum[o], v); atomicAdd(&bsq[o], v2); }
    }
    __syncthreads();
    if (tid < 16) {
        atomicAdd(&bnacc[tid], (double)bsum[tid]);
        atomicAdd(&bnacc[16 + tid], (double)bsq[tid]);
    }
}

__global__ void bn_finalize(const double* __restrict__ acc, const float* __restrict__ g,
                            const float* __restrict__ b, float* __restrict__ st, int E)
{
    int i = threadIdx.x;
    if (i >= 16) return;
    double mean = acc[i] / (double)E;
    double var  = acc[16 + i] / (double)E - mean * mean;
    float s = (float)((double)g[i] / sqrt(var + 1e-5));
    st[i] = s;
    st[16 + i] = b[i] - (float)mean * s;
}

// ---------------- conversion passes ----------------
__global__ void wprep_all(const float* __restrict__ W0, const float* __restrict__ W1,
                          const float* __restrict__ W2, const float* __restrict__ W3,
                          const float* __restrict__ W4, const float* __restrict__ W5,
                          const float* __restrict__ W6,
                          bf16* __restrict__ hi, bf16* __restrict__ lo)
{
    int idx = blockIdx.x * 256 + threadIdx.x;
    if (idx >= W_TOTAL) return;
    const float* src; int K, NT, start;
    if      (idx < OW_B1)  { src = W0; K = 320; NT = 256; start = OW_RED; }
    else if (idx < OW_B2)  { src = W1; K = 384; NT = 128; start = OW_B1; }
    else if (idx < OW_V1)  { src = W2; K = 128; NT = 128; start = OW_B2; }
    else if (idx < OW_V2)  { src = W3; K = 256; NT = 128; start = OW_V1; }
    else if (idx < OW_V3)  { src = W4; K = 128; NT = 128; start = OW_V2; }
    else if (idx < OW_O)   { src = W5; K = 128; NT = 128; start = OW_V3; }
    else                   { src = W6; K = 128; NT = 128; start = OW_O; }
    int local = idx - start;
    int k = local / NT, n = local % NT;
    float v = src[local];
    bf16 h = __float2bfloat16_rn(v);
    hi[start + (size_t)n * K + k] = h;
    lo[start + (size_t)n * K + k] = __float2bfloat16_rn(v - __bfloat162float(h));
}

// hVW = hV @ Wb1[0:128,:]  (exact fp32, per-node)
__global__ __launch_bounds__(256)
void hvw_kernel(const float* __restrict__ hV, const float* __restrict__ Wb1,
                float* __restrict__ hVW, int N)
{
    __shared__ float xs[2][128];
    const int t = threadIdx.x;
    const int which = t >> 7, c = t & 127;
    const int node = blockIdx.x * 2 + which;
    if (node < N) xs[which][c] = hV[(size_t)node * 128 + c];
    __syncthreads();
    if (node >= N) return;
    float s = 0.f;
#pragma unroll 8
    for (int k = 0; k < 128; k++) s += xs[which][k] * Wb1[k * 128 + c];
    hVW[(size_t)node * 128 + c] = s;
}

// hagg -> planes with softmax normalization folded in
__global__ void c2planes_norm(const float* __restrict__ x, const float* __restrict__ gsum,
                              bf16* __restrict__ hi, bf16* __restrict__ lo, int N)
{
    int i = blockIdx.x * 256 + threadIdx.x;
    if (i >= N * 128) return;
    int node = i >> 7, col = i & 127;
    float s = gsum[node * 4 + (col >> 5)];
    float v = x[i] / (s > 0.f ? s : 1.f);
    bf16 h = __float2bfloat16_rn(v);
    hi[i] = h;
    lo[i] = __float2bfloat16_rn(v - __bfloat162float(h));
}

// ================= GEMM building blocks (512 threads, 16 warps = 4m x 4n) =================
template<int NT>
__device__ __forceinline__ void mma_half512(
    float (&acc)[2][NT][4], uint32_t aHi, uint32_t aLo,
    uint32_t bHi, uint32_t bLo, int ks0, int tid)
{
    const int wid = tid >> 5, lane = tid & 31;
    const int wm = wid >> 2, wn = wid & 3;
    const int a_row = wm * 32 + (lane & 7) + ((lane & 8) ? 8 : 0);
    const int a_ub  = (lane & 16) ? 1 : 0;
    const int b_row0 = wn * (NT * 8) + (lane & 7) + ((lane & 16) ? 8 : 0);
    const int b_ub  = (lane & 8) ? 1 : 0;
#pragma unroll
    for (int kss = 0; kss < 2; kss++) {
        const int ks = ks0 + kss;
        uint32_t ahi[2][4], alo[2][4];
#pragma unroll
        for (int mt = 0; mt < 2; mt++) {
            const int r = a_row + mt * 16;
            const int u = ks * 2 + a_ub;
            const uint32_t off = r * 128 + (uint32_t)(((u ^ (r & 7))) << 4);
            ldsm4(ahi[mt], aHi + off);
            ldsm4(alo[mt], aLo + off);
        }
        uint32_t bhi[NT / 2][4], blo[NT / 2][4];
#pragma unroll
        for (int g = 0; g < NT / 2; g++) {
            const int n = b_row0 + g * 16;
            const int u = ks * 2 + b_ub;
            const uint32_t off = n * 128 + (uint32_t)(((u ^ (n & 7))) << 4);
            ldsm4(bhi[g], bHi + off);
            ldsm4(blo[g], bLo + off);
        }
#pragma unroll
        for (int mt = 0; mt < 2; mt++)
#pragma unroll
            for (int ntl = 0; ntl < NT; ntl++) {
                float* a_ = acc[mt][ntl];
                const uint32_t* bh = &bhi[ntl >> 1][(ntl & 1) * 2];
                const uint32_t* bl = &blo[ntl >> 1][(ntl & 1) * 2];
                mma16816(a_, ahi[mt], bh);
                mma16816(a_, ahi[mt], bl);
                mma16816(a_, alo[mt], bh);
            }
    }
}

__device__ __forceinline__ void stage_half(uint32_t dstHi, uint32_t dstLo,
                                           const bf16* __restrict__ Whi,
                                           const bf16* __restrict__ Wlo,
                                           int K, int k0, int half, int rows, int tid)
{
    for (int i = tid; i < rows * 4; i += 512) {
        const int r = i >> 2, u = (i & 3) + half * 4;
        const uint32_t d = r * 128 + (uint32_t)(((u ^ (r & 7))) << 4);
        cp16(dstHi + d, (const char*)(Whi + (size_t)r * K + k0) + u * 16);
        cp16(dstLo + d, (const char*)(Wlo + (size_t)r * K + k0) + u * 16);
    }
    CP_COMMIT();
}

// stage 2 full 64-K chunks (128 rows) of weight planes into dst (hi: +0, lo: +32K)
__device__ __forceinline__ void stage_chunks2(uint32_t dst,
                                              const bf16* __restrict__ Whi,
                                              const bf16* __restrict__ Wlo,
                                              int K, int k0, int tid)
{
    for (int i = tid; i < 2048; i += 512) {
        const int ch = i >> 10, rem = i & 1023;
        const int r = rem >> 3, u = rem & 7;
        const uint32_t d = ch * 16384 + r * 128 + (uint32_t)(((u ^ (r & 7))) << 4);
        cp16(dst + d,         (const char*)(Whi + (size_t)r * K + k0 + ch * 64) + u * 16);
        cp16(dst + 32768 + d, (const char*)(Wlo + (size_t)r * K + k0 + ch * 64) + u * 16);
    }
    CP_COMMIT();
}

template<int NT, typename FA>
__device__ __forceinline__ void run_phase(float (&acc)[2][NT][4], FA addrA,
                                          const bf16* __restrict__ Wh, const bf16* __restrict__ Wl,
                                          int K, int k0base, int nch,
                                          uint32_t bHi, uint32_t bLo, int tid)
{
    stage_half(bHi, bLo, Wh, Wl, K, k0base, 0, 128, tid);
    const int H = nch * 2;
    for (int h = 0; h < H; h++) {
        if (h + 1 < H) {
            stage_half(bHi, bLo, Wh, Wl, K, k0base + ((h + 1) >> 1) * 64, (h + 1) & 1, 128, tid);
            CP_WAIT(1);
        } else {
            CP_WAIT(0);
        }
        __syncthreads();
        uint32_t aHi, aLo;
        addrA(h >> 1, aHi, aLo);
        mma_half512<NT>(acc, aHi, aLo, bHi, bLo, (h & 1) * 2, tid);
        __syncthreads();
    }
}

template<int NT, int ACT>
__device__ __forceinline__ void store_planes512(const float (&acc)[2][NT][4],
                                                char* smemp, uint32_t baseHi, uint32_t baseLo,
                                                const float* __restrict__ bias, int tid)
{
    const int wid = tid >> 5, lane = tid & 31;
    const int wm = wid >> 2, wn = wid & 3;
#pragma unroll
    for (int mt = 0; mt < 2; mt++)
#pragma unroll
        for (int nt = 0; nt < NT; nt++) {
            const int c = wn * (NT * 8) + nt * 8 + (lane & 3) * 2;
            const int kc = c >> 6, kk = c & 63, u = kk >> 3;
            const float b0 = bias ? bias[c] : 0.f;
            const float b1 = bias ? bias[c + 1] : 0.f;
#pragma unroll
            for (int half = 0; half < 2; half++) {
                const int r = wm * 32 + mt * 16 + (lane >> 2) + half * 8;
                float e0 = acc[mt][nt][half * 2] + b0;
                float e1 = acc[mt][nt][half * 2 + 1] + b1;
                if (ACT == 1) { e0 = fmaxf(e0, 0.f); e1 = fmaxf(e1, 0.f); }
                if (ACT == 2) { e0 = gelu_f(e0); e1 = gelu_f(e1); }
                bf16 h0 = __float2bfloat16_rn(e0);
                bf16 h1 = __float2bfloat16_rn(e1);
                __nv_bfloat162 hp; hp.x = h0; hp.y = h1;
                __nv_bfloat162 lp;
                lp.x = __float2bfloat16_rn(e0 - __bfloat162float(h0));
                lp.y = __float2bfloat16_rn(e1 - __bfloat162float(h1));
                const uint32_t ad = kc * 16384 + r * 128 +
                                    (uint32_t)(((u ^ (r & 7))) << 4) + (kk & 7) * 2;
                *(__nv_bfloat162*)(smemp + baseHi + ad) = hp;
                *(__nv_bfloat162*)(smemp + baseLo + ad) = lp;
            }
        }
}

// ---------------- MEGA kernel (512 threads) ----------------
// smem: [0,64K) heHi, [64K,128K) heLo, [128K,192K) xv, [192K,224K) stg,
//       [224K,226K) att (e values), [226K,226.5K) cen
__global__ __launch_bounds__(512, 1)
void mega_kernel(const float* __restrict__ Vff, const float* __restrict__ HE,
                 const float* __restrict__ bn_st,
                 const float* __restrict__ hVW,
                 const int* __restrict__ eidx,
                 const bf16* __restrict__ wredh, const bf16* __restrict__ wredl,
                 const bf16* __restrict__ wb1h, const bf16* __restrict__ wb1l,
                 const float* __restrict__ bb1,
                 const bf16* __restrict__ wb2h, const bf16* __restrict__ wb2l,
                 const float* __restrict__ bb2,
                 const float* __restrict__ Wb3, const float* __restrict__ bb3,
                 const bf16* __restrict__ wv1h, const bf16* __restrict__ wv1l,
                 const float* __restrict__ bv1,
                 const bf16* __restrict__ wv2h, const bf16* __restrict__ wv2l,
                 const float* __restrict__ bv2,
                 const bf16* __restrict__ wv3h, const bf16* __restrict__ wv3l,
                 const float* __restrict__ bv3,
                 float* __restrict__ gsum, float* __restrict__ hagg, int M)
{
    extern __shared__ char smem[];
    const uint32_t sb = smem_u32(smem);
    const uint32_t heHi = sb;
    const uint32_t heLo = sb + 65536;
    const uint32_t xv   = sb + 131072;
    const uint32_t stg  = sb + 196608;
    const int tid = threadIdx.x;
    const int wid = tid >> 5, lane = tid & 31;
    const int row0 = blockIdx.x * 128;

    const int lr = tid >> 2;              // 4 threads per row
    const int arow = (row0 + lr < M) ? (row0 + lr) : (M - 1);
    const int cu0 = (tid & 3) * 4;        // fp32 16B-unit base for A convert

    // center table for this tile (used by P1 epilogue and P3/P6)
    {
        int* cens = (int*)(smem + CEN_OFF);
        if (tid < 128) {
            int er = row0 + tid;
            cens[tid] = eidx[er < M ? er : M - 1];
        }
    }

    // ================= P0: hE = [vff_bn | h_E] @ W_red (K=320, N=256) =================
    {
        float acc0[2][8][4];
#pragma unroll
        for (int i = 0; i < 2; i++)
#pragma unroll
            for (int j = 0; j < 8; j++)
#pragma unroll
                for (int q = 0; q < 4; q++) acc0[i][j][q] = 0.f;

        float4 areg[4];
        {
            const float4* pa = (const float4*)(Vff + (size_t)arow * 64);
#pragma unroll
            for (int jj = 0; jj < 4; jj++) areg[jj] = pa[cu0 + jj];
        }
        stage_half(xv + 32768, stg, wredh, wredl, 320, 0, 0, 256, tid);

        for (int kc = 0; kc < 5; kc++) {
            {
                float4 f[4];
#pragma unroll
                for (int jj = 0; jj < 4; jj++) f[jj] = areg[jj];
                if (kc == 0 && cu0 >= 12) {
#pragma unroll
                    for (int jj = 0; jj < 4; jj++) {
                        const int u = cu0 + jj;
                        if (u >= 12) {
                            const int col = u * 4;
                            f[jj].x = fmaf(f[jj].x, bn_st[col - 48], bn_st[col - 32]);
                            f[jj].y = fmaf(f[jj].y, bn_st[col - 47], bn_st[col - 31]);
                            f[jj].z = fmaf(f[jj].z, bn_st[col - 46], bn_st[col - 30]);
                            f[jj].w = fmaf(f[jj].w, bn_st[col - 45], bn_st[col - 29]);
                        }
                    }
                }
#pragma unroll
                for (int jj = 0; jj < 2; jj++) {
                    float v[8] = {f[2 * jj].x, f[2 * jj].y, f[2 * jj].z, f[2 * jj].w,
                                  f[2 * jj + 1].x, f[2 * jj + 1].y, f[2 * jj + 1].z, f[2 * jj + 1].w};
                    uint32_t ph[4], pl[4];
#pragma unroll
                    for (int j = 0; j < 4; j++) {
                        float a = v[2 * j], b = v[2 * j + 1];
                        bf16 ha = __float2bfloat16_rn(a);
                        bf16 hb = __float2bfloat16_rn(b);
                        __nv_bfloat162 hp; hp.x = ha; hp.y = hb;
                        __nv_bfloat162 lp;
                        lp.x = __float2bfloat16_rn(a - __bfloat162float(ha));
                        lp.y = __float2bfloat16_rn(b - __bfloat162float(hb));
                        ph[j] = reinterpret_cast<uint32_t&>(hp);
                        pl[j] = reinterpret_cast<uint32_t&>(lp);
                    }
                    const int un = (cu0 >> 1) + jj;
                    const uint32_t ad = lr * 128 + (uint32_t)(((un ^ (lr & 7))) << 4);
                    *(uint4*)(smem + 131072 + ad)         = make_uint4(ph[0], ph[1], ph[2], ph[3]);
                    *(uint4*)(smem + 131072 + 16384 + ad) = make_uint4(pl[0], pl[1], pl[2], pl[3]);
                }
            }
            if (kc < 4) {
                const float4* pa = (const float4*)(HE + (size_t)arow * 256 + kc * 64);
#pragma unroll
                for (int jj = 0; jj < 4; jj++) areg[jj] = pa[cu0 + jj];
            }
#pragma unroll
            for (int hh = 0; hh < 2; hh++) {
                const int h = kc * 2 + hh;
                if (h + 1 < 10) {
                    stage_half(xv + 32768, stg, wredh, wredl, 320,
                               ((h + 1) >> 1) * 64, (h + 1) & 1, 256, tid);
                    CP_WAIT(1);
                } else {
                    CP_WAIT(0);
                }
                __syncthreads();
                mma_half512<8>(acc0, xv, xv + 16384, xv + 32768, stg, hh * 2, tid);
                __syncthreads();
            }
        }

        store_planes512<8, 0>(acc0, smem, 0, 65536, nullptr, tid);
    }
    __syncthreads();

    // ================= P1: x1 = relu(hVW[center] + hE @ Wb1_bot + bb1), K=256 =================
    float acc1[2][4][4];
#pragma unroll
    for (int i = 0; i < 2; i++)
#pragma unroll
        for (int j = 0; j < 4; j++)
#pragma unroll
            for (int q = 0; q < 4; q++) acc1[i][j][q] = 0.f;
    {
        run_phase<4>(acc1,
            [&](int kc, uint32_t& aHi, uint32_t& aLo) {
                aHi = heHi + kc * 16384; aLo = heLo + kc * 16384;
            },
            wb1h, wb1l, 384, 128, 4, stg, stg + 16384, tid);

        // epilogue: fused per-fragment global hVW read + bias + relu -> x1 planes in xv
        const int* cens = (const int*)(smem + CEN_OFF);
        const int wm = wid >> 2, wn = wid & 3;
#pragma unroll
        for (int mt = 0; mt < 2; mt++)
#pragma unroll
            for (int nt = 0; nt < 4; nt++) {
                const int c = wn * 32 + nt * 8 + (lane & 3) * 2;
                const int kc = c >> 6, kk = c & 63, u = kk >> 3;
                const float b0 = bb1[c], b1 = bb1[c + 1];
#pragma unroll
                for (int half = 0; half < 2; half++) {
                    const int r = wm * 32 + mt * 16 + (lane >> 2) + half * 8;
                    const float2 hv = *(const float2*)(hVW + (size_t)cens[r] * 128 + c);
                    float e0 = fmaxf(acc1[mt][nt][half * 2] + b0 + hv.x, 0.f);
                    float e1 = fmaxf(acc1[mt][nt][half * 2 + 1] + b1 + hv.y, 0.f);
                    bf16 h0 = __float2bfloat16_rn(e0);
                    bf16 h1 = __float2bfloat16_rn(e1);
                    __nv_bfloat162 hp; hp.x = h0; hp.y = h1;
                    __nv_bfloat162 lp;
                    lp.x = __float2bfloat16_rn(e0 - __bfloat162float(h0));
                    lp.y = __float2bfloat16_rn(e1 - __bfloat162float(h1));
                    const uint32_t ad = kc * 16384 + r * 128 +
                                        (uint32_t)(((u ^ (r & 7))) << 4) + (kk & 7) * 2;
                    *(__nv_bfloat162*)(smem + 131072 + ad) = hp;
                    *(__nv_bfloat162*)(smem + 131072 + 32768 + ad) = lp;
                }
            }
    }
    __syncthreads();

    // ================= P2: x2 = relu(x1 @ Wb2 + bb2) =================
    float acc2[2][4][4];
#pragma unroll
    for (int i = 0; i < 2; i++)
#pragma unroll
        for (int j = 0; j < 4; j++)
#pragma unroll
            for (int q = 0; q < 4; q++) acc2[i][j][q] = 0.f;
    run_phase<4>(acc2,
        [&](int kc, uint32_t& aHi, uint32_t& aLo) {
            aHi = xv + kc * 16384; aLo = xv + 32768 + kc * 16384;
        },
        wb2h, wb2l, 128, 0, 2, stg, stg + 16384, tid);

    // x2 fp32 -> xv (x1 dead)
    {
        const int wm = wid >> 2, wn = wid & 3;
#pragma unroll
        for (int mt = 0; mt < 2; mt++)
#pragma unroll
            for (int nt = 0; nt < 4; nt++) {
                const int c = wn * 32 + nt * 8 + (lane & 3) * 2;
                const float b0 = bb2[c], b1 = bb2[c + 1];
#pragma unroll
                for (int half = 0; half < 2; half++) {
                    const int r = wm * 32 + mt * 16 + (lane >> 2) + half * 8;
                    float e0 = fmaxf(acc2[mt][nt][half * 2] + b0, 0.f);
                    float e1 = fmaxf(acc2[mt][nt][half * 2 + 1] + b1, 0.f);
                    *(float2*)(smem + 131072 + ((size_t)r * 128 + c) * 4) = make_float2(e0, e1);
                }
            }
    }
    // Wb3 transposed into stg
    {
        float* wb3s = (float*)(smem + 196608);
        if (tid < 128) {
#pragma unroll
            for (int h = 0; h < 4; h++) wb3s[h * 128 + tid] = Wb3[tid * 8 + h];
        }
    }
    __syncthreads();

    // ================= P3: e = exp(logits), segment sum =================
    {
        const float* x2s = (const float*)(smem + 131072);
        const float* wb3s = (const float*)(smem + 196608);
        float* atts = (float*)(smem + ATT_OFF);
        const int* cens = (const int*)(smem + CEN_OFF);
        for (int rr = wid * 8; rr < wid * 8 + 8; rr++) {
            const int e = row0 + rr;
            if (e >= M) break;
            float p0 = 0.f, p1 = 0.f, p2 = 0.f, p3 = 0.f;
#pragma unroll
            for (int j = 0; j < 4; j++) {
                const int c = lane + j * 32;
                const float x = x2s[rr * 128 + c];
                p0 += x * wb3s[c];
                p1 += x * wb3s[128 + c];
                p2 += x * wb3s[256 + c];
                p3 += x * wb3s[384 + c];
            }
#pragma unroll
            for (int off = 16; off; off >>= 1) {
                p0 += __shfl_xor_sync(0xffffffffu, p0, off);
                p1 += __shfl_xor_sync(0xffffffffu, p1, off);
                p2 += __shfl_xor_sync(0xffffffffu, p2, off);
                p3 += __shfl_xor_sync(0xffffffffu, p3, off);
            }
            if (lane < 4) {
                const float p = (lane == 0) ? p0 : (lane == 1) ? p1 : (lane == 2) ? p2 : p3;
                const float l = (p + bb3[lane]) * 0.17677669529663687f;
                const float ex = expf(l);
                atts[rr * 4 + lane] = ex;
                atomicAdd(&gsum[cens[rr] * 4 + lane], ex);
            }
        }
    }
    __syncthreads();

    // ================= P4: v1 = gelu(hE @ Wv1 + bv1), batched weights in xv =================
    float acc3[2][4][4];
#pragma unroll
    for (int i = 0; i < 2; i++)
#pragma unroll
        for (int j = 0; j < 4; j++)
#pragma unroll
            for (int q = 0; q < 4; q++) acc3[i][j][q] = 0.f;
    stage_chunks2(xv, wv1h, wv1l, 256, 0, tid);
    CP_WAIT(0);
    __syncthreads();
#pragma unroll
    for (int h = 0; h < 4; h++)
        mma_half512<4>(acc3, heHi + (h >> 1) * 16384, heLo + (h >> 1) * 16384,
                       xv + (h >> 1) * 16384, xv + 32768 + (h >> 1) * 16384, (h & 1) * 2, tid);
    __syncthreads();
    stage_chunks2(xv, wv1h, wv1l, 256, 128, tid);
    CP_WAIT(0);
    __syncthreads();
#pragma unroll
    for (int h = 0; h < 4; h++)
        mma_half512<4>(acc3, heHi + (2 + (h >> 1)) * 16384, heLo + (2 + (h >> 1)) * 16384,
                       xv + (h >> 1) * 16384, xv + 32768 + (h >> 1) * 16384, (h & 1) * 2, tid);
    __syncthreads();
    // overlap: stage Wv2 -> heLo region (hE dead after P4) while storing v1 planes -> xv
    stage_chunks2(heLo, wv2h, wv2l, 128, 0, tid);
    store_planes512<4, 2>(acc3, smem, 131072, 131072 + 32768, bv1, tid);  // v1 -> xv
    CP_WAIT(0);
    __syncthreads();

    // ================= P5: v2 = gelu(v1 @ Wv2 + bv2) =================
    float acc4[2][4][4];
#pragma unroll
    for (int i = 0; i < 2; i++)
#pragma unroll
        for (int j = 0; j < 4; j++)
#pragma unroll
            for (int q = 0; q < 4; q++) acc4[i][j][q] = 0.f;
#pragma unroll
    for (int h = 0; h < 4; h++)
        mma_half512<4>(acc4, xv + (h >> 1) * 16384, xv + 32768 + (h >> 1) * 16384,
                       heLo + (h >> 1) * 16384, heLo + 32768 + (h >> 1) * 16384, (h & 1) * 2, tid);
    __syncthreads();
    // overlap: stage Wv3 -> xv (v1 dead) while storing v2 planes -> heHi region
    stage_chunks2(xv, wv3h, wv3l, 128, 0, tid);
    store_planes512<4, 2>(acc4, smem, 0, 32768, bv2, tid);   // v2 -> heHi region (hE dead)
    CP_WAIT(0);
    __syncthreads();

    // ================= P6: V = v2 @ Wv3 + bv3; hagg[center] += e * V =================
    float acc5[2][4][4];
#pragma unroll
    for (int i = 0; i < 2; i++)
#pragma unroll
        for (int j = 0; j < 4; j++)
#pragma unroll
            for (int q = 0; q < 4; q++) acc5[i][j][q] = 0.f;
#pragma unroll
    for (int h = 0; h < 4; h++)
        mma_half512<4>(acc5, heHi + (h >> 1) * 16384, heHi + 32768 + (h >> 1) * 16384,
                       xv + (h >> 1) * 16384, xv + 32768 + (h >> 1) * 16384, (h & 1) * 2, tid);
    {
        const float* atts = (const float*)(smem + ATT_OFF);
        const int* cens = (const int*)(smem + CEN_OFF);
        const int wm = wid >> 2, wn = wid & 3;
#pragma unroll
        for (int mt = 0; mt < 2; mt++) {
#pragma unroll
            for (int nt = 0; nt < 4; nt++) {
                const int c = wn * 32 + nt * 8 + (lane & 3) * 2;
                const int h = c >> 5;
                const float b0 = bv3[c], b1 = bv3[c + 1];
#pragma unroll
                for (int half = 0; half < 2; half++) {
                    const int rl = wm * 32 + mt * 16 + (lane >> 2) + half * 8;
                    if (row0 + rl < M) {
                        const float a = atts[rl * 4 + h];
                        float* dst = hagg + (size_t)cens[rl] * 128 + c;
                        red2(dst, (acc5[mt][nt][half * 2] + b0) * a,
                                  (acc5[mt][nt][half * 2 + 1] + b1) * a);
                    }
                }
            }
        }
    }
}

// ---------------- standalone GEMM (W_O), 256 threads ----------------
__device__ __forceinline__ void ldsm_mma8(float (&acc)[2][8][4], uint32_t aB, uint32_t bB, int tid)
{
    const int wid = tid >> 5, lane = tid & 31;
    const int wm = wid >> 1, wn = wid & 1;
    const int a_row = wm * 32 + (lane & 7) + ((lane & 8) ? 8 : 0);
    const int a_ub  = (lane & 16) ? 1 : 0;
    const int b_row0 = wn * 64 + (lane & 7) + ((lane & 16) ? 8 : 0);
    const int b_ub  = (lane & 8) ? 1 : 0;
#pragma unroll
    for (int ks = 0; ks < 4; ks++) {
        uint32_t ahi[2][4], alo[2][4];
#pragma unroll
        for (int mt = 0; mt < 2; mt++) {
            const int r = a_row + mt * 16;
            const int u = ks * 2 + a_ub;
            const uint32_t off = r * 128 + (uint32_t)(((u ^ (r & 7))) << 4);
            ldsm4(ahi[mt], aB + off);
            ldsm4(alo[mt], aB + 16384 + off);
        }
        uint32_t bhi[4][4], blo[4][4];
#pragma unroll
        for (int g = 0; g < 4; g++) {
            const int n = b_row0 + g * 16;
            const int u = ks * 2 + b_ub;
            const uint32_t off = n * 128 + (uint32_t)(((u ^ (n & 7))) << 4);
            ldsm4(bhi[g], bB + off);
            ldsm4(blo[g], bB + 16384 + off);
        }
#pragma unroll
        for (int mt = 0; mt < 2; mt++)
#pragma unroll
            for (int ntl = 0; ntl < 8; ntl++) {
                float* a_ = acc[mt][ntl];
                const uint32_t* bh = &bhi[ntl >> 1][(ntl & 1) * 2];
                const uint32_t* bl = &blo[ntl >> 1][(ntl & 1) * 2];
                mma16816(a_, ahi[mt], bh);
                mma16816(a_, ahi[mt], bl);
                mma16816(a_, alo[mt], bh);
            }
    }
}

__global__ __launch_bounds__(256, 1)
void hmma_gemm_o(const bf16* __restrict__ Ahi, const bf16* __restrict__ Alo,
                 const bf16* __restrict__ Bhi, const bf16* __restrict__ Blo,
                 float* __restrict__ Cf, int M)
{
    extern __shared__ char smem[];
    const uint32_t sb = smem_u32(smem);
    const int tid = threadIdx.x;
    const int wid = tid >> 5, lane = tid & 31;
    const int row0 = blockIdx.x * 128;

    const int lr = tid >> 1;
    const int arow = (row0 + lr < M) ? (row0 + lr) : (M - 1);

    float acc[2][8][4];
#pragma unroll
    for (int i = 0; i < 2; i++)
#pragma unroll
        for (int j = 0; j < 8; j++)
#pragma unroll
            for (int q = 0; q < 4; q++) acc[i][j][q] = 0.f;

    for (int kc = 0; kc < 2; kc++) {
        const int k0 = kc * 64;
#pragma unroll
        for (int i = 0; i < 4; i++) {
            const int u = (tid & 1) * 4 + i;
            const uint32_t d = lr * 128 + (uint32_t)(((u ^ (lr & 7))) << 4);
            cp16(sb + d,         (const char*)(Ahi + (size_t)arow * 128 + k0) + u * 16);
            cp16(sb + 16384 + d, (const char*)(Alo + (size_t)arow * 128 + k0) + u * 16);
        }
        for (int i = tid; i < 128 * 8; i += 256) {
            const int r = i >> 3, u = i & 7;
            const uint32_t d = r * 128 + (uint32_t)(((u ^ (r & 7))) << 4);
            cp16(sb + 32768 + d, (const char*)(Bhi + (size_t)r * 128 + k0) + u * 16);
            cp16(sb + 49152 + d, (const char*)(Blo + (size_t)r * 128 + k0) + u * 16);
        }
        CP_COMMIT();
        CP_WAIT(0);
        __syncthreads();
        ldsm_mma8(acc, sb, sb + 32768, tid);
        __syncthreads();
    }

    const int wm = wid >> 1, wn = wid & 1;
#pragma unroll
    for (int mt = 0; mt < 2; mt++) {
        const int r = row0 + wm * 32 + mt * 16 + (lane >> 2);
#pragma unroll
        for (int nt = 0; nt < 8; nt++) {
            const int c = wn * 64 + nt * 8 + (lane & 3) * 2;
#pragma unroll
            for (int half = 0; half < 2; half++) {
                const int rr = r + half * 8;
                if (rr >= M) continue;
                *(float2*)(Cf + (size_t)rr * 128 + c) =
                    make_float2(acc[mt][nt][half * 2], acc[mt][nt][half * 2 + 1]);
            }
        }
    }
}

// ---------------- host launch ----------------
extern "C" void kernel_launch(void* const* d_in, const int* in_sizes, int n_in,
                              void* d_out, int out_size)
{
    const float* h_V   = (const float*)d_in[0];
    const float* h_E   = (const float*)d_in[1];
    const int*   eidx  = (const int*)  d_in[2];
    const float* hvv   = (const float*)d_in[3];
    const float* frame = (const float*)d_in[4];
    const float* W_vec = (const float*)d_in[5];
    const float* W_red = (const float*)d_in[6];
    const float* Wb1   = (const float*)d_in[7];
    const float* bb1   = (const float*)d_in[8];
    const float* Wb2   = (const float*)d_in[9];
    const float* bb2   = (const float*)d_in[10];
    const float* Wb3   = (const float*)d_in[11];
    const float* bb3   = (const float*)d_in[12];
    const float* Wv1   = (const float*)d_in[13];
    const float* bv1   = (const float*)d_in[14];
    const float* Wv2   = (const float*)d_in[15];
    const float* bv2   = (const float*)d_in[16];
    const float* Wv3   = (const float*)d_in[17];
    const float* bv3   = (const float*)d_in[18];
    const float* W_O   = (const float*)d_in[19];
    const float* bn_g  = (const float*)d_in[20];
    const float* bn_b  = (const float*)d_in[21];

    int E = in_sizes[2] / 2;
    int N = in_sizes[0] / 128;
    float* out = (float*)d_out;

    float *vff, *hVW, *gsum, *hagg, *bnst;
    bf16 *hgh, *hgl, *wh, *wl;
    double* bnacc;
    cudaGetSymbolAddress((void**)&vff,   g_vff);
    cudaGetSymbolAddress((void**)&hVW,   g_hVW);
    cudaGetSymbolAddress((void**)&hgh,   g_hgh);
    cudaGetSymbolAddress((void**)&hgl,   g_hgl);
    cudaGetSymbolAddress((void**)&wh,    g_wh);
    cudaGetSymbolAddress((void**)&wl,    g_wl);
    cudaGetSymbolAddress((void**)&gsum,  g_sum);
    cudaGetSymbolAddress((void**)&hagg,  g_hagg);
    cudaGetSymbolAddress((void**)&bnacc, g_bnacc);
    cudaGetSymbolAddress((void**)&bnst,  g_bnst);

    const int SMEM_O = 65536;
    cudaFuncSetAttribute(mega_kernel, cudaFuncAttributeMaxDynamicSharedMemorySize, SMEM_MEGA);
    cudaFuncSetAttribute(hmma_gemm_o, cudaFuncAttributeMaxDynamicSharedMemorySize, SMEM_O);

    int Mt = (E + 127) / 128;
    int Mo = (N + 127) / 128;

    init_kernel<<<(N * 128 + 255) / 256, 256>>>(gsum, hagg, bnacc, N);
    geom_kernel<<<(E + 255) / 256, 256>>>(eidx, hvv, frame, W_vec, vff, bnacc, E);
    bn_finalize<<<1, 32>>>(bnacc, bn_g, bn_b, bnst, E);

    wprep_all<<<(W_TOTAL + 255) / 256, 256>>>(W_red, Wb1, Wb2, Wv1, Wv2, Wv3, W_O, wh, wl);
    hvw_kernel<<<(N + 1) / 2, 256>>>(h_V, Wb1, hVW, N);

    mega_kernel<<<Mt, 512, SMEM_MEGA>>>(
        vff, h_E, bnst, hVW, eidx,
        wh + OW_RED, wl + OW_RED,
        wh + OW_B1, wl + OW_B1, bb1,
        wh + OW_B2, wl + OW_B2, bb2,
        Wb3, bb3,
        wh + OW_V1, wl + OW_V1, bv1,
        wh + OW_V2, wl + OW_V2, bv2,
        wh + OW_V3, wl + OW_V3, bv3,
        gsum, hagg, E);

    // hagg normalized by segment sums -> planes, then out = hagg @ W_O
    c2planes_norm<<<(N * 128 + 255) / 256, 256>>>(hagg, gsum, hgh, hgl, N);
    hmma_gemm_o<<<Mo, 256, SMEM_O>>>(hgh, hgl, wh + OW_O, wl + OW_O, out, N);
}

// round 12
// speedup vs baseline: 1.1329x; 1.0692x over previous
#include <cuda_runtime.h>
#include <cuda_bf16.h>
#include <math.h>
#include <stdint.h>

#define E_CONST 320000
#define N_CONST 10000
typedef __nv_bfloat16 bf16;

// ---------------- scratch (no allocations allowed) ----------------
static __device__ float    g_vff [(size_t)E_CONST * 64];   // fp32 [sincos48|dist16]
static __device__ float    g_hVW [N_CONST * 128];          // hV @ Wb1_top (fp32, per node)
static __device__ bf16     g_hgh [N_CONST * 128];
static __device__ bf16     g_hgl [N_CONST * 128];
static __device__ bf16     g_wh  [262144];                 // all weights, [n][k]
static __device__ bf16     g_wl  [262144];
static __device__ float    g_sum [N_CONST * 4];
static __device__ float    g_hagg[N_CONST * 128];
static __device__ double   g_bnacc[32];
static __device__ float    g_bnst[32];

// weight plane offsets (elements)
#define OW_RED 0        // 256 x 320
#define OW_B1  81920    // 128 x 384
#define OW_B2  131072   // 128 x 128
#define OW_V1  147456   // 128 x 256
#define OW_V2  180224   // 128 x 128
#define OW_V3  196608   // 128 x 128
#define OW_O   212992   // 128 x 128
#define W_TOTAL 229376

// mega smem tail (beyond the 224KB working set)
#define ATT_OFF 229376
#define CEN_OFF 231424
#define SMEM_MEGA 231936

// ---------------- helpers ----------------
__device__ __forceinline__ uint32_t smem_u32(const void* p) {
    uint32_t a;
    asm("{ .reg .u64 t; cvta.to.shared.u64 t, %1; cvt.u32.u64 %0, t; }" : "=r"(a) : "l"(p));
    return a;
}
__device__ __forceinline__ void cp16(uint32_t dst, const void* src) {
    asm volatile("cp.async.cg.shared.global [%0], [%1], 16;"
        :: "r"(dst), "l"(__cvta_generic_to_global(src)) : "memory");
}
#define CP_COMMIT() asm volatile("cp.async.commit_group;" ::: "memory")
#define CP_WAIT(n)  asm volatile("cp.async.wait_group %0;" :: "n"(n) : "memory")

__device__ __forceinline__ void ldsm4(uint32_t* r, uint32_t addr) {
    asm volatile("ldmatrix.sync.aligned.m8n8.x4.shared.b16 {%0,%1,%2,%3}, [%4];"
        : "=r"(r[0]), "=r"(r[1]), "=r"(r[2]), "=r"(r[3]) : "r"(addr));
}
__device__ __forceinline__ void mma16816(float* d, const uint32_t* a, const uint32_t* b) {
    asm volatile(
        "mma.sync.aligned.m16n8k16.row.col.f32.bf16.bf16.f32 "
        "{%0,%1,%2,%3}, {%4,%5,%6,%7}, {%8,%9}, {%0,%1,%2,%3};"
        : "+f"(d[0]), "+f"(d[1]), "+f"(d[2]), "+f"(d[3])
        : "r"(a[0]), "r"(a[1]), "r"(a[2]), "r"(a[3]), "r"(b[0]), "r"(b[1]));
}
__device__ __forceinline__ void red2(float* addr, float x, float y) {
    asm volatile("red.global.v2.f32.add [%0], {%1, %2};"
        :: "l"(__cvta_generic_to_global(addr)), "f"(x), "f"(y) : "memory");
}
__device__ __forceinline__ float gelu_f(float x) {
    return 0.5f * x * (1.f + erff(x * 0.70710678118654752f));
}

// ---------------- init ----------------
__global__ void init_kernel(float* gsum, float* hagg, double* bnacc, int N)
{
    int i = blockIdx.x * 256 + threadIdx.x;
    if (i < N * 128) hagg[i] = 0.f;
    if (i < N * 4) gsum[i] = 0.f;
    if (i < 32) bnacc[i] = 0.0;
}

// ---------------- geometry + BN stats (vectorized loads, smem-transposed stores) ----------------
__global__ __launch_bounds__(256)
void geom_kernel(const int* __restrict__ eidx, const float* __restrict__ hvv,
                 const float* __restrict__ frame, const float* __restrict__ Wvec,
                 float* __restrict__ vff, double* __restrict__ bnacc, int E)
{
    extern __shared__ float sbuf[];   // 256 * 65 floats (padded rows)
    __shared__ float Ws[512];
    __shared__ float bsum[16], bsq[16];
    int tid = threadIdx.x;
    for (int i = tid; i < 512; i += 256) Ws[i] = Wvec[i];
    if (tid < 16) { bsum[tid] = 0.f; bsq[tid] = 0.f; }
    __syncthreads();

    const int e0 = blockIdx.x * 256;
    const int e = e0 + tid;
    float dloc[16];
#pragma unroll
    for (int o = 0; o < 16; o++) dloc[o] = 0.f;

    if (e < E) {
        const int c = eidx[e];
        const int d = eidx[E + e];
        float F[9];
#pragma unroll
        for (int i = 0; i < 9; i++) F[i] = frame[e * 9 + i];

        float vdt[48], vsrc[48];
        {
            const float4* pd = (const float4*)(hvv + (size_t)d * 48);
            const float4* pc = (const float4*)(hvv + (size_t)c * 48);
#pragma unroll
            for (int i = 0; i < 12; i++) {
                ((float4*)vdt)[i]  = pd[i];
                ((float4*)vsrc)[i] = pc[i];
            }
        }
        // rotate dst vectors in place
#pragma unroll
        for (int v = 0; v < 16; v++) {
            const float x = vdt[v * 3 + 0], y = vdt[v * 3 + 1], z = vdt[v * 3 + 2];
            vdt[v * 3 + 0] = F[0] * x + F[1] * y + F[2] * z;
            vdt[v * 3 + 1] = F[3] * x + F[4] * y + F[5] * z;
            vdt[v * 3 + 2] = F[6] * x + F[7] * y + F[8] * z;
        }

        float* row = sbuf + tid * 65;
#pragma unroll
        for (int o = 0; o < 16; o++) {
            float v0 = vdt[o * 3 + 0], v1 = vdt[o * 3 + 1], v2 = vdt[o * 3 + 2];
#pragma unroll
            for (int v = 0; v < 16; v++) {
                const float wa = Ws[o * 32 + v], wb = Ws[o * 32 + 16 + v];
                v0 += wa * vdt[v * 3 + 0] + wb * vsrc[v * 3 + 0];
                v1 += wa * vdt[v * 3 + 1] + wb * vsrc[v * 3 + 1];
                v2 += wa * vdt[v * 3 + 2] + wb * vsrc[v * 3 + 2];
            }
            const float dist = sqrtf(v0 * v0 + v1 * v1 + v2 * v2) + 1e-6f;
            const float inv = 1.f / dist;
            row[o * 3 + 0] = v0 * inv;
            row[o * 3 + 1] = v1 * inv;
            row[o * 3 + 2] = v2 * inv;
            row[48 + o] = dist;
            dloc[o] = dist;
        }
    }

    // BN partials
#pragma unroll
    for (int o = 0; o < 16; o++) {
        float v = dloc[o], v2 = v * v;
#pragma unroll
        for (int off = 16; off; off >>= 1) {
            v  += __shfl_down_sync(0xffffffffu, v, off);
            v2 += __shfl_down_sync(0xffffffffu, v2, off);
        }
        if ((tid & 31) == 0) { atomicAdd(&bsum[o], v); atomicAdd(&bsq[o], v2); }
    }
    __syncthreads();
    if (tid < 16) {
        atomicAdd(&bnacc[tid], (double)bsum[tid]);
        atomicAdd(&bnacc[16 + tid], (double)bsq[tid]);
    }

    // coalesced writeback: 16 float4s per edge row
    const int nblk = (E - e0 < 256) ? (E - e0) : 256;
    for (int j = tid; j < nblk * 16; j += 256) {
        const int r = j >> 4, q = (j & 15) * 4;
        const float* sr = sbuf + r * 65 + q;
        *(float4*)(vff + (size_t)(e0 + r) * 64 + q) =
            make_float4(sr[0], sr[1], sr[2], sr[3]);
    }
}

__global__ void bn_finalize(const double* __restrict__ acc, const float* __restrict__ g,
                            const float* __restrict__ b, float* __restrict__ st, int E)
{
    int i = threadIdx.x;
    if (i >= 16) return;
    double mean = acc[i] / (double)E;
    double var  = acc[16 + i] / (double)E - mean * mean;
    float s = (float)((double)g[i] / sqrt(var + 1e-5));
    st[i] = s;
    st[16 + i] = b[i] - (float)mean * s;
}

// ---------------- conversion passes ----------------
__global__ void wprep_all(const float* __restrict__ W0, const float* __restrict__ W1,
                          const float* __restrict__ W2, const float* __restrict__ W3,
                          const float* __restrict__ W4, const float* __restrict__ W5,
                          const float* __restrict__ W6,
                          bf16* __restrict__ hi, bf16* __restrict__ lo)
{
    int idx = blockIdx.x * 256 + threadIdx.x;
    if (idx >= W_TOTAL) return;
    const float* src; int K, NT, start;
    if      (idx < OW_B1)  { src = W0; K = 320; NT = 256; start = OW_RED; }
    else if (idx < OW_B2)  { src = W1; K = 384; NT = 128; start = OW_B1; }
    else if (idx < OW_V1)  { src = W2; K = 128; NT = 128; start = OW_B2; }
    else if (idx < OW_V2)  { src = W3; K = 256; NT = 128; start = OW_V1; }
    else if (idx < OW_V3)  { src = W4; K = 128; NT = 128; start = OW_V2; }
    else if (idx < OW_O)   { src = W5; K = 128; NT = 128; start = OW_V3; }
    else                   { src = W6; K = 128; NT = 128; start = OW_O; }
    int local = idx - start;
    int k = local / NT, n = local % NT;
    float v = src[local];
    bf16 h = __float2bfloat16_rn(v);
    hi[start + (size_t)n * K + k] = h;
    lo[start + (size_t)n * K + k] = __float2bfloat16_rn(v - __bfloat162float(h));
}

// hVW = hV @ Wb1[0:128,:]  (exact fp32, per-node)
__global__ __launch_bounds__(256)
void hvw_kernel(const float* __restrict__ hV, const float* __restrict__ Wb1,
                float* __restrict__ hVW, int N)
{
    __shared__ float xs[2][128];
    const int t = threadIdx.x;
    const int which = t >> 7, c = t & 127;
    const int node = blockIdx.x * 2 + which;
    if (node < N) xs[which][c] = hV[(size_t)node * 128 + c];
    __syncthreads();
    if (node >= N) return;
    float s = 0.f;
#pragma unroll 8
    for (int k = 0; k < 128; k++) s += xs[which][k] * Wb1[k * 128 + c];
    hVW[(size_t)node * 128 + c] = s;
}

// hagg -> planes with softmax normalization folded in
__global__ void c2planes_norm(const float* __restrict__ x, const float* __restrict__ gsum,
                              bf16* __restrict__ hi, bf16* __restrict__ lo, int N)
{
    int i = blockIdx.x * 256 + threadIdx.x;
    if (i >= N * 128) return;
    int node = i >> 7, col = i & 127;
    float s = gsum[node * 4 + (col >> 5)];
    float v = x[i] / (s > 0.f ? s : 1.f);
    bf16 h = __float2bfloat16_rn(v);
    hi[i] = h;
    lo[i] = __float2bfloat16_rn(v - __bfloat162float(h));
}

// ================= GEMM building blocks (512 threads, 16 warps = 4m x 4n) =================
template<int NT>
__device__ __forceinline__ void mma_half512(
    float (&acc)[2][NT][4], uint32_t aHi, uint32_t aLo,
    uint32_t bHi, uint32_t bLo, int ks0, int tid)
{
    const int wid = tid >> 5, lane = tid & 31;
    const int wm = wid >> 2, wn = wid & 3;
    const int a_row = wm * 32 + (lane & 7) + ((lane & 8) ? 8 : 0);
    const int a_ub  = (lane & 16) ? 1 : 0;
    const int b_row0 = wn * (NT * 8) + (lane & 7) + ((lane & 16) ? 8 : 0);
    const int b_ub  = (lane & 8) ? 1 : 0;
#pragma unroll
    for (int kss = 0; kss < 2; kss++) {
        const int ks = ks0 + kss;
        uint32_t ahi[2][4], alo[2][4];
#pragma unroll
        for (int mt = 0; mt < 2; mt++) {
            const int r = a_row + mt * 16;
            const int u = ks * 2 + a_ub;
            const uint32_t off = r * 128 + (uint32_t)(((u ^ (r & 7))) << 4);
            ldsm4(ahi[mt], aHi + off);
            ldsm4(alo[mt], aLo + off);
        }
        uint32_t bhi[NT / 2][4], blo[NT / 2][4];
#pragma unroll
        for (int g = 0; g < NT / 2; g++) {
            const int n = b_row0 + g * 16;
            const int u = ks * 2 + b_ub;
            const uint32_t off = n * 128 + (uint32_t)(((u ^ (n & 7))) << 4);
            ldsm4(bhi[g], bHi + off);
            ldsm4(blo[g], bLo + off);
        }
#pragma unroll
        for (int mt = 0; mt < 2; mt++)
#pragma unroll
            for (int ntl = 0; ntl < NT; ntl++) {
                float* a_ = acc[mt][ntl];
                const uint32_t* bh = &bhi[ntl >> 1][(ntl & 1) * 2];
                const uint32_t* bl = &blo[ntl >> 1][(ntl & 1) * 2];
                mma16816(a_, ahi[mt], bh);
                mma16816(a_, ahi[mt], bl);
                mma16816(a_, alo[mt], bh);
            }
    }
}

__device__ __forceinline__ void stage_half(uint32_t dstHi, uint32_t dstLo,
                                           const bf16* __restrict__ Whi,
                                           const bf16* __restrict__ Wlo,
                                           int K, int k0, int half, int rows, int tid)
{
    for (int i = tid; i < rows * 4; i += 512) {
        const int r = i >> 2, u = (i & 3) + half * 4;
        const uint32_t d = r * 128 + (uint32_t)(((u ^ (r & 7))) << 4);
        cp16(dstHi + d, (const char*)(Whi + (size_t)r * K + k0) + u * 16);
        cp16(dstLo + d, (const char*)(Wlo + (size_t)r * K + k0) + u * 16);
    }
    CP_COMMIT();
}

// stage 2 full 64-K chunks (128 rows) of weight planes into dst (hi: +0, lo: +32K)
__device__ __forceinline__ void stage_chunks2(uint32_t dst,
                                              const bf16* __restrict__ Whi,
                                              const bf16* __restrict__ Wlo,
                                              int K, int k0, int tid)
{
    for (int i = tid; i < 2048; i += 512) {
        const int ch = i >> 10, rem = i & 1023;
        const int r = rem >> 3, u = rem & 7;
        const uint32_t d = ch * 16384 + r * 128 + (uint32_t)(((u ^ (r & 7))) << 4);
        cp16(dst + d,         (const char*)(Whi + (size_t)r * K + k0 + ch * 64) + u * 16);
        cp16(dst + 32768 + d, (const char*)(Wlo + (size_t)r * K + k0 + ch * 64) + u * 16);
    }
    CP_COMMIT();
}

template<int NT, typename FA>
__device__ __forceinline__ void run_phase(float (&acc)[2][NT][4], FA addrA,
                                          const bf16* __restrict__ Wh, const bf16* __restrict__ Wl,
                                          int K, int k0base, int nch,
                                          uint32_t bHi, uint32_t bLo, int tid)
{
    stage_half(bHi, bLo, Wh, Wl, K, k0base, 0, 128, tid);
    const int H = nch * 2;
    for (int h = 0; h < H; h++) {
        if (h + 1 < H) {
            stage_half(bHi, bLo, Wh, Wl, K, k0base + ((h + 1) >> 1) * 64, (h + 1) & 1, 128, tid);
            CP_WAIT(1);
        } else {
            CP_WAIT(0);
        }
        __syncthreads();
        uint32_t aHi, aLo;
        addrA(h >> 1, aHi, aLo);
        mma_half512<NT>(acc, aHi, aLo, bHi, bLo, (h & 1) * 2, tid);
        __syncthreads();
    }
}

template<int NT, int ACT>
__device__ __forceinline__ void store_planes512(const float (&acc)[2][NT][4],
                                                char* smemp, uint32_t baseHi, uint32_t baseLo,
                                                const float* __restrict__ bias, int tid)
{
    const int wid = tid >> 5, lane = tid & 31;
    const int wm = wid >> 2, wn = wid & 3;
#pragma unroll
    for (int mt = 0; mt < 2; mt++)
#pragma unroll
        for (int nt = 0; nt < NT; nt++) {
            const int c = wn * (NT * 8) + nt * 8 + (lane & 3) * 2;
            const int kc = c >> 6, kk = c & 63, u = kk >> 3;
            const float b0 = bias ? bias[c] : 0.f;
            const float b1 = bias ? bias[c + 1] : 0.f;
#pragma unroll
            for (int half = 0; half < 2; half++) {
                const int r = wm * 32 + mt * 16 + (lane >> 2) + half * 8;
                float e0 = acc[mt][nt][half * 2] + b0;
                float e1 = acc[mt][nt][half * 2 + 1] + b1;
                if (ACT == 1) { e0 = fmaxf(e0, 0.f); e1 = fmaxf(e1, 0.f); }
                if (ACT == 2) { e0 = gelu_f(e0); e1 = gelu_f(e1); }
                bf16 h0 = __float2bfloat16_rn(e0);
                bf16 h1 = __float2bfloat16_rn(e1);
                __nv_bfloat162 hp; hp.x = h0; hp.y = h1;
                __nv_bfloat162 lp;
                lp.x = __float2bfloat16_rn(e0 - __bfloat162float(h0));
                lp.y = __float2bfloat16_rn(e1 - __bfloat162float(h1));
                const uint32_t ad = kc * 16384 + r * 128 +
                                    (uint32_t)(((u ^ (r & 7))) << 4) + (kk & 7) * 2;
                *(__nv_bfloat162*)(smemp + baseHi + ad) = hp;
                *(__nv_bfloat162*)(smemp + baseLo + ad) = lp;
            }
        }
}

// ---------------- MEGA kernel (512 threads) ----------------
// smem: [0,64K) heHi, [64K,128K) heLo, [128K,192K) xv, [192K,224K) stg,
//       [224K,226K) att (e values), [226K,226.5K) cen
__global__ __launch_bounds__(512, 1)
void mega_kernel(const float* __restrict__ Vff, const float* __restrict__ HE,
                 const float* __restrict__ bn_st,
                 const float* __restrict__ hVW,
                 const int* __restrict__ eidx,
                 const bf16* __restrict__ wredh, const bf16* __restrict__ wredl,
                 const bf16* __restrict__ wb1h, const bf16* __restrict__ wb1l,
                 const float* __restrict__ bb1,
                 const bf16* __restrict__ wb2h, const bf16* __restrict__ wb2l,
                 const float* __restrict__ bb2,
                 const float* __restrict__ Wb3, const float* __restrict__ bb3,
                 const bf16* __restrict__ wv1h, const bf16* __restrict__ wv1l,
                 const float* __restrict__ bv1,
                 const bf16* __restrict__ wv2h, const bf16* __restrict__ wv2l,
                 const float* __restrict__ bv2,
                 const bf16* __restrict__ wv3h, const bf16* __restrict__ wv3l,
                 const float* __restrict__ bv3,
                 float* __restrict__ gsum, float* __restrict__ hagg, int M)
{
    extern __shared__ char smem[];
    const uint32_t sb = smem_u32(smem);
    const uint32_t heHi = sb;
    const uint32_t heLo = sb + 65536;
    const uint32_t xv   = sb + 131072;
    const uint32_t stg  = sb + 196608;
    const int tid = threadIdx.x;
    const int wid = tid >> 5, lane = tid & 31;
    const int row0 = blockIdx.x * 128;

    const int lr = tid >> 2;              // 4 threads per row
    const int arow = (row0 + lr < M) ? (row0 + lr) : (M - 1);
    const int cu0 = (tid & 3) * 4;        // fp32 16B-unit base for A convert

    // center table for this tile (used by P1 epilogue and P3/P6)
    {
        int* cens = (int*)(smem + CEN_OFF);
        if (tid < 128) {
            int er = row0 + tid;
            cens[tid] = eidx[er < M ? er : M - 1];
        }
    }

    // ================= P0: hE = [vff_bn | h_E] @ W_red (K=320, N=256) =================
    {
        float acc0[2][8][4];
#pragma unroll
        for (int i = 0; i < 2; i++)
#pragma unroll
            for (int j = 0; j < 8; j++)
#pragma unroll
                for (int q = 0; q < 4; q++) acc0[i][j][q] = 0.f;

        float4 areg[4];
        {
            const float4* pa = (const float4*)(Vff + (size_t)arow * 64);
#pragma unroll
            for (int jj = 0; jj < 4; jj++) areg[jj] = pa[cu0 + jj];
        }
        stage_half(xv + 32768, stg, wredh, wredl, 320, 0, 0, 256, tid);

        for (int kc = 0; kc < 5; kc++) {
            {
                float4 f[4];
#pragma unroll
                for (int jj = 0; jj < 4; jj++) f[jj] = areg[jj];
                if (kc == 0 && cu0 >= 12) {
#pragma unroll
                    for (int jj = 0; jj < 4; jj++) {
                        const int u = cu0 + jj;
                        if (u >= 12) {
                            const int col = u * 4;
                            f[jj].x = fmaf(f[jj].x, bn_st[col - 48], bn_st[col - 32]);
                            f[jj].y = fmaf(f[jj].y, bn_st[col - 47], bn_st[col - 31]);
                            f[jj].z = fmaf(f[jj].z, bn_st[col - 46], bn_st[col - 30]);
                            f[jj].w = fmaf(f[jj].w, bn_st[col - 45], bn_st[col - 29]);
                        }
                    }
                }
#pragma unroll
                for (int jj = 0; jj < 2; jj++) {
                    float v[8] = {f[2 * jj].x, f[2 * jj].y, f[2 * jj].z, f[2 * jj].w,
                                  f[2 * jj + 1].x, f[2 * jj + 1].y, f[2 * jj + 1].z, f[2 * jj + 1].w};
                    uint32_t ph[4], pl[4];
#pragma unroll
                    for (int j = 0; j < 4; j++) {
                        float a = v[2 * j], b = v[2 * j + 1];
                        bf16 ha = __float2bfloat16_rn(a);
                        bf16 hb = __float2bfloat16_rn(b);
                        __nv_bfloat162 hp; hp.x = ha; hp.y = hb;
                        __nv_bfloat162 lp;
                        lp.x = __float2bfloat16_rn(a - __bfloat162float(ha));
                        lp.y = __float2bfloat16_rn(b - __bfloat162float(hb));
                        ph[j] = reinterpret_cast<uint32_t&>(hp);
                        pl[j] = reinterpret_cast<uint32_t&>(lp);
                    }
                    const int un = (cu0 >> 1) + jj;
                    const uint32_t ad = lr * 128 + (uint32_t)(((un ^ (lr & 7))) << 4);
                    *(uint4*)(smem + 131072 + ad)         = make_uint4(ph[0], ph[1], ph[2], ph[3]);
                    *(uint4*)(smem + 131072 + 16384 + ad) = make_uint4(pl[0], pl[1], pl[2], pl[3]);
                }
            }
            if (kc < 4) {
                const float4* pa = (const float4*)(HE + (size_t)arow * 256 + kc * 64);
#pragma unroll
                for (int jj = 0; jj < 4; jj++) areg[jj] = pa[cu0 + jj];
            }
#pragma unroll
            for (int hh = 0; hh < 2; hh++) {
                const int h = kc * 2 + hh;
                if (h + 1 < 10) {
                    stage_half(xv + 32768, stg, wredh, wredl, 320,
                               ((h + 1) >> 1) * 64, (h + 1) & 1, 256, tid);
                    CP_WAIT(1);
                } else {
                    CP_WAIT(0);
                }
                __syncthreads();
                mma_half512<8>(acc0, xv, xv + 16384, xv + 32768, stg, hh * 2, tid);
                __syncthreads();
            }
        }

        // overlap: stage Wb1 batch0 (K cols 128..255) into xv during P0 epilogue
        stage_chunks2(xv, wb1h, wb1l, 384, 128, tid);
        store_planes512<8, 0>(acc0, smem, 0, 65536, nullptr, tid);
    }
    __syncthreads();

    // ================= P1: x1 = relu(hVW[center] + hE @ Wb1_bot + bb1), K=256 =================
    float acc1[2][4][4];
#pragma unroll
    for (int i = 0; i < 2; i++)
#pragma unroll
        for (int j = 0; j < 4; j++)
#pragma unroll
            for (int q = 0; q < 4; q++) acc1[i][j][q] = 0.f;
    {
        CP_WAIT(0);
        __syncthreads();
        mma_half512<4>(acc1, heHi,         heLo,         xv,         xv + 32768, 0, tid);
        mma_half512<4>(acc1, heHi,         heLo,         xv,         xv + 32768, 2, tid);
        mma_half512<4>(acc1, heHi + 16384, heLo + 16384, xv + 16384, xv + 49152, 0, tid);
        mma_half512<4>(acc1, heHi + 16384, heLo + 16384, xv + 16384, xv + 49152, 2, tid);
        __syncthreads();
        stage_chunks2(xv, wb1h, wb1l, 384, 256, tid);
        CP_WAIT(0);
        __syncthreads();
        mma_half512<4>(acc1, heHi + 32768, heLo + 32768, xv,         xv + 32768, 0, tid);
        mma_half512<4>(acc1, heHi + 32768, heLo + 32768, xv,         xv + 32768, 2, tid);
        mma_half512<4>(acc1, heHi + 49152, heLo + 49152, xv + 16384, xv + 49152, 0, tid);
        mma_half512<4>(acc1, heHi + 49152, heLo + 49152, xv + 16384, xv + 49152, 2, tid);
        __syncthreads();

        // epilogue: fused per-fragment global hVW read + bias + relu -> x1 planes in xv
        const int* cens = (const int*)(smem + CEN_OFF);
        const int wm = wid >> 2, wn = wid & 3;
#pragma unroll
        for (int mt = 0; mt < 2; mt++)
#pragma unroll
            for (int nt = 0; nt < 4; nt++) {
                const int c = wn * 32 + nt * 8 + (lane & 3) * 2;
                const int kc = c >> 6, kk = c & 63, u = kk >> 3;
                const float b0 = bb1[c], b1 = bb1[c + 1];
#pragma unroll
                for (int half = 0; half < 2; half++) {
                    const int r = wm * 32 + mt * 16 + (lane >> 2) + half * 8;
                    const float2 hv = *(const float2*)(hVW + (size_t)cens[r] * 128 + c);
                    float e0 = fmaxf(acc1[mt][nt][half * 2] + b0 + hv.x, 0.f);
                    float e1 = fmaxf(acc1[mt][nt][half * 2 + 1] + b1 + hv.y, 0.f);
                    bf16 h0 = __float2bfloat16_rn(e0);
                    bf16 h1 = __float2bfloat16_rn(e1);
                    __nv_bfloat162 hp; hp.x = h0; hp.y = h1;
                    __nv_bfloat162 lp;
                    lp.x = __float2bfloat16_rn(e0 - __bfloat162float(h0));
                    lp.y = __float2bfloat16_rn(e1 - __bfloat162float(h1));
                    const uint32_t ad = kc * 16384 + r * 128 +
                                        (uint32_t)(((u ^ (r & 7))) << 4) + (kk & 7) * 2;
                    *(__nv_bfloat162*)(smem + 131072 + ad) = hp;
                    *(__nv_bfloat162*)(smem + 131072 + 32768 + ad) = lp;
                }
            }
    }
    __syncthreads();

    // ================= P2: x2 = relu(x1 @ Wb2 + bb2) =================
    float acc2[2][4][4];
#pragma unroll
    for (int i = 0; i < 2; i++)
#pragma unroll
        for (int j = 0; j < 4; j++)
#pragma unroll
            for (int q = 0; q < 4; q++) acc2[i][j][q] = 0.f;
    run_phase<4>(acc2,
        [&](int kc, uint32_t& aHi, uint32_t& aLo) {
            aHi = xv + kc * 16384; aLo = xv + 32768 + kc * 16384;
        },
        wb2h, wb2l, 128, 0, 2, stg, stg + 16384, tid);

    // x2 fp32 -> xv (x1 dead)
    {
        const int wm = wid >> 2, wn = wid & 3;
#pragma unroll
        for (int mt = 0; mt < 2; mt++)
#pragma unroll
            for (int nt = 0; nt < 4; nt++) {
                const int c = wn * 32 + nt * 8 + (lane & 3) * 2;
                const float b0 = bb2[c], b1 = bb2[c + 1];
#pragma unroll
                for (int half = 0; half < 2; half++) {
                    const int r = wm * 32 + mt * 16 + (lane >> 2) + half * 8;
                    float e0 = fmaxf(acc2[mt][nt][half * 2] + b0, 0.f);
                    float e1 = fmaxf(acc2[mt][nt][half * 2 + 1] + b1, 0.f);
                    *(float2*)(smem + 131072 + ((size_t)r * 128 + c) * 4) = make_float2(e0, e1);
                }
            }
    }
    // Wb3 transposed into stg
    {
        float* wb3s = (float*)(smem + 196608);
        if (tid < 128) {
#pragma unroll
            for (int h = 0; h < 4; h++) wb3s[h * 128 + tid] = Wb3[tid * 8 + h];
        }
    }
    __syncthreads();

    // ================= P3: e = exp(logits), segment sum =================
    {
        const float* x2s = (const float*)(smem + 131072);
        const float* wb3s = (const float*)(smem + 196608);
        float* atts = (float*)(smem + ATT_OFF);
        const int* cens = (const int*)(smem + CEN_OFF);
        for (int rr = wid * 8; rr < wid * 8 + 8; rr++) {
            const int e = row0 + rr;
            if (e >= M) break;
            float p0 = 0.f, p1 = 0.f, p2 = 0.f, p3 = 0.f;
#pragma unroll
            for (int j = 0; j < 4; j++) {
                const int c = lane + j * 32;
                const float x = x2s[rr * 128 + c];
                p0 += x * wb3s[c];
                p1 += x * wb3s[128 + c];
                p2 += x * wb3s[256 + c];
                p3 += x * wb3s[384 + c];
            }
#pragma unroll
            for (int off = 16; off; off >>= 1) {
                p0 += __shfl_xor_sync(0xffffffffu, p0, off);
                p1 += __shfl_xor_sync(0xffffffffu, p1, off);
                p2 += __shfl_xor_sync(0xffffffffu, p2, off);
                p3 += __shfl_xor_sync(0xffffffffu, p3, off);
            }
            if (lane < 4) {
                const float p = (lane == 0) ? p0 : (lane == 1) ? p1 : (lane == 2) ? p2 : p3;
                const float l = (p + bb3[lane]) * 0.17677669529663687f;
                const float ex = expf(l);
                atts[rr * 4 + lane] = ex;
                atomicAdd(&gsum[cens[rr] * 4 + lane], ex);
            }
        }
    }
    __syncthreads();

    // ================= P4: v1 = gelu(hE @ Wv1 + bv1), batched weights in xv =================
    float acc3[2][4][4];
#pragma unroll
    for (int i = 0; i < 2; i++)
#pragma unroll
        for (int j = 0; j < 4; j++)
#pragma unroll
            for (int q = 0; q < 4; q++) acc3[i][j][q] = 0.f;
    stage_chunks2(xv, wv1h, wv1l, 256, 0, tid);
    CP_WAIT(0);
    __syncthreads();
#pragma unroll
    for (int h = 0; h < 4; h++)
        mma_half512<4>(acc3, heHi + (h >> 1) * 16384, heLo + (h >> 1) * 16384,
                       xv + (h >> 1) * 16384, xv + 32768 + (h >> 1) * 16384, (h & 1) * 2, tid);
    __syncthreads();
    stage_chunks2(xv, wv1h, wv1l, 256, 128, tid);
    CP_WAIT(0);
    __syncthreads();
#pragma unroll
    for (int h = 0; h < 4; h++)
        mma_half512<4>(acc3, heHi + (2 + (h >> 1)) * 16384, heLo + (2 + (h >> 1)) * 16384,
                       xv + (h >> 1) * 16384, xv + 32768 + (h >> 1) * 16384, (h & 1) * 2, tid);
    __syncthreads();
    // overlap: stage Wv2 -> heLo region (hE dead after P4) while storing v1 planes -> xv
    stage_chunks2(heLo, wv2h, wv2l, 128, 0, tid);
    store_planes512<4, 2>(acc3, smem, 131072, 131072 + 32768, bv1, tid);  // v1 -> xv
    CP_WAIT(0);
    __syncthreads();

    // ================= P5: v2 = gelu(v1 @ Wv2 + bv2) =================
    float acc4[2][4][4];
#pragma unroll
    for (int i = 0; i < 2; i++)
#pragma unroll
        for (int j = 0; j < 4; j++)
#pragma unroll
            for (int q = 0; q < 4; q++) acc4[i][j][q] = 0.f;
#pragma unroll
    for (int h = 0; h < 4; h++)
        mma_half512<4>(acc4, xv + (h >> 1) * 16384, xv + 32768 + (h >> 1) * 16384,
                       heLo + (h >> 1) * 16384, heLo + 32768 + (h >> 1) * 16384, (h & 1) * 2, tid);
    __syncthreads();
    // overlap: stage Wv3 -> xv (v1 dead) while storing v2 planes -> heHi region
    stage_chunks2(xv, wv3h, wv3l, 128, 0, tid);
    store_planes512<4, 2>(acc4, smem, 0, 32768, bv2, tid);   // v2 -> heHi region (hE dead)
    CP_WAIT(0);
    __syncthreads();

    // ================= P6: V = v2 @ Wv3 + bv3; hagg[center] += e * V =================
    float acc5[2][4][4];
#pragma unroll
    for (int i = 0; i < 2; i++)
#pragma unroll
        for (int j = 0; j < 4; j++)
#pragma unroll
            for (int q = 0; q < 4; q++) acc5[i][j][q] = 0.f;
#pragma unroll
    for (int h = 0; h < 4; h++)
        mma_half512<4>(acc5, heHi + (h >> 1) * 16384, heHi + 32768 + (h >> 1) * 16384,
                       xv + (h >> 1) * 16384, xv + 32768 + (h >> 1) * 16384, (h & 1) * 2, tid);
    {
        const float* atts = (const float*)(smem + ATT_OFF);
        const int* cens = (const int*)(smem + CEN_OFF);
        const int wm = wid >> 2, wn = wid & 3;
#pragma unroll
        for (int mt = 0; mt < 2; mt++) {
#pragma unroll
            for (int nt = 0; nt < 4; nt++) {
                const int c = wn * 32 + nt * 8 + (lane & 3) * 2;
                const int h = c >> 5;
                const float b0 = bv3[c], b1 = bv3[c + 1];
#pragma unroll
                for (int half = 0; half < 2; half++) {
                    const int rl = wm * 32 + mt * 16 + (lane >> 2) + half * 8;
                    if (row0 + rl < M) {
                        const float a = atts[rl * 4 + h];
                        float* dst = hagg + (size_t)cens[rl] * 128 + c;
                        red2(dst, (acc5[mt][nt][half * 2] + b0) * a,
                                  (acc5[mt][nt][half * 2 + 1] + b1) * a);
                    }
                }
            }
        }
    }
}

// ---------------- standalone GEMM (W_O), 256 threads ----------------
__device__ __forceinline__ void ldsm_mma8(float (&acc)[2][8][4], uint32_t aB, uint32_t bB, int tid)
{
    const int wid = tid >> 5, lane = tid & 31;
    const int wm = wid >> 1, wn = wid & 1;
    const int a_row = wm * 32 + (lane & 7) + ((lane & 8) ? 8 : 0);
    const int a_ub  = (lane & 16) ? 1 : 0;
    const int b_row0 = wn * 64 + (lane & 7) + ((lane & 16) ? 8 : 0);
    const int b_ub  = (lane & 8) ? 1 : 0;
#pragma unroll
    for (int ks = 0; ks < 4; ks++) {
        uint32_t ahi[2][4], alo[2][4];
#pragma unroll
        for (int mt = 0; mt < 2; mt++) {
            const int r = a_row + mt * 16;
            const int u = ks * 2 + a_ub;
            const uint32_t off = r * 128 + (uint32_t)(((u ^ (r & 7))) << 4);
            ldsm4(ahi[mt], aB + off);
            ldsm4(alo[mt], aB + 16384 + off);
        }
        uint32_t bhi[4][4], blo[4][4];
#pragma unroll
        for (int g = 0; g < 4; g++) {
            const int n = b_row0 + g * 16;
            const int u = ks * 2 + b_ub;
            const uint32_t off = n * 128 + (uint32_t)(((u ^ (n & 7))) << 4);
            ldsm4(bhi[g], bB + off);
            ldsm4(blo[g], bB + 16384 + off);
        }
#pragma unroll
        for (int mt = 0; mt < 2; mt++)
#pragma unroll
            for (int ntl = 0; ntl < 8; ntl++) {
                float* a_ = acc[mt][ntl];
                const uint32_t* bh = &bhi[ntl >> 1][(ntl & 1) * 2];
                const uint32_t* bl = &blo[ntl >> 1][(ntl & 1) * 2];
                mma16816(a_, ahi[mt], bh);
                mma16816(a_, ahi[mt], bl);
                mma16816(a_, alo[mt], bh);
            }
    }
}

__global__ __launch_bounds__(256, 1)
void hmma_gemm_o(const bf16* __restrict__ Ahi, const bf16* __restrict__ Alo,
                 const bf16* __restrict__ Bhi, const bf16* __restrict__ Blo,
                 float* __restrict__ Cf, int M)
{
    extern __shared__ char smem[];
    const uint32_t sb = smem_u32(smem);
    const int tid = threadIdx.x;
    const int wid = tid >> 5, lane = tid & 31;
    const int row0 = blockIdx.x * 128;

    const int lr = tid >> 1;
    const int arow = (row0 + lr < M) ? (row0 + lr) : (M - 1);

    float acc[2][8][4];
#pragma unroll
    for (int i = 0; i < 2; i++)
#pragma unroll
        for (int j = 0; j < 8; j++)
#pragma unroll
            for (int q = 0; q < 4; q++) acc[i][j][q] = 0.f;

    for (int kc = 0; kc < 2; kc++) {
        const int k0 = kc * 64;
#pragma unroll
        for (int i = 0; i < 4; i++) {
            const int u = (tid & 1) * 4 + i;
            const uint32_t d = lr * 128 + (uint32_t)(((u ^ (lr & 7))) << 4);
            cp16(sb + d,         (const char*)(Ahi + (size_t)arow * 128 + k0) + u * 16);
            cp16(sb + 16384 + d, (const char*)(Alo + (size_t)arow * 128 + k0) + u * 16);
        }
        for (int i = tid; i < 128 * 8; i += 256) {
            const int r = i >> 3, u = i & 7;
            const uint32_t d = r * 128 + (uint32_t)(((u ^ (r & 7))) << 4);
            cp16(sb + 32768 + d, (const char*)(Bhi + (size_t)r * 128 + k0) + u * 16);
            cp16(sb + 49152 + d, (const char*)(Blo + (size_t)r * 128 + k0) + u * 16);
        }
        CP_COMMIT();
        CP_WAIT(0);
        __syncthreads();
        ldsm_mma8(acc, sb, sb + 32768, tid);
        __syncthreads();
    }

    const int wm = wid >> 1, wn = wid & 1;
#pragma unroll
    for (int mt = 0; mt < 2; mt++) {
        const int r = row0 + wm * 32 + mt * 16 + (lane >> 2);
#pragma unroll
        for (int nt = 0; nt < 8; nt++) {
            const int c = wn * 64 + nt * 8 + (lane & 3) * 2;
#pragma unroll
            for (int half = 0; half < 2; half++) {
                const int rr = r + half * 8;
                if (rr >= M) continue;
                *(float2*)(Cf + (size_t)rr * 128 + c) =
                    make_float2(acc[mt][nt][half * 2], acc[mt][nt][half * 2 + 1]);
            }
        }
    }
}

// ---------------- host launch ----------------
extern "C" void kernel_launch(void* const* d_in, const int* in_sizes, int n_in,
                              void* d_out, int out_size)
{
    const float* h_V   = (const float*)d_in[0];
    const float* h_E   = (const float*)d_in[1];
    const int*   eidx  = (const int*)  d_in[2];
    const float* hvv   = (const float*)d_in[3];
    const float* frame = (const float*)d_in[4];
    const float* W_vec = (const float*)d_in[5];
    const float* W_red = (const float*)d_in[6];
    const float* Wb1   = (const float*)d_in[7];
    const float* bb1   = (const float*)d_in[8];
    const float* Wb2   = (const float*)d_in[9];
    const float* bb2   = (const float*)d_in[10];
    const float* Wb3   = (const float*)d_in[11];
    const float* bb3   = (const float*)d_in[12];
    const float* Wv1   = (const float*)d_in[13];
    const float* bv1   = (const float*)d_in[14];
    const float* Wv2   = (const float*)d_in[15];
    const float* bv2   = (const float*)d_in[16];
    const float* Wv3   = (const float*)d_in[17];
    const float* bv3   = (const float*)d_in[18];
    const float* W_O   = (const float*)d_in[19];
    const float* bn_g  = (const float*)d_in[20];
    const float* bn_b  = (const float*)d_in[21];

    int E = in_sizes[2] / 2;
    int N = in_sizes[0] / 128;
    float* out = (float*)d_out;

    float *vff, *hVW, *gsum, *hagg, *bnst;
    bf16 *hgh, *hgl, *wh, *wl;
    double* bnacc;
    cudaGetSymbolAddress((void**)&vff,   g_vff);
    cudaGetSymbolAddress((void**)&hVW,   g_hVW);
    cudaGetSymbolAddress((void**)&hgh,   g_hgh);
    cudaGetSymbolAddress((void**)&hgl,   g_hgl);
    cudaGetSymbolAddress((void**)&wh,    g_wh);
    cudaGetSymbolAddress((void**)&wl,    g_wl);
    cudaGetSymbolAddress((void**)&gsum,  g_sum);
    cudaGetSymbolAddress((void**)&hagg,  g_hagg);
    cudaGetSymbolAddress((void**)&bnacc, g_bnacc);
    cudaGetSymbolAddress((void**)&bnst,  g_bnst);

    const int SMEM_O = 65536;
    const int SMEM_G = 256 * 65 * 4;   // 66560
    cudaFuncSetAttribute(mega_kernel, cudaFuncAttributeMaxDynamicSharedMemorySize, SMEM_MEGA);
    cudaFuncSetAttribute(hmma_gemm_o, cudaFuncAttributeMaxDynamicSharedMemorySize, SMEM_O);
    cudaFuncSetAttribute(geom_kernel, cudaFuncAttributeMaxDynamicSharedMemorySize, SMEM_G);

    int Mt = (E + 127) / 128;
    int Mo = (N + 127) / 128;

    init_kernel<<<(N * 128 + 255) / 256, 256>>>(gsum, hagg, bnacc, N);
    geom_kernel<<<(E + 255) / 256, 256, SMEM_G>>>(eidx, hvv, frame, W_vec, vff, bnacc, E);
    bn_finalize<<<1, 32>>>(bnacc, bn_g, bn_b, bnst, E);

    wprep_all<<<(W_TOTAL + 255) / 256, 256>>>(W_red, Wb1, Wb2, Wv1, Wv2, Wv3, W_O, wh, wl);
    hvw_kernel<<<(N + 1) / 2, 256>>>(h_V, Wb1, hVW, N);

    mega_kernel<<<Mt, 512, SMEM_MEGA>>>(
        vff, h_E, bnst, hVW, eidx,
        wh + OW_RED, wl + OW_RED,
        wh + OW_B1, wl + OW_B1, bb1,
        wh + OW_B2, wl + OW_B2, bb2,
        Wb3, bb3,
        wh + OW_V1, wl + OW_V1, bv1,
        wh + OW_V2, wl + OW_V2, bv2,
        wh + OW_V3, wl + OW_V3, bv3,
        gsum, hagg, E);

    // hagg normalized by segment sums -> planes, then out = hagg @ W_O
    c2planes_norm<<<(N * 128 + 255) / 256, 256>>>(hagg, gsum, hgh, hgl, N);
    hmma_gemm_o<<<Mo, 256, SMEM_O>>>(hgh, hgl, wh + OW_O, wl + OW_O, out, N);
}

// round 13
// speedup vs baseline: 1.1512x; 1.0162x over previous
#include <cuda_runtime.h>
#include <cuda_bf16.h>
#include <math.h>
#include <stdint.h>

#define E_CONST 320000
#define N_CONST 10000
typedef __nv_bfloat16 bf16;

// ---------------- scratch (no allocations allowed) ----------------
static __device__ float    g_vff [(size_t)E_CONST * 64];   // fp32 [sincos48|dist16]
static __device__ float    g_hVW [N_CONST * 128];          // hV @ Wb1_top (fp32, per node)
static __device__ bf16     g_hgh [N_CONST * 128];
static __device__ bf16     g_hgl [N_CONST * 128];
static __device__ bf16     g_wh  [262144];                 // all weights, [n][k]
static __device__ bf16     g_wl  [262144];
static __device__ float    g_sum [N_CONST * 4];
static __device__ float    g_hagg[N_CONST * 128];
static __device__ double   g_bnacc[32];
static __device__ float    g_bnst[32];

// weight plane offsets (elements)
#define OW_RED 0        // 256 x 320
#define OW_B1  81920    // 128 x 384
#define OW_B2  131072   // 128 x 128
#define OW_V1  147456   // 128 x 256
#define OW_V2  180224   // 128 x 128
#define OW_V3  196608   // 128 x 128
#define OW_O   212992   // 128 x 128
#define W_TOTAL 229376

// mega smem tail (beyond the 224KB working set)
#define ATT_OFF 229376
#define CEN_OFF 231424
#define SMEM_MEGA 231936

// ---------------- helpers ----------------
__device__ __forceinline__ uint32_t smem_u32(const void* p) {
    uint32_t a;
    asm("{ .reg .u64 t; cvta.to.shared.u64 t, %1; cvt.u32.u64 %0, t; }" : "=r"(a) : "l"(p));
    return a;
}
__device__ __forceinline__ void cp16(uint32_t dst, const void* src) {
    asm volatile("cp.async.cg.shared.global [%0], [%1], 16;"
        :: "r"(dst), "l"(__cvta_generic_to_global(src)) : "memory");
}
#define CP_COMMIT() asm volatile("cp.async.commit_group;" ::: "memory")
#define CP_WAIT(n)  asm volatile("cp.async.wait_group %0;" :: "n"(n) : "memory")

__device__ __forceinline__ void ldsm4(uint32_t* r, uint32_t addr) {
    asm volatile("ldmatrix.sync.aligned.m8n8.x4.shared.b16 {%0,%1,%2,%3}, [%4];"
        : "=r"(r[0]), "=r"(r[1]), "=r"(r[2]), "=r"(r[3]) : "r"(addr));
}
__device__ __forceinline__ void mma16816(float* d, const uint32_t* a, const uint32_t* b) {
    asm volatile(
        "mma.sync.aligned.m16n8k16.row.col.f32.bf16.bf16.f32 "
        "{%0,%1,%2,%3}, {%4,%5,%6,%7}, {%8,%9}, {%0,%1,%2,%3};"
        : "+f"(d[0]), "+f"(d[1]), "+f"(d[2]), "+f"(d[3])
        : "r"(a[0]), "r"(a[1]), "r"(a[2]), "r"(a[3]), "r"(b[0]), "r"(b[1]));
}
__device__ __forceinline__ void red2(float* addr, float x, float y) {
    asm volatile("red.global.v2.f32.add [%0], {%1, %2};"
        :: "l"(__cvta_generic_to_global(addr)), "f"(x), "f"(y) : "memory");
}
__device__ __forceinline__ float gelu_f(float x) {
    return 0.5f * x * (1.f + erff(x * 0.70710678118654752f));
}

// ---------------- init ----------------
__global__ void init_kernel(float* gsum, float* hagg, double* bnacc, int N)
{
    int i = blockIdx.x * 256 + threadIdx.x;
    if (i < N * 128) hagg[i] = 0.f;
    if (i < N * 4) gsum[i] = 0.f;
    if (i < 32) bnacc[i] = 0.0;
}

// ---------------- geometry + BN stats (vectorized loads, smem-transposed stores) ----------------
__global__ __launch_bounds__(256)
void geom_kernel(const int* __restrict__ eidx, const float* __restrict__ hvv,
                 const float* __restrict__ frame, const float* __restrict__ Wvec,
                 float* __restrict__ vff, double* __restrict__ bnacc, int E)
{
    extern __shared__ float sbuf[];   // 256 * 65 floats (padded rows)
    __shared__ float Ws[512];
    __shared__ float bsum[16], bsq[16];
    int tid = threadIdx.x;
    for (int i = tid; i < 512; i += 256) Ws[i] = Wvec[i];
    if (tid < 16) { bsum[tid] = 0.f; bsq[tid] = 0.f; }
    __syncthreads();

    const int e0 = blockIdx.x * 256;
    const int e = e0 + tid;
    float dloc[16];
#pragma unroll
    for (int o = 0; o < 16; o++) dloc[o] = 0.f;

    if (e < E) {
        const int c = eidx[e];
        const int d = eidx[E + e];
        float F[9];
#pragma unroll
        for (int i = 0; i < 9; i++) F[i] = frame[e * 9 + i];

        float vdt[48], vsrc[48];
        {
            const float4* pd = (const float4*)(hvv + (size_t)d * 48);
            const float4* pc = (const float4*)(hvv + (size_t)c * 48);
#pragma unroll
            for (int i = 0; i < 12; i++) {
                ((float4*)vdt)[i]  = pd[i];
                ((float4*)vsrc)[i] = pc[i];
            }
        }
#pragma unroll
        for (int v = 0; v < 16; v++) {
            const float x = vdt[v * 3 + 0], y = vdt[v * 3 + 1], z = vdt[v * 3 + 2];
            vdt[v * 3 + 0] = F[0] * x + F[1] * y + F[2] * z;
            vdt[v * 3 + 1] = F[3] * x + F[4] * y + F[5] * z;
            vdt[v * 3 + 2] = F[6] * x + F[7] * y + F[8] * z;
        }

        float* row = sbuf + tid * 65;
#pragma unroll
        for (int o = 0; o < 16; o++) {
            float v0 = vdt[o * 3 + 0], v1 = vdt[o * 3 + 1], v2 = vdt[o * 3 + 2];
#pragma unroll
            for (int v = 0; v < 16; v++) {
                const float wa = Ws[o * 32 + v], wb = Ws[o * 32 + 16 + v];
                v0 += wa * vdt[v * 3 + 0] + wb * vsrc[v * 3 + 0];
                v1 += wa * vdt[v * 3 + 1] + wb * vsrc[v * 3 + 1];
                v2 += wa * vdt[v * 3 + 2] + wb * vsrc[v * 3 + 2];
            }
            const float dist = sqrtf(v0 * v0 + v1 * v1 + v2 * v2) + 1e-6f;
            const float inv = 1.f / dist;
            row[o * 3 + 0] = v0 * inv;
            row[o * 3 + 1] = v1 * inv;
            row[o * 3 + 2] = v2 * inv;
            row[48 + o] = dist;
            dloc[o] = dist;
        }
    }

#pragma unroll
    for (int o = 0; o < 16; o++) {
        float v = dloc[o], v2 = v * v;
#pragma unroll
        for (int off = 16; off; off >>= 1) {
            v  += __shfl_down_sync(0xffffffffu, v, off);
            v2 += __shfl_down_sync(0xffffffffu, v2, off);
        }
        if ((tid & 31) == 0) { atomicAdd(&bsum[o], v); atomicAdd(&bsq[o], v2); }
    }
    __syncthreads();
    if (tid < 16) {
        atomicAdd(&bnacc[tid], (double)bsum[tid]);
        atomicAdd(&bnacc[16 + tid], (double)bsq[tid]);
    }

    const int nblk = (E - e0 < 256) ? (E - e0) : 256;
    for (int j = tid; j < nblk * 16; j += 256) {
        const int r = j >> 4, q = (j & 15) * 4;
        const float* sr = sbuf + r * 65 + q;
        *(float4*)(vff + (size_t)(e0 + r) * 64 + q) =
            make_float4(sr[0], sr[1], sr[2], sr[3]);
    }
}

__global__ void bn_finalize(const double* __restrict__ acc, const float* __restrict__ g,
                            const float* __restrict__ b, float* __restrict__ st, int E)
{
    int i = threadIdx.x;
    if (i >= 16) return;
    double mean = acc[i] / (double)E;
    double var  = acc[16 + i] / (double)E - mean * mean;
    float s = (float)((double)g[i] / sqrt(var + 1e-5));
    st[i] = s;
    st[16 + i] = b[i] - (float)mean * s;
}

// ---------------- conversion passes ----------------
__global__ void wprep_all(const float* __restrict__ W0, const float* __restrict__ W1,
                          const float* __restrict__ W2, const float* __restrict__ W3,
                          const float* __restrict__ W4, const float* __restrict__ W5,
                          const float* __restrict__ W6,
                          bf16* __restrict__ hi, bf16* __restrict__ lo)
{
    int idx = blockIdx.x * 256 + threadIdx.x;
    if (idx >= W_TOTAL) return;
    const float* src; int K, NT, start;
    if      (idx < OW_B1)  { src = W0; K = 320; NT = 256; start = OW_RED; }
    else if (idx < OW_B2)  { src = W1; K = 384; NT = 128; start = OW_B1; }
    else if (idx < OW_V1)  { src = W2; K = 128; NT = 128; start = OW_B2; }
    else if (idx < OW_V2)  { src = W3; K = 256; NT = 128; start = OW_V1; }
    else if (idx < OW_V3)  { src = W4; K = 128; NT = 128; start = OW_V2; }
    else if (idx < OW_O)   { src = W5; K = 128; NT = 128; start = OW_V3; }
    else                   { src = W6; K = 128; NT = 128; start = OW_O; }
    int local = idx - start;
    int k = local / NT, n = local % NT;
    float v = src[local];
    bf16 h = __float2bfloat16_rn(v);
    hi[start + (size_t)n * K + k] = h;
    lo[start + (size_t)n * K + k] = __float2bfloat16_rn(v - __bfloat162float(h));
}

// hVW = hV @ Wb1[0:128,:]  (exact fp32, per-node)
__global__ __launch_bounds__(256)
void hvw_kernel(const float* __restrict__ hV, const float* __restrict__ Wb1,
                float* __restrict__ hVW, int N)
{
    __shared__ float xs[2][128];
    const int t = threadIdx.x;
    const int which = t >> 7, c = t & 127;
    const int node = blockIdx.x * 2 + which;
    if (node < N) xs[which][c] = hV[(size_t)node * 128 + c];
    __syncthreads();
    if (node >= N) return;
    float s = 0.f;
#pragma unroll 8
    for (int k = 0; k < 128; k++) s += xs[which][k] * Wb1[k * 128 + c];
    hVW[(size_t)node * 128 + c] = s;
}

// hagg -> planes with softmax normalization folded in
__global__ void c2planes_norm(const float* __restrict__ x, const float* __restrict__ gsum,
                              bf16* __restrict__ hi, bf16* __restrict__ lo, int N)
{
    int i = blockIdx.x * 256 + threadIdx.x;
    if (i >= N * 128) return;
    int node = i >> 7, col = i & 127;
    float s = gsum[node * 4 + (col >> 5)];
    float v = x[i] / (s > 0.f ? s : 1.f);
    bf16 h = __float2bfloat16_rn(v);
    hi[i] = h;
    lo[i] = __float2bfloat16_rn(v - __bfloat162float(h));
}

// ================= GEMM building blocks (512 threads, 16 warps = 4m x 4n) =================
template<int NT>
__device__ __forceinline__ void mma_half512(
    float (&acc)[2][NT][4], uint32_t aHi, uint32_t aLo,
    uint32_t bHi, uint32_t bLo, int ks0, int tid)
{
    const int wid = tid >> 5, lane = tid & 31;
    const int wm = wid >> 2, wn = wid & 3;
    const int a_row = wm * 32 + (lane & 7) + ((lane & 8) ? 8 : 0);
    const int a_ub  = (lane & 16) ? 1 : 0;
    const int b_row0 = wn * (NT * 8) + (lane & 7) + ((lane & 16) ? 8 : 0);
    const int b_ub  = (lane & 8) ? 1 : 0;
#pragma unroll
    for (int kss = 0; kss < 2; kss++) {
        const int ks = ks0 + kss;
        uint32_t ahi[2][4], alo[2][4];
#pragma unroll
        for (int mt = 0; mt < 2; mt++) {
            const int r = a_row + mt * 16;
            const int u = ks * 2 + a_ub;
            const uint32_t off = r * 128 + (uint32_t)(((u ^ (r & 7))) << 4);
            ldsm4(ahi[mt], aHi + off);
            ldsm4(alo[mt], aLo + off);
        }
        uint32_t bhi[NT / 2][4], blo[NT / 2][4];
#pragma unroll
        for (int g = 0; g < NT / 2; g++) {
            const int n = b_row0 + g * 16;
            const int u = ks * 2 + b_ub;
            const uint32_t off = n * 128 + (uint32_t)(((u ^ (n & 7))) << 4);
            ldsm4(bhi[g], bHi + off);
            ldsm4(blo[g], bLo + off);
        }
#pragma unroll
        for (int mt = 0; mt < 2; mt++)
#pragma unroll
            for (int ntl = 0; ntl < NT; ntl++) {
                float* a_ = acc[mt][ntl];
                const uint32_t* bh = &bhi[ntl >> 1][(ntl & 1) * 2];
                const uint32_t* bl = &blo[ntl >> 1][(ntl & 1) * 2];
                mma16816(a_, ahi[mt], bh);
                mma16816(a_, ahi[mt], bl);
                mma16816(a_, alo[mt], bh);
            }
    }
}

// full 64-K chunk (2 halves, no intermediate syncs)
template<int NT>
__device__ __forceinline__ void mma_chunk(
    float (&acc)[2][NT][4], uint32_t aHi, uint32_t aLo,
    uint32_t bHi, uint32_t bLo, int tid)
{
    mma_half512<NT>(acc, aHi, aLo, bHi, bLo, 0, tid);
    mma_half512<NT>(acc, aHi, aLo, bHi, bLo, 2, tid);
}

__device__ __forceinline__ void stage_half(uint32_t dstHi, uint32_t dstLo,
                                           const bf16* __restrict__ Whi,
                                           const bf16* __restrict__ Wlo,
                                           int K, int k0, int half, int rows, int tid)
{
    for (int i = tid; i < rows * 4; i += 512) {
        const int r = i >> 2, u = (i & 3) + half * 4;
        const uint32_t d = r * 128 + (uint32_t)(((u ^ (r & 7))) << 4);
        cp16(dstHi + d, (const char*)(Whi + (size_t)r * K + k0) + u * 16);
        cp16(dstLo + d, (const char*)(Wlo + (size_t)r * K + k0) + u * 16);
    }
    CP_COMMIT();
}

// stage 1 full 64-K chunk (128 rows): hi -> dst, lo -> dst+16384
__device__ __forceinline__ void stage_chunk1(uint32_t dst,
                                             const bf16* __restrict__ Whi,
                                             const bf16* __restrict__ Wlo,
                                             int K, int k0, int tid)
{
    for (int i = tid; i < 1024; i += 512) {
        const int r = i >> 3, u = i & 7;
        const uint32_t d = r * 128 + (uint32_t)(((u ^ (r & 7))) << 4);
        cp16(dst + d,         (const char*)(Whi + (size_t)r * K + k0) + u * 16);
        cp16(dst + 16384 + d, (const char*)(Wlo + (size_t)r * K + k0) + u * 16);
    }
    CP_COMMIT();
}

// stage 2 full 64-K chunks (128 rows): hi ch -> dst+ch*16K, lo ch -> dst+32K+ch*16K
__device__ __forceinline__ void stage_chunks2(uint32_t dst,
                                              const bf16* __restrict__ Whi,
                                              const bf16* __restrict__ Wlo,
                                              int K, int k0, int tid)
{
    for (int i = tid; i < 2048; i += 512) {
        const int ch = i >> 10, rem = i & 1023;
        const int r = rem >> 3, u = rem & 7;
        const uint32_t d = ch * 16384 + r * 128 + (uint32_t)(((u ^ (r & 7))) << 4);
        cp16(dst + d,         (const char*)(Whi + (size_t)r * K + k0 + ch * 64) + u * 16);
        cp16(dst + 32768 + d, (const char*)(Wlo + (size_t)r * K + k0 + ch * 64) + u * 16);
    }
    CP_COMMIT();
}

template<int NT, int ACT>
__device__ __forceinline__ void store_planes512(const float (&acc)[2][NT][4],
                                                char* smemp, uint32_t baseHi, uint32_t baseLo,
                                                const float* __restrict__ bias, int tid)
{
    const int wid = tid >> 5, lane = tid & 31;
    const int wm = wid >> 2, wn = wid & 3;
#pragma unroll
    for (int mt = 0; mt < 2; mt++)
#pragma unroll
        for (int nt = 0; nt < NT; nt++) {
            const int c = wn * (NT * 8) + nt * 8 + (lane & 3) * 2;
            const int kc = c >> 6, kk = c & 63, u = kk >> 3;
            const float b0 = bias ? bias[c] : 0.f;
            const float b1 = bias ? bias[c + 1] : 0.f;
#pragma unroll
            for (int half = 0; half < 2; half++) {
                const int r = wm * 32 + mt * 16 + (lane >> 2) + half * 8;
                float e0 = acc[mt][nt][half * 2] + b0;
                float e1 = acc[mt][nt][half * 2 + 1] + b1;
                if (ACT == 1) { e0 = fmaxf(e0, 0.f); e1 = fmaxf(e1, 0.f); }
                if (ACT == 2) { e0 = gelu_f(e0); e1 = gelu_f(e1); }
                bf16 h0 = __float2bfloat16_rn(e0);
                bf16 h1 = __float2bfloat16_rn(e1);
                __nv_bfloat162 hp; hp.x = h0; hp.y = h1;
                __nv_bfloat162 lp;
                lp.x = __float2bfloat16_rn(e0 - __bfloat162float(h0));
                lp.y = __float2bfloat16_rn(e1 - __bfloat162float(h1));
                const uint32_t ad = kc * 16384 + r * 128 +
                                    (uint32_t)(((u ^ (r & 7))) << 4) + (kk & 7) * 2;
                *(__nv_bfloat162*)(smemp + baseHi + ad) = hp;
                *(__nv_bfloat162*)(smemp + baseLo + ad) = lp;
            }
        }
}

// ---------------- MEGA kernel (512 threads) ----------------
// smem: [0,64K) heHi, [64K,128K) heLo, [128K,192K) xv, [192K,224K) stg,
//       [224K,226K) att (e values), [226K,226.5K) cen
__global__ __launch_bounds__(512, 1)
void mega_kernel(const float* __restrict__ Vff, const float* __restrict__ HE,
                 const float* __restrict__ bn_st,
                 const float* __restrict__ hVW,
                 const int* __restrict__ eidx,
                 const bf16* __restrict__ wredh, const bf16* __restrict__ wredl,
                 const bf16* __restrict__ wb1h, const bf16* __restrict__ wb1l,
                 const float* __restrict__ bb1,
                 const bf16* __restrict__ wb2h, const bf16* __restrict__ wb2l,
                 const float* __restrict__ bb2,
                 const float* __restrict__ Wb3, const float* __restrict__ bb3,
                 const bf16* __restrict__ wv1h, const bf16* __restrict__ wv1l,
                 const float* __restrict__ bv1,
                 const bf16* __restrict__ wv2h, const bf16* __restrict__ wv2l,
                 const float* __restrict__ bv2,
                 const bf16* __restrict__ wv3h, const bf16* __restrict__ wv3l,
                 const float* __restrict__ bv3,
                 float* __restrict__ gsum, float* __restrict__ hagg, int M)
{
    extern __shared__ char smem[];
    const uint32_t sb = smem_u32(smem);
    const uint32_t heHi = sb;
    const uint32_t heLo = sb + 65536;
    const uint32_t xv   = sb + 131072;
    const uint32_t stg  = sb + 196608;
    const int tid = threadIdx.x;
    const int wid = tid >> 5, lane = tid & 31;
    const int row0 = blockIdx.x * 128;

    const int lr = tid >> 2;              // 4 threads per row
    const int arow = (row0 + lr < M) ? (row0 + lr) : (M - 1);
    const int cu0 = (tid & 3) * 4;        // fp32 16B-unit base for A convert

    // center table for this tile
    {
        int* cens = (int*)(smem + CEN_OFF);
        if (tid < 128) {
            int er = row0 + tid;
            cens[tid] = eidx[er < M ? er : M - 1];
        }
    }

    // ================= P0: hE = [vff_bn | h_E] @ W_red (K=320, N=256) =================
    {
        float acc0[2][8][4];
#pragma unroll
        for (int i = 0; i < 2; i++)
#pragma unroll
            for (int j = 0; j < 8; j++)
#pragma unroll
                for (int q = 0; q < 4; q++) acc0[i][j][q] = 0.f;

        float4 areg[4];
        {
            const float4* pa = (const float4*)(Vff + (size_t)arow * 64);
#pragma unroll
            for (int jj = 0; jj < 4; jj++) areg[jj] = pa[cu0 + jj];
        }
        stage_half(xv + 32768, stg, wredh, wredl, 320, 0, 0, 256, tid);

        for (int kc = 0; kc < 5; kc++) {
            {
                float4 f[4];
#pragma unroll
                for (int jj = 0; jj < 4; jj++) f[jj] = areg[jj];
                if (kc == 0 && cu0 >= 12) {
#pragma unroll
                    for (int jj = 0; jj < 4; jj++) {
                        const int u = cu0 + jj;
                        if (u >= 12) {
                            const int col = u * 4;
                            f[jj].x = fmaf(f[jj].x, bn_st[col - 48], bn_st[col - 32]);
                            f[jj].y = fmaf(f[jj].y, bn_st[col - 47], bn_st[col - 31]);
                            f[jj].z = fmaf(f[jj].z, bn_st[col - 46], bn_st[col - 30]);
                            f[jj].w = fmaf(f[jj].w, bn_st[col - 45], bn_st[col - 29]);
                        }
                    }
                }
#pragma unroll
                for (int jj = 0; jj < 2; jj++) {
                    float v[8] = {f[2 * jj].x, f[2 * jj].y, f[2 * jj].z, f[2 * jj].w,
                                  f[2 * jj + 1].x, f[2 * jj + 1].y, f[2 * jj + 1].z, f[2 * jj + 1].w};
                    uint32_t ph[4], pl[4];
#pragma unroll
                    for (int j = 0; j < 4; j++) {
                        float a = v[2 * j], b = v[2 * j + 1];
                        bf16 ha = __float2bfloat16_rn(a);
                        bf16 hb = __float2bfloat16_rn(b);
                        __nv_bfloat162 hp; hp.x = ha; hp.y = hb;
                        __nv_bfloat162 lp;
                        lp.x = __float2bfloat16_rn(a - __bfloat162float(ha));
                        lp.y = __float2bfloat16_rn(b - __bfloat162float(hb));
                        ph[j] = reinterpret_cast<uint32_t&>(hp);
                        pl[j] = reinterpret_cast<uint32_t&>(lp);
                    }
                    const int un = (cu0 >> 1) + jj;
                    const uint32_t ad = lr * 128 + (uint32_t)(((un ^ (lr & 7))) << 4);
                    *(uint4*)(smem + 131072 + ad)         = make_uint4(ph[0], ph[1], ph[2], ph[3]);
                    *(uint4*)(smem + 131072 + 16384 + ad) = make_uint4(pl[0], pl[1], pl[2], pl[3]);
                }
            }
            if (kc < 4) {
                const float4* pa = (const float4*)(HE + (size_t)arow * 256 + kc * 64);
#pragma unroll
                for (int jj = 0; jj < 4; jj++) areg[jj] = pa[cu0 + jj];
            }
#pragma unroll
            for (int hh = 0; hh < 2; hh++) {
                const int h = kc * 2 + hh;
                if (h + 1 < 10) {
                    stage_half(xv + 32768, stg, wredh, wredl, 320,
                               ((h + 1) >> 1) * 64, (h + 1) & 1, 256, tid);
                    CP_WAIT(1);
                } else {
                    CP_WAIT(0);
                }
                __syncthreads();
                mma_half512<8>(acc0, xv, xv + 16384, xv + 32768, stg, hh * 2, tid);
                __syncthreads();
            }
        }

        // prestage Wb1 chunks 0,1 -> xv (G1), chunk2 -> stg (G2), overlapped with epilogue
        stage_chunks2(xv, wb1h, wb1l, 384, 128, tid);   // G1
        stage_chunk1(stg, wb1h, wb1l, 384, 256, tid);   // G2
        store_planes512<8, 0>(acc0, smem, 0, 65536, nullptr, tid);
    }
    __syncthreads();

    // ================= P1: x1 = relu(hVW[center] + hE @ Wb1_bot + bb1), K=256 =================
    float acc1[2][4][4];
#pragma unroll
    for (int i = 0; i < 2; i++)
#pragma unroll
        for (int j = 0; j < 4; j++)
#pragma unroll
            for (int q = 0; q < 4; q++) acc1[i][j][q] = 0.f;
    {
        CP_WAIT(1);                        // G1 done (G2 pending)
        __syncthreads();
        mma_chunk<4>(acc1, heHi,         heLo,         xv,         xv + 32768, tid);
        mma_chunk<4>(acc1, heHi + 16384, heLo + 16384, xv + 16384, xv + 49152, tid);
        __syncthreads();
        stage_chunk1(xv, wb1h, wb1l, 384, 320, tid);   // G3: chunk3 -> xv (hi +0, lo +16384)
        CP_WAIT(1);                        // G2 done (G3 pending)
        __syncthreads();
        mma_chunk<4>(acc1, heHi + 32768, heLo + 32768, stg, stg + 16384, tid);
        CP_WAIT(0);                        // G3 done
        __syncthreads();
        mma_chunk<4>(acc1, heHi + 49152, heLo + 49152, xv, xv + 16384, tid);
        __syncthreads();

        // prestage Wb2 chunk0 -> stg (G4), overlapped with epilogue
        stage_chunk1(stg, wb2h, wb2l, 128, 0, tid);    // G4

        // epilogue: fused per-fragment global hVW read + bias + relu -> x1 planes in xv
        const int* cens = (const int*)(smem + CEN_OFF);
        const int wm = wid >> 2, wn = wid & 3;
#pragma unroll
        for (int mt = 0; mt < 2; mt++)
#pragma unroll
            for (int nt = 0; nt < 4; nt++) {
                const int c = wn * 32 + nt * 8 + (lane & 3) * 2;
                const int kc = c >> 6, kk = c & 63, u = kk >> 3;
                const float b0 = bb1[c], b1 = bb1[c + 1];
#pragma unroll
                for (int half = 0; half < 2; half++) {
                    const int r = wm * 32 + mt * 16 + (lane >> 2) + half * 8;
                    const float2 hv = *(const float2*)(hVW + (size_t)cens[r] * 128 + c);
                    float e0 = fmaxf(acc1[mt][nt][half * 2] + b0 + hv.x, 0.f);
                    float e1 = fmaxf(acc1[mt][nt][half * 2 + 1] + b1 + hv.y, 0.f);
                    bf16 h0 = __float2bfloat16_rn(e0);
                    bf16 h1 = __float2bfloat16_rn(e1);
                    __nv_bfloat162 hp; hp.x = h0; hp.y = h1;
                    __nv_bfloat162 lp;
                    lp.x = __float2bfloat16_rn(e0 - __bfloat162float(h0));
                    lp.y = __float2bfloat16_rn(e1 - __bfloat162float(h1));
                    const uint32_t ad = kc * 16384 + r * 128 +
                                        (uint32_t)(((u ^ (r & 7))) << 4) + (kk & 7) * 2;
                    *(__nv_bfloat162*)(smem + 131072 + ad) = hp;
                    *(__nv_bfloat162*)(smem + 131072 + 32768 + ad) = lp;
                }
            }
    }
    CP_WAIT(0);                            // G4 done (hidden behind epilogue)
    __syncthreads();

    // ================= P2: x2 = relu(x1 @ Wb2 + bb2) =================
    float acc2[2][4][4];
#pragma unroll
    for (int i = 0; i < 2; i++)
#pragma unroll
        for (int j = 0; j < 4; j++)
#pragma unroll
            for (int q = 0; q < 4; q++) acc2[i][j][q] = 0.f;
    mma_chunk<4>(acc2, xv, xv + 32768, stg, stg + 16384, tid);
    __syncthreads();
    stage_chunk1(stg, wb2h, wb2l, 128, 64, tid);       // G5
    CP_WAIT(0);
    __syncthreads();
    mma_chunk<4>(acc2, xv + 16384, xv + 49152, stg, stg + 16384, tid);
    __syncthreads();
    stage_chunk1(stg, wv1h, wv1l, 256, 0, tid);        // G6: Wv1 c0 (hidden behind x2 store + P3)

    // x2 fp32 -> xv (x1 dead)
    {
        const int wm = wid >> 2, wn = wid & 3;
#pragma unroll
        for (int mt = 0; mt < 2; mt++)
#pragma unroll
            for (int nt = 0; nt < 4; nt++) {
                const int c = wn * 32 + nt * 8 + (lane & 3) * 2;
                const float b0 = bb2[c], b1 = bb2[c + 1];
#pragma unroll
                for (int half = 0; half < 2; half++) {
                    const int r = wm * 32 + mt * 16 + (lane >> 2) + half * 8;
                    float e0 = fmaxf(acc2[mt][nt][half * 2] + b0, 0.f);
                    float e1 = fmaxf(acc2[mt][nt][half * 2 + 1] + b1, 0.f);
                    *(float2*)(smem + 131072 + ((size_t)r * 128 + c) * 4) = make_float2(e0, e1);
                }
            }
    }
    __syncthreads();

    // ================= P3: e = exp(logits), segment sum (Wb3 read direct from L2) =================
    {
        const float* x2s = (const float*)(smem + 131072);
        float* atts = (float*)(smem + ATT_OFF);
        const int* cens = (const int*)(smem + CEN_OFF);
        for (int rr = wid * 8; rr < wid * 8 + 8; rr++) {
            const int e = row0 + rr;
            if (e >= M) break;
            float p0 = 0.f, p1 = 0.f, p2 = 0.f, p3 = 0.f;
#pragma unroll
            for (int j = 0; j < 4; j++) {
                const int c = lane + j * 32;
                const float x = x2s[rr * 128 + c];
                const float4 w4 = *(const float4*)(Wb3 + c * 8);
                p0 += x * w4.x;
                p1 += x * w4.y;
                p2 += x * w4.z;
                p3 += x * w4.w;
            }
#pragma unroll
            for (int off = 16; off; off >>= 1) {
                p0 += __shfl_xor_sync(0xffffffffu, p0, off);
                p1 += __shfl_xor_sync(0xffffffffu, p1, off);
                p2 += __shfl_xor_sync(0xffffffffu, p2, off);
                p3 += __shfl_xor_sync(0xffffffffu, p3, off);
            }
            if (lane < 4) {
                const float p = (lane == 0) ? p0 : (lane == 1) ? p1 : (lane == 2) ? p2 : p3;
                const float l = (p + bb3[lane]) * 0.17677669529663687f;
                const float ex = expf(l);
                atts[rr * 4 + lane] = ex;
                atomicAdd(&gsum[cens[rr] * 4 + lane], ex);
            }
        }
    }
    __syncthreads();

    // ================= P4: v1 = gelu(hE @ Wv1 + bv1), ping-pong xv/stg staging =================
    float acc3[2][4][4];
#pragma unroll
    for (int i = 0; i < 2; i++)
#pragma unroll
        for (int j = 0; j < 4; j++)
#pragma unroll
            for (int q = 0; q < 4; q++) acc3[i][j][q] = 0.f;
    stage_chunk1(xv, wv1h, wv1l, 256, 64, tid);        // G7: c1 -> xv
    CP_WAIT(1);                                        // G6 done (G7 pending)
    __syncthreads();
    mma_chunk<4>(acc3, heHi, heLo, stg, stg + 16384, tid);             // c0
    __syncthreads();
    stage_chunk1(stg, wv1h, wv1l, 256, 128, tid);      // G8: c2 -> stg
    CP_WAIT(1);                                        // G7 done
    __syncthreads();
    mma_chunk<4>(acc3, heHi + 16384, heLo + 16384, xv, xv + 16384, tid); // c1
    __syncthreads();
    stage_chunk1(xv, wv1h, wv1l, 256, 192, tid);       // G9: c3 -> xv
    CP_WAIT(1);                                        // G8 done
    __syncthreads();
    mma_chunk<4>(acc3, heHi + 32768, heLo + 32768, stg, stg + 16384, tid); // c2
    CP_WAIT(0);                                        // G9 done
    __syncthreads();
    mma_chunk<4>(acc3, heHi + 49152, heLo + 49152, xv, xv + 16384, tid);   // c3
    __syncthreads();
    // overlap: stage Wv2 -> heLo (hE lo dead) while storing v1 planes -> xv
    stage_chunks2(heLo, wv2h, wv2l, 128, 0, tid);      // G10
    store_planes512<4, 2>(acc3, smem, 131072, 131072 + 32768, bv1, tid);  // v1 -> xv
    CP_WAIT(0);
    __syncthreads();

    // ================= P5: v2 = gelu(v1 @ Wv2 + bv2) =================
    float acc4[2][4][4];
#pragma unroll
    for (int i = 0; i < 2; i++)
#pragma unroll
        for (int j = 0; j < 4; j++)
#pragma unroll
            for (int q = 0; q < 4; q++) acc4[i][j][q] = 0.f;
#pragma unroll
    for (int ch = 0; ch < 2; ch++)
        mma_chunk<4>(acc4, xv + ch * 16384, xv + 32768 + ch * 16384,
                     heLo + ch * 16384, heLo + 32768 + ch * 16384, tid);
    __syncthreads();
    // overlap: stage Wv3 -> xv (v1 dead) while storing v2 planes -> heHi (hE hi dead)
    stage_chunks2(xv, wv3h, wv3l, 128, 0, tid);        // G11
    store_planes512<4, 2>(acc4, smem, 0, 32768, bv2, tid);
    CP_WAIT(0);
    __syncthreads();

    // ================= P6: V = v2 @ Wv3 + bv3; hagg[center] += e * V =================
    float acc5[2][4][4];
#pragma unroll
    for (int i = 0; i < 2; i++)
#pragma unroll
        for (int j = 0; j < 4; j++)
#pragma unroll
            for (int q = 0; q < 4; q++) acc5[i][j][q] = 0.f;
#pragma unroll
    for (int ch = 0; ch < 2; ch++)
        mma_chunk<4>(acc5, heHi + ch * 16384, heHi + 32768 + ch * 16384,
                     xv + ch * 16384, xv + 32768 + ch * 16384, tid);
    {
        const float* atts = (const float*)(smem + ATT_OFF);
        const int* cens = (const int*)(smem + CEN_OFF);
        const int wm = wid >> 2, wn = wid & 3;
#pragma unroll
        for (int mt = 0; mt < 2; mt++) {
#pragma unroll
            for (int nt = 0; nt < 4; nt++) {
                const int c = wn * 32 + nt * 8 + (lane & 3) * 2;
                const int h = c >> 5;
                const float b0 = bv3[c], b1 = bv3[c + 1];
#pragma unroll
                for (int half = 0; half < 2; half++) {
                    const int rl = wm * 32 + mt * 16 + (lane >> 2) + half * 8;
                    if (row0 + rl < M) {
                        const float a = atts[rl * 4 + h];
                        float* dst = hagg + (size_t)cens[rl] * 128 + c;
                        red2(dst, (acc5[mt][nt][half * 2] + b0) * a,
                                  (acc5[mt][nt][half * 2 + 1] + b1) * a);
                    }
                }
            }
        }
    }
}

// ---------------- standalone GEMM (W_O), 256 threads ----------------
__device__ __forceinline__ void ldsm_mma8(float (&acc)[2][8][4], uint32_t aB, uint32_t bB, int tid)
{
    const int wid = tid >> 5, lane = tid & 31;
    const int wm = wid >> 1, wn = wid & 1;
    const int a_row = wm * 32 + (lane & 7) + ((lane & 8) ? 8 : 0);
    const int a_ub  = (lane & 16) ? 1 : 0;
    const int b_row0 = wn * 64 + (lane & 7) + ((lane & 16) ? 8 : 0);
    const int b_ub  = (lane & 8) ? 1 : 0;
#pragma unroll
    for (int ks = 0; ks < 4; ks++) {
        uint32_t ahi[2][4], alo[2][4];
#pragma unroll
        for (int mt = 0; mt < 2; mt++) {
            const int r = a_row + mt * 16;
            const int u = ks * 2 + a_ub;
            const uint32_t off = r * 128 + (uint32_t)(((u ^ (r & 7))) << 4);
            ldsm4(ahi[mt], aB + off);
            ldsm4(alo[mt], aB + 16384 + off);
        }
        uint32_t bhi[4][4], blo[4][4];
#pragma unroll
        for (int g = 0; g < 4; g++) {
            const int n = b_row0 + g * 16;
            const int u = ks * 2 + b_ub;
            const uint32_t off = n * 128 + (uint32_t)(((u ^ (n & 7))) << 4);
            ldsm4(bhi[g], bB + off);
            ldsm4(blo[g], bB + 16384 + off);
        }
#pragma unroll
        for (int mt = 0; mt < 2; mt++)
#pragma unroll
            for (int ntl = 0; ntl < 8; ntl++) {
                float* a_ = acc[mt][ntl];
                const uint32_t* bh = &bhi[ntl >> 1][(ntl & 1) * 2];
                const uint32_t* bl = &blo[ntl >> 1][(ntl & 1) * 2];
                mma16816(a_, ahi[mt], bh);
                mma16816(a_, ahi[mt], bl);
                mma16816(a_, alo[mt], bh);
            }
    }
}

__global__ __launch_bounds__(256, 1)
void hmma_gemm_o(const bf16* __restrict__ Ahi, const bf16* __restrict__ Alo,
                 const bf16* __restrict__ Bhi, const bf16* __restrict__ Blo,
                 float* __restrict__ Cf, int M)
{
    extern __shared__ char smem[];
    const uint32_t sb = smem_u32(smem);
    const int tid = threadIdx.x;
    const int wid = tid >> 5, lane = tid & 31;
    const int row0 = blockIdx.x * 128;

    const int lr = tid >> 1;
    const int arow = (row0 + lr < M) ? (row0 + lr) : (M - 1);

    float acc[2][8][4];
#pragma unroll
    for (int i = 0; i < 2; i++)
#pragma unroll
        for (int j = 0; j < 8; j++)
#pragma unroll
            for (int q = 0; q < 4; q++) acc[i][j][q] = 0.f;

    for (int kc = 0; kc < 2; kc++) {
        const int k0 = kc * 64;
#pragma unroll
        for (int i = 0; i < 4; i++) {
            const int u = (tid & 1) * 4 + i;
            const uint32_t d = lr * 128 + (uint32_t)(((u ^ (lr & 7))) << 4);
            cp16(sb + d,         (const char*)(Ahi + (size_t)arow * 128 + k0) + u * 16);
            cp16(sb + 16384 + d, (const char*)(Alo + (size_t)arow * 128 + k0) + u * 16);
        }
        for (int i = tid; i < 128 * 8; i += 256) {
            const int r = i >> 3, u = i & 7;
            const uint32_t d = r * 128 + (uint32_t)(((u ^ (r & 7))) << 4);
            cp16(sb + 32768 + d, (const char*)(Bhi + (size_t)r * 128 + k0) + u * 16);
            cp16(sb + 49152 + d, (const char*)(Blo + (size_t)r * 128 + k0) + u * 16);
        }
        CP_COMMIT();
        CP_WAIT(0);
        __syncthreads();
        ldsm_mma8(acc, sb, sb + 32768, tid);
        __syncthreads();
    }

    const int wm = wid >> 1, wn = wid & 1;
#pragma unroll
    for (int mt = 0; mt < 2; mt++) {
        const int r = row0 + wm * 32 + mt * 16 + (lane >> 2);
#pragma unroll
        for (int nt = 0; nt < 8; nt++) {
            const int c = wn * 64 + nt * 8 + (lane & 3) * 2;
#pragma unroll
            for (int half = 0; half < 2; half++) {
                const int rr = r + half * 8;
                if (rr >= M) continue;
                *(float2*)(Cf + (size_t)rr * 128 + c) =
                    make_float2(acc[mt][nt][half * 2], acc[mt][nt][half * 2 + 1]);
            }
        }
    }
}

// ---------------- host launch ----------------
extern "C" void kernel_launch(void* const* d_in, const int* in_sizes, int n_in,
                              void* d_out, int out_size)
{
    const float* h_V   = (const float*)d_in[0];
    const float* h_E   = (const float*)d_in[1];
    const int*   eidx  = (const int*)  d_in[2];
    const float* hvv   = (const float*)d_in[3];
    const float* frame = (const float*)d_in[4];
    const float* W_vec = (const float*)d_in[5];
    const float* W_red = (const float*)d_in[6];
    const float* Wb1   = (const float*)d_in[7];
    const float* bb1   = (const float*)d_in[8];
    const float* Wb2   = (const float*)d_in[9];
    const float* bb2   = (const float*)d_in[10];
    const float* Wb3   = (const float*)d_in[11];
    const float* bb3   = (const float*)d_in[12];
    const float* Wv1   = (const float*)d_in[13];
    const float* bv1   = (const float*)d_in[14];
    const float* Wv2   = (const float*)d_in[15];
    const float* bv2   = (const float*)d_in[16];
    const float* Wv3   = (const float*)d_in[17];
    const float* bv3   = (const float*)d_in[18];
    const float* W_O   = (const float*)d_in[19];
    const float* bn_g  = (const float*)d_in[20];
    const float* bn_b  = (const float*)d_in[21];

    int E = in_sizes[2] / 2;
    int N = in_sizes[0] / 128;
    float* out = (float*)d_out;

    float *vff, *hVW, *gsum, *hagg, *bnst;
    bf16 *hgh, *hgl, *wh, *wl;
    double* bnacc;
    cudaGetSymbolAddress((void**)&vff,   g_vff);
    cudaGetSymbolAddress((void**)&hVW,   g_hVW);
    cudaGetSymbolAddress((void**)&hgh,   g_hgh);
    cudaGetSymbolAddress((void**)&hgl,   g_hgl);
    cudaGetSymbolAddress((void**)&wh,    g_wh);
    cudaGetSymbolAddress((void**)&wl,    g_wl);
    cudaGetSymbolAddress((void**)&gsum,  g_sum);
    cudaGetSymbolAddress((void**)&hagg,  g_hagg);
    cudaGetSymbolAddress((void**)&bnacc, g_bnacc);
    cudaGetSymbolAddress((void**)&bnst,  g_bnst);

    const int SMEM_O = 65536;
    const int SMEM_G = 256 * 65 * 4;   // 66560
    cudaFuncSetAttribute(mega_kernel, cudaFuncAttributeMaxDynamicSharedMemorySize, SMEM_MEGA);
    cudaFuncSetAttribute(hmma_gemm_o, cudaFuncAttributeMaxDynamicSharedMemorySize, SMEM_O);
    cudaFuncSetAttribute(geom_kernel, cudaFuncAttributeMaxDynamicSharedMemorySize, SMEM_G);

    int Mt = (E + 127) / 128;
    int Mo = (N + 127) / 128;

    init_kernel<<<(N * 128 + 255) / 256, 256>>>(gsum, hagg, bnacc, N);
    geom_kernel<<<(E + 255) / 256, 256, SMEM_G>>>(eidx, hvv, frame, W_vec, vff, bnacc, E);
    bn_finalize<<<1, 32>>>(bnacc, bn_g, bn_b, bnst, E);

    wprep_all<<<(W_TOTAL + 255) / 256, 256>>>(W_red, Wb1, Wb2, Wv1, Wv2, Wv3, W_O, wh, wl);
    hvw_kernel<<<(N + 1) / 2, 256>>>(h_V, Wb1, hVW, N);

    mega_kernel<<<Mt, 512, SMEM_MEGA>>>(
        vff, h_E, bnst, hVW, eidx,
        wh + OW_RED, wl + OW_RED,
        wh + OW_B1, wl + OW_B1, bb1,
        wh + OW_B2, wl + OW_B2, bb2,
        Wb3, bb3,
        wh + OW_V1, wl + OW_V1, bv1,
        wh + OW_V2, wl + OW_V2, bv2,
        wh + OW_V3, wl + OW_V3, bv3,
        gsum, hagg, E);

    // hagg normalized by segment sums -> planes, then out = hagg @ W_O
    c2planes_norm<<<(N * 128 + 255) / 256, 256>>>(hagg, gsum, hgh, hgl, N);
    hmma_gemm_o<<<Mo, 256, SMEM_O>>>(hgh, hgl, wh + OW_O, wl + OW_O, out, N);
}

// round 14
// speedup vs baseline: 1.4520x; 1.2612x over previous
#include <cuda_runtime.h>
#include <cuda_fp16.h>
#include <math.h>
#include <stdint.h>

#define E_CONST 320000
#define N_CONST 10000
typedef __half f16;

// ---------------- scratch (no allocations allowed) ----------------
static __device__ float    g_vff [(size_t)E_CONST * 64];   // fp32 [sincos48|dist16]
static __device__ float    g_hVW [N_CONST * 128];          // hV @ Wb1_top (fp32, per node)
static __device__ f16      g_hgh [N_CONST * 128];
static __device__ f16      g_hgl [N_CONST * 128];
static __device__ f16      g_w   [262144];                 // all weights, single fp16 plane, [n][k]
static __device__ float    g_sum [N_CONST * 4];
static __device__ float    g_hagg[N_CONST * 128];
static __device__ double   g_bnacc[32];
static __device__ float    g_bnst[32];

// weight plane offsets (elements)
#define OW_RED 0        // 256 x 320
#define OW_B1  81920    // 128 x 384
#define OW_B2  131072   // 128 x 128
#define OW_V1  147456   // 128 x 256
#define OW_V2  180224   // 128 x 128
#define OW_V3  196608   // 128 x 128
#define OW_O   212992   // 128 x 128
#define W_TOTAL 229376

// mega smem tail (beyond the 224KB working set)
#define ATT_OFF 229376
#define CEN_OFF 231424
#define SMEM_MEGA 231936

// ---------------- helpers ----------------
__device__ __forceinline__ uint32_t smem_u32(const void* p) {
    uint32_t a;
    asm("{ .reg .u64 t; cvta.to.shared.u64 t, %1; cvt.u32.u64 %0, t; }" : "=r"(a) : "l"(p));
    return a;
}
__device__ __forceinline__ void cp16(uint32_t dst, const void* src) {
    asm volatile("cp.async.cg.shared.global [%0], [%1], 16;"
        :: "r"(dst), "l"(__cvta_generic_to_global(src)) : "memory");
}
#define CP_COMMIT() asm volatile("cp.async.commit_group;" ::: "memory")
#define CP_WAIT(n)  asm volatile("cp.async.wait_group %0;" :: "n"(n) : "memory")

__device__ __forceinline__ void ldsm4(uint32_t* r, uint32_t addr) {
    asm volatile("ldmatrix.sync.aligned.m8n8.x4.shared.b16 {%0,%1,%2,%3}, [%4];"
        : "=r"(r[0]), "=r"(r[1]), "=r"(r[2]), "=r"(r[3]) : "r"(addr));
}
__device__ __forceinline__ void mmaf16(float* d, const uint32_t* a, const uint32_t* b) {
    asm volatile(
        "mma.sync.aligned.m16n8k16.row.col.f32.f16.f16.f32 "
        "{%0,%1,%2,%3}, {%4,%5,%6,%7}, {%8,%9}, {%0,%1,%2,%3};"
        : "+f"(d[0]), "+f"(d[1]), "+f"(d[2]), "+f"(d[3])
        : "r"(a[0]), "r"(a[1]), "r"(a[2]), "r"(a[3]), "r"(b[0]), "r"(b[1]));
}
__device__ __forceinline__ void red2(float* addr, float x, float y) {
    asm volatile("red.global.v2.f32.add [%0], {%1, %2};"
        :: "l"(__cvta_generic_to_global(addr)), "f"(x), "f"(y) : "memory");
}
__device__ __forceinline__ float gelu_f(float x) {
    return 0.5f * x * (1.f + erff(x * 0.70710678118654752f));
}
// pack two floats to (hi,lo) fp16 pairs
__device__ __forceinline__ void split2(float a, float b, uint32_t& hi, uint32_t& lo) {
    __half ha = __float2half_rn(a), hb = __float2half_rn(b);
    __half la = __float2half_rn(a - __half2float(ha));
    __half lb = __float2half_rn(b - __half2float(hb));
    __half2 hp; hp.x = ha; hp.y = hb;
    __half2 lp; lp.x = la; lp.y = lb;
    hi = reinterpret_cast<uint32_t&>(hp);
    lo = reinterpret_cast<uint32_t&>(lp);
}

// ---------------- init ----------------
__global__ void init_kernel(float* gsum, float* hagg, double* bnacc, int N)
{
    int i = blockIdx.x * 256 + threadIdx.x;
    if (i < N * 128) hagg[i] = 0.f;
    if (i < N * 4) gsum[i] = 0.f;
    if (i < 32) bnacc[i] = 0.0;
}

// ---------------- geometry + BN stats ----------------
__global__ __launch_bounds__(256)
void geom_kernel(const int* __restrict__ eidx, const float* __restrict__ hvv,
                 const float* __restrict__ frame, const float* __restrict__ Wvec,
                 float* __restrict__ vff, double* __restrict__ bnacc, int E)
{
    extern __shared__ float sbuf[];   // 256 * 65 floats
    __shared__ float Ws[512];
    __shared__ float bsum[16], bsq[16];
    int tid = threadIdx.x;
    for (int i = tid; i < 512; i += 256) Ws[i] = Wvec[i];
    if (tid < 16) { bsum[tid] = 0.f; bsq[tid] = 0.f; }
    __syncthreads();

    const int e0 = blockIdx.x * 256;
    const int e = e0 + tid;
    float dloc[16];
#pragma unroll
    for (int o = 0; o < 16; o++) dloc[o] = 0.f;

    if (e < E) {
        const int c = eidx[e];
        const int d = eidx[E + e];
        float F[9];
#pragma unroll
        for (int i = 0; i < 9; i++) F[i] = frame[e * 9 + i];

        float vdt[48], vsrc[48];
        {
            const float4* pd = (const float4*)(hvv + (size_t)d * 48);
            const float4* pc = (const float4*)(hvv + (size_t)c * 48);
#pragma unroll
            for (int i = 0; i < 12; i++) {
                ((float4*)vdt)[i]  = pd[i];
                ((float4*)vsrc)[i] = pc[i];
            }
        }
#pragma unroll
        for (int v = 0; v < 16; v++) {
            const float x = vdt[v * 3 + 0], y = vdt[v * 3 + 1], z = vdt[v * 3 + 2];
            vdt[v * 3 + 0] = F[0] * x + F[1] * y + F[2] * z;
            vdt[v * 3 + 1] = F[3] * x + F[4] * y + F[5] * z;
            vdt[v * 3 + 2] = F[6] * x + F[7] * y + F[8] * z;
        }

        float* row = sbuf + tid * 65;
#pragma unroll
        for (int o = 0; o < 16; o++) {
            float v0 = vdt[o * 3 + 0], v1 = vdt[o * 3 + 1], v2 = vdt[o * 3 + 2];
#pragma unroll
            for (int v = 0; v < 16; v++) {
                const float wa = Ws[o * 32 + v], wb = Ws[o * 32 + 16 + v];
                v0 += wa * vdt[v * 3 + 0] + wb * vsrc[v * 3 + 0];
                v1 += wa * vdt[v * 3 + 1] + wb * vsrc[v * 3 + 1];
                v2 += wa * vdt[v * 3 + 2] + wb * vsrc[v * 3 + 2];
            }
            const float dist = sqrtf(v0 * v0 + v1 * v1 + v2 * v2) + 1e-6f;
            const float inv = 1.f / dist;
            row[o * 3 + 0] = v0 * inv;
            row[o * 3 + 1] = v1 * inv;
            row[o * 3 + 2] = v2 * inv;
            row[48 + o] = dist;
            dloc[o] = dist;
        }
    }

#pragma unroll
    for (int o = 0; o < 16; o++) {
        float v = dloc[o], v2 = v * v;
#pragma unroll
        for (int off = 16; off; off >>= 1) {
            v  += __shfl_down_sync(0xffffffffu, v, off);
            v2 += __shfl_down_sync(0xffffffffu, v2, off);
        }
        if ((tid & 31) == 0) { atomicAdd(&bsum[o], v); atomicAdd(&bsq[o], v2); }
    }
    __syncthreads();
    if (tid < 16) {
        atomicAdd(&bnacc[tid], (double)bsum[tid]);
        atomicAdd(&bnacc[16 + tid], (double)bsq[tid]);
    }

    const int nblk = (E - e0 < 256) ? (E - e0) : 256;
    for (int j = tid; j < nblk * 16; j += 256) {
        const int r = j >> 4, q = (j & 15) * 4;
        const float* sr = sbuf + r * 65 + q;
        *(float4*)(vff + (size_t)(e0 + r) * 64 + q) =
            make_float4(sr[0], sr[1], sr[2], sr[3]);
    }
}

__global__ void bn_finalize(const double* __restrict__ acc, const float* __restrict__ g,
                            const float* __restrict__ b, float* __restrict__ st, int E)
{
    int i = threadIdx.x;
    if (i >= 16) return;
    double mean = acc[i] / (double)E;
    double var  = acc[16 + i] / (double)E - mean * mean;
    float s = (float)((double)g[i] / sqrt(var + 1e-5));
    st[i] = s;
    st[16 + i] = b[i] - (float)mean * s;
}

// ---------------- conversion passes ----------------
__global__ void wprep_all(const float* __restrict__ W0, const float* __restrict__ W1,
                          const float* __restrict__ W2, const float* __restrict__ W3,
                          const float* __restrict__ W4, const float* __restrict__ W5,
                          const float* __restrict__ W6, f16* __restrict__ w)
{
    int idx = blockIdx.x * 256 + threadIdx.x;
    if (idx >= W_TOTAL) return;
    const float* src; int K, NT, start;
    if      (idx < OW_B1)  { src = W0; K = 320; NT = 256; start = OW_RED; }
    else if (idx < OW_B2)  { src = W1; K = 384; NT = 128; start = OW_B1; }
    else if (idx < OW_V1)  { src = W2; K = 128; NT = 128; start = OW_B2; }
    else if (idx < OW_V2)  { src = W3; K = 256; NT = 128; start = OW_V1; }
    else if (idx < OW_V3)  { src = W4; K = 128; NT = 128; start = OW_V2; }
    else if (idx < OW_O)   { src = W5; K = 128; NT = 128; start = OW_V3; }
    else                   { src = W6; K = 128; NT = 128; start = OW_O; }
    int local = idx - start;
    int k = local / NT, n = local % NT;
    w[start + (size_t)n * K + k] = __float2half_rn(src[local]);
}

// hVW = hV @ Wb1[0:128,:]  (exact fp32, per-node)
__global__ __launch_bounds__(256)
void hvw_kernel(const float* __restrict__ hV, const float* __restrict__ Wb1,
                float* __restrict__ hVW, int N)
{
    __shared__ float xs[2][128];
    const int t = threadIdx.x;
    const int which = t >> 7, c = t & 127;
    const int node = blockIdx.x * 2 + which;
    if (node < N) xs[which][c] = hV[(size_t)node * 128 + c];
    __syncthreads();
    if (node >= N) return;
    float s = 0.f;
#pragma unroll 8
    for (int k = 0; k < 128; k++) s += xs[which][k] * Wb1[k * 128 + c];
    hVW[(size_t)node * 128 + c] = s;
}

// hagg -> fp16 hi/lo planes with softmax normalization folded in
__global__ void c2planes_norm(const float* __restrict__ x, const float* __restrict__ gsum,
                              f16* __restrict__ hi, f16* __restrict__ lo, int N)
{
    int i = blockIdx.x * 256 + threadIdx.x;
    if (i >= N * 128) return;
    int node = i >> 7, col = i & 127;
    float s = gsum[node * 4 + (col >> 5)];
    float v = x[i] / (s > 0.f ? s : 1.f);
    f16 h = __float2half_rn(v);
    hi[i] = h;
    lo[i] = __float2half_rn(v - __half2float(h));
}

// ================= GEMM building blocks (512 threads, 16 warps = 4m x 4n) =================
// fp16x2: A = hi+lo planes (full precision), B = single fp16 plane.
template<int NT>
__device__ __forceinline__ void mma_half512(
    float (&acc)[2][NT][4], uint32_t aHi, uint32_t aLo, uint32_t bB, int ks0, int tid)
{
    const int wid = tid >> 5, lane = tid & 31;
    const int wm = wid >> 2, wn = wid & 3;
    const int a_row = wm * 32 + (lane & 7) + ((lane & 8) ? 8 : 0);
    const int a_ub  = (lane & 16) ? 1 : 0;
    const int b_row0 = wn * (NT * 8) + (lane & 7) + ((lane & 16) ? 8 : 0);
    const int b_ub  = (lane & 8) ? 1 : 0;
#pragma unroll
    for (int kss = 0; kss < 2; kss++) {
        const int ks = ks0 + kss;
        uint32_t ahi[2][4], alo[2][4];
#pragma unroll
        for (int mt = 0; mt < 2; mt++) {
            const int r = a_row + mt * 16;
            const int u = ks * 2 + a_ub;
            const uint32_t off = r * 128 + (uint32_t)(((u ^ (r & 7))) << 4);
            ldsm4(ahi[mt], aHi + off);
            ldsm4(alo[mt], aLo + off);
        }
        uint32_t bb[NT / 2][4];
#pragma unroll
        for (int g = 0; g < NT / 2; g++) {
            const int n = b_row0 + g * 16;
            const int u = ks * 2 + b_ub;
            const uint32_t off = n * 128 + (uint32_t)(((u ^ (n & 7))) << 4);
            ldsm4(bb[g], bB + off);
        }
#pragma unroll
        for (int mt = 0; mt < 2; mt++)
#pragma unroll
            for (int ntl = 0; ntl < NT; ntl++) {
                float* a_ = acc[mt][ntl];
                const uint32_t* bp = &bb[ntl >> 1][(ntl & 1) * 2];
                mmaf16(a_, ahi[mt], bp);
                mmaf16(a_, alo[mt], bp);
            }
    }
}

template<int NT>
__device__ __forceinline__ void mma_chunk(
    float (&acc)[2][NT][4], uint32_t aHi, uint32_t aLo, uint32_t bB, int tid)
{
    mma_half512<NT>(acc, aHi, aLo, bB, 0, tid);
    mma_half512<NT>(acc, aHi, aLo, bB, 2, tid);
}

// stage one 64-K chunk of a single-plane weight, `rows` rows (16B units: 8/row)
__device__ __forceinline__ void stage_w(uint32_t dst, const f16* __restrict__ W,
                                        int K, int k0, int rows, int tid)
{
    for (int i = tid; i < rows * 8; i += 512) {
        const int r = i >> 3, u = i & 7;
        const uint32_t d = r * 128 + (uint32_t)(((u ^ (r & 7))) << 4);
        cp16(dst + d, (const char*)(W + (size_t)r * K + k0) + u * 16);
    }
    CP_COMMIT();
}
// stage two 64-K chunks (128 rows) into dst, dst+16K
__device__ __forceinline__ void stage_w2(uint32_t dst, const f16* __restrict__ W,
                                         int K, int k0, int tid)
{
    for (int i = tid; i < 2048; i += 512) {
        const int ch = i >> 10, rem = i & 1023;
        const int r = rem >> 3, u = rem & 7;
        const uint32_t d = ch * 16384 + r * 128 + (uint32_t)(((u ^ (r & 7))) << 4);
        cp16(dst + d, (const char*)(W + (size_t)r * K + k0 + ch * 64) + u * 16);
    }
    CP_COMMIT();
}

// store fragments -> smem fp16 hi/lo planes (chunked layout), bias+activation
template<int NT, int ACT>
__device__ __forceinline__ void store_planes512(const float (&acc)[2][NT][4],
                                                char* smemp, uint32_t baseHi, uint32_t baseLo,
                                                const float* __restrict__ bias, int tid)
{
    const int wid = tid >> 5, lane = tid & 31;
    const int wm = wid >> 2, wn = wid & 3;
#pragma unroll
    for (int mt = 0; mt < 2; mt++)
#pragma unroll
        for (int nt = 0; nt < NT; nt++) {
            const int c = wn * (NT * 8) + nt * 8 + (lane & 3) * 2;
            const int kc = c >> 6, kk = c & 63, u = kk >> 3;
            const float b0 = bias ? bias[c] : 0.f;
            const float b1 = bias ? bias[c + 1] : 0.f;
#pragma unroll
            for (int half = 0; half < 2; half++) {
                const int r = wm * 32 + mt * 16 + (lane >> 2) + half * 8;
                float e0 = acc[mt][nt][half * 2] + b0;
                float e1 = acc[mt][nt][half * 2 + 1] + b1;
                if (ACT == 1) { e0 = fmaxf(e0, 0.f); e1 = fmaxf(e1, 0.f); }
                if (ACT == 2) { e0 = gelu_f(e0); e1 = gelu_f(e1); }
                uint32_t hp, lp;
                split2(e0, e1, hp, lp);
                const uint32_t ad = kc * 16384 + r * 128 +
                                    (uint32_t)(((u ^ (r & 7))) << 4) + (kk & 7) * 2;
                *(uint32_t*)(smemp + baseHi + ad) = hp;
                *(uint32_t*)(smemp + baseLo + ad) = lp;
            }
        }
}

// ---------------- MEGA kernel (512 threads) ----------------
// smem: [0,64K) heHi (4 chunks; later v2 hi/lo), [64K,128K) heLo (later Wv3 stage),
//       [128K,192K) xv (A-convert / x1,v1 planes / x2 fp32 / weight staging),
//       [192K,224K) stg (weight chunks / P0 B ping-pong buffer),
//       [224K..) att, cen
__global__ __launch_bounds__(512, 1)
void mega_kernel(const float* __restrict__ Vff, const float* __restrict__ HE,
                 const float* __restrict__ bn_st,
                 const float* __restrict__ hVW,
                 const int* __restrict__ eidx,
                 const f16* __restrict__ wred,
                 const f16* __restrict__ wb1, const float* __restrict__ bb1,
                 const f16* __restrict__ wb2, const float* __restrict__ bb2,
                 const float* __restrict__ Wb3, const float* __restrict__ bb3,
                 const f16* __restrict__ wv1, const float* __restrict__ bv1,
                 const f16* __restrict__ wv2, const float* __restrict__ bv2,
                 const f16* __restrict__ wv3, const float* __restrict__ bv3,
                 float* __restrict__ gsum, float* __restrict__ hagg, int M)
{
    extern __shared__ char smem[];
    const uint32_t sb = smem_u32(smem);
    const uint32_t heHi = sb;
    const uint32_t heLo = sb + 65536;
    const uint32_t xv   = sb + 131072;
    const uint32_t stg  = sb + 196608;
    const int tid = threadIdx.x;
    const int wid = tid >> 5, lane = tid & 31;
    const int row0 = blockIdx.x * 128;

    const int lr = tid >> 2;              // 4 threads per row
    const int arow = (row0 + lr < M) ? (row0 + lr) : (M - 1);
    const int cu0 = (tid & 3) * 4;        // fp32 16B-unit base for A convert

    {
        int* cens = (int*)(smem + CEN_OFF);
        if (tid < 128) {
            int er = row0 + tid;
            cens[tid] = eidx[er < M ? er : M - 1];
        }
    }

    // ================= P0: hE = [vff_bn | h_E] @ W_red (K=320, N=256) =================
    // A: fp32 regs -> fp16 hi/lo planes at xv[0,32K); B: full-chunk ping-pong xv+32K / stg
    {
        float acc0[2][8][4];
#pragma unroll
        for (int i = 0; i < 2; i++)
#pragma unroll
            for (int j = 0; j < 8; j++)
#pragma unroll
                for (int q = 0; q < 4; q++) acc0[i][j][q] = 0.f;

        float4 areg[4];
        {
            const float4* pa = (const float4*)(Vff + (size_t)arow * 64);
#pragma unroll
            for (int jj = 0; jj < 4; jj++) areg[jj] = pa[cu0 + jj];
        }
        stage_w(xv + 32768, wred, 320, 0, 256, tid);   // G0: B0 -> buf0

        for (int kc = 0; kc < 5; kc++) {
            // convert A regs -> fp16 hi/lo planes
            {
                float4 f[4];
#pragma unroll
                for (int jj = 0; jj < 4; jj++) f[jj] = areg[jj];
                if (kc == 0 && cu0 >= 12) {
#pragma unroll
                    for (int jj = 0; jj < 4; jj++) {
                        const int u = cu0 + jj;
                        if (u >= 12) {
                            const int col = u * 4;
                            f[jj].x = fmaf(f[jj].x, bn_st[col - 48], bn_st[col - 32]);
                            f[jj].y = fmaf(f[jj].y, bn_st[col - 47], bn_st[col - 31]);
                            f[jj].z = fmaf(f[jj].z, bn_st[col - 46], bn_st[col - 30]);
                            f[jj].w = fmaf(f[jj].w, bn_st[col - 45], bn_st[col - 29]);
                        }
                    }
                }
#pragma unroll
                for (int jj = 0; jj < 2; jj++) {
                    uint32_t ph[4], pl[4];
                    split2(f[2*jj].x,   f[2*jj].y,   ph[0], pl[0]);
                    split2(f[2*jj].z,   f[2*jj].w,   ph[1], pl[1]);
                    split2(f[2*jj+1].x, f[2*jj+1].y, ph[2], pl[2]);
                    split2(f[2*jj+1].z, f[2*jj+1].w, ph[3], pl[3]);
                    const int un = (cu0 >> 1) + jj;
                    const uint32_t ad = lr * 128 + (uint32_t)(((un ^ (lr & 7))) << 4);
                    *(uint4*)(smem + 131072 + ad)         = make_uint4(ph[0], ph[1], ph[2], ph[3]);
                    *(uint4*)(smem + 131072 + 16384 + ad) = make_uint4(pl[0], pl[1], pl[2], pl[3]);
                }
            }
            if (kc < 4) {
                const float4* pa = (const float4*)(HE + (size_t)arow * 256 + kc * 64);
#pragma unroll
                for (int jj = 0; jj < 4; jj++) areg[jj] = pa[cu0 + jj];
                // stage B(kc+1) into the other buffer
                stage_w(((kc + 1) & 1) ? stg : (xv + 32768), wred, 320, (kc + 1) * 64, 256, tid);
                CP_WAIT(1);
            } else {
                CP_WAIT(0);
            }
            __syncthreads();
            mma_chunk<8>(acc0, xv, xv + 16384, (kc & 1) ? stg : (xv + 32768), tid);
            __syncthreads();
        }

        // prestage Wb1 c0,c1 -> stg (G5), overlapped with hE epilogue
        stage_w2(stg, wb1, 384, 128, tid);
        store_planes512<8, 0>(acc0, smem, 0, 65536, nullptr, tid);
    }
    CP_WAIT(0);
    __syncthreads();

    // ================= P1: x1 = relu(hVW[center] + hE @ Wb1_bot + bb1), K=256 =================
    float acc1[2][4][4];
#pragma unroll
    for (int i = 0; i < 2; i++)
#pragma unroll
        for (int j = 0; j < 4; j++)
#pragma unroll
            for (int q = 0; q < 4; q++) acc1[i][j][q] = 0.f;
    {
        stage_w2(xv, wb1, 384, 256, tid);               // G6: c2,c3 -> xv[0,32K)
        mma_chunk<4>(acc1, heHi,         heLo,         stg,         tid);
        mma_chunk<4>(acc1, heHi + 16384, heLo + 16384, stg + 16384, tid);
        CP_WAIT(0);
        __syncthreads();
        mma_chunk<4>(acc1, heHi + 32768, heLo + 32768, xv,         tid);
        mma_chunk<4>(acc1, heHi + 49152, heLo + 49152, xv + 16384, tid);
        __syncthreads();

        stage_w2(stg, wb2, 128, 0, tid);                // G7: Wb2 c0,c1 -> stg

        // epilogue: fused global hVW read + bias + relu -> x1 planes in xv
        const int* cens = (const int*)(smem + CEN_OFF);
        const int wm = wid >> 2, wn = wid & 3;
#pragma unroll
        for (int mt = 0; mt < 2; mt++)
#pragma unroll
            for (int nt = 0; nt < 4; nt++) {
                const int c = wn * 32 + nt * 8 + (lane & 3) * 2;
                const int kc = c >> 6, kk = c & 63, u = kk >> 3;
                const float b0 = bb1[c], b1 = bb1[c + 1];
#pragma unroll
                for (int half = 0; half < 2; half++) {
                    const int r = wm * 32 + mt * 16 + (lane >> 2) + half * 8;
                    const float2 hv = *(const float2*)(hVW + (size_t)cens[r] * 128 + c);
                    float e0 = fmaxf(acc1[mt][nt][half * 2] + b0 + hv.x, 0.f);
                    float e1 = fmaxf(acc1[mt][nt][half * 2 + 1] + b1 + hv.y, 0.f);
                    uint32_t hp, lp;
                    split2(e0, e1, hp, lp);
                    const uint32_t ad = kc * 16384 + r * 128 +
                                        (uint32_t)(((u ^ (r & 7))) << 4) + (kk & 7) * 2;
                    *(uint32_t*)(smem + 131072 + ad) = hp;
                    *(uint32_t*)(smem + 131072 + 32768 + ad) = lp;
                }
            }
    }
    CP_WAIT(0);
    __syncthreads();

    // ================= P2: x2 = relu(x1 @ Wb2 + bb2) =================
    float acc2[2][4][4];
#pragma unroll
    for (int i = 0; i < 2; i++)
#pragma unroll
        for (int j = 0; j < 4; j++)
#pragma unroll
            for (int q = 0; q < 4; q++) acc2[i][j][q] = 0.f;
    mma_chunk<4>(acc2, xv,         xv + 32768, stg,         tid);
    mma_chunk<4>(acc2, xv + 16384, xv + 49152, stg + 16384, tid);
    __syncthreads();
    stage_w2(stg, wv1, 256, 0, tid);                    // G8: Wv1 c0,c1 -> stg
    // x2 fp32 -> xv (x1 dead)
    {
        const int wm = wid >> 2, wn = wid & 3;
#pragma unroll
        for (int mt = 0; mt < 2; mt++)
#pragma unroll
            for (int nt = 0; nt < 4; nt++) {
                const int c = wn * 32 + nt * 8 + (lane & 3) * 2;
                const float b0 = bb2[c], b1 = bb2[c + 1];
#pragma unroll
                for (int half = 0; half < 2; half++) {
                    const int r = wm * 32 + mt * 16 + (lane >> 2) + half * 8;
                    float e0 = fmaxf(acc2[mt][nt][half * 2] + b0, 0.f);
                    float e1 = fmaxf(acc2[mt][nt][half * 2 + 1] + b1, 0.f);
                    *(float2*)(smem + 131072 + ((size_t)r * 128 + c) * 4) = make_float2(e0, e1);
                }
            }
    }
    __syncthreads();

    // ================= P3: e = exp(logits), segment sum (Wb3 from L2) =================
    {
        const float* x2s = (const float*)(smem + 131072);
        float* atts = (float*)(smem + ATT_OFF);
        const int* cens = (const int*)(smem + CEN_OFF);
        for (int rr = wid * 8; rr < wid * 8 + 8; rr++) {
            const int e = row0 + rr;
            if (e >= M) break;
            float p0 = 0.f, p1 = 0.f, p2 = 0.f, p3 = 0.f;
#pragma unroll
            for (int j = 0; j < 4; j++) {
                const int c = lane + j * 32;
                const float x = x2s[rr * 128 + c];
                const float4 w4 = *(const float4*)(Wb3 + c * 8);
                p0 += x * w4.x;
                p1 += x * w4.y;
                p2 += x * w4.z;
                p3 += x * w4.w;
            }
#pragma unroll
            for (int off = 16; off; off >>= 1) {
                p0 += __shfl_xor_sync(0xffffffffu, p0, off);
                p1 += __shfl_xor_sync(0xffffffffu, p1, off);
                p2 += __shfl_xor_sync(0xffffffffu, p2, off);
                p3 += __shfl_xor_sync(0xffffffffu, p3, off);
            }
            if (lane < 4) {
                const float p = (lane == 0) ? p0 : (lane == 1) ? p1 : (lane == 2) ? p2 : p3;
                const float l = (p + bb3[lane]) * 0.17677669529663687f;
                const float ex = expf(l);
                atts[rr * 4 + lane] = ex;
                atomicAdd(&gsum[cens[rr] * 4 + lane], ex);
            }
        }
    }
    __syncthreads();

    // ================= P4: v1 = gelu(hE @ Wv1 + bv1) =================
    float acc3[2][4][4];
#pragma unroll
    for (int i = 0; i < 2; i++)
#pragma unroll
        for (int j = 0; j < 4; j++)
#pragma unroll
            for (int q = 0; q < 4; q++) acc3[i][j][q] = 0.f;
    stage_w2(xv, wv1, 256, 128, tid);                   // G9: c2,c3 -> xv (x2 dead after P3)
    CP_WAIT(1);                                         // G8 done (G9 pending)
    __syncthreads();
    mma_chunk<4>(acc3, heHi,         heLo,         stg,         tid);
    mma_chunk<4>(acc3, heHi + 16384, heLo + 16384, stg + 16384, tid);
    CP_WAIT(0);                                         // G9 done
    __syncthreads();
    mma_chunk<4>(acc3, heHi + 32768, heLo + 32768, xv,         tid);
    mma_chunk<4>(acc3, heHi + 49152, heLo + 49152, xv + 16384, tid);
    __syncthreads();
    stage_w2(stg, wv2, 128, 0, tid);                    // G10: Wv2 -> stg
    store_planes512<4, 2>(acc3, smem, 131072, 131072 + 32768, bv1, tid);  // v1 -> xv
    CP_WAIT(0);
    __syncthreads();

    // ================= P5: v2 = gelu(v1 @ Wv2 + bv2) =================
    float acc4[2][4][4];
#pragma unroll
    for (int i = 0; i < 2; i++)
#pragma unroll
        for (int j = 0; j < 4; j++)
#pragma unroll
            for (int q = 0; q < 4; q++) acc4[i][j][q] = 0.f;
    mma_chunk<4>(acc4, xv,         xv + 32768, stg,         tid);
    mma_chunk<4>(acc4, xv + 16384, xv + 49152, stg + 16384, tid);
    __syncthreads();
    stage_w2(heLo, wv3, 128, 0, tid);                   // G11: Wv3 -> heLo (hE dead)
    store_planes512<4, 2>(acc4, smem, 0, 32768, bv2, tid);   // v2 -> heHi region
    CP_WAIT(0);
    __syncthreads();

    // ================= P6: V = v2 @ Wv3 + bv3; hagg[center] += e * V =================
    float acc5[2][4][4];
#pragma unroll
    for (int i = 0; i < 2; i++)
#pragma unroll
        for (int j = 0; j < 4; j++)
#pragma unroll
            for (int q = 0; q < 4; q++) acc5[i][j][q] = 0.f;
    mma_chunk<4>(acc5, heHi,         heHi + 32768, heLo,         tid);
    mma_chunk<4>(acc5, heHi + 16384, heHi + 49152, heLo + 16384, tid);
    {
        const float* atts = (const float*)(smem + ATT_OFF);
        const int* cens = (const int*)(smem + CEN_OFF);
        const int wm = wid >> 2, wn = wid & 3;
#pragma unroll
        for (int mt = 0; mt < 2; mt++) {
#pragma unroll
            for (int nt = 0; nt < 4; nt++) {
                const int c = wn * 32 + nt * 8 + (lane & 3) * 2;
                const int h = c >> 5;
                const float b0 = bv3[c], b1 = bv3[c + 1];
#pragma unroll
                for (int half = 0; half < 2; half++) {
                    const int rl = wm * 32 + mt * 16 + (lane >> 2) + half * 8;
                    if (row0 + rl < M) {
                        const float a = atts[rl * 4 + h];
                        float* dst = hagg + (size_t)cens[rl] * 128 + c;
                        red2(dst, (acc5[mt][nt][half * 2] + b0) * a,
                                  (acc5[mt][nt][half * 2 + 1] + b1) * a);
                    }
                }
            }
        }
    }
}

// ---------------- standalone GEMM (W_O), 256 threads, fp16x2 ----------------
__global__ __launch_bounds__(256, 1)
void hmma_gemm_o(const f16* __restrict__ Ahi, const f16* __restrict__ Alo,
                 const f16* __restrict__ B, float* __restrict__ Cf, int M)
{
    extern __shared__ char smem[];
    const uint32_t sb = smem_u32(smem);
    const int tid = threadIdx.x;
    const int wid = tid >> 5, lane = tid & 31;
    const int row0 = blockIdx.x * 128;

    const int lr = tid >> 1;
    const int arow = (row0 + lr < M) ? (row0 + lr) : (M - 1);

    float acc[2][8][4];
#pragma unroll
    for (int i = 0; i < 2; i++)
#pragma unroll
        for (int j = 0; j < 8; j++)
#pragma unroll
            for (int q = 0; q < 4; q++) acc[i][j][q] = 0.f;

    const int wm = wid >> 1, wn = wid & 1;
    const int a_row = wm * 32 + (lane & 7) + ((lane & 8) ? 8 : 0);
    const int a_ub  = (lane & 16) ? 1 : 0;
    const int b_row0 = wn * 64 + (lane & 7) + ((lane & 16) ? 8 : 0);
    const int b_ub  = (lane & 8) ? 1 : 0;

    for (int kc = 0; kc < 2; kc++) {
        const int k0 = kc * 64;
#pragma unroll
        for (int i = 0; i < 4; i++) {
            const int u = (tid & 1) * 4 + i;
            const uint32_t d = lr * 128 + (uint32_t)(((u ^ (lr & 7))) << 4);
            cp16(sb + d,         (const char*)(Ahi + (size_t)arow * 128 + k0) + u * 16);
            cp16(sb + 16384 + d, (const char*)(Alo + (size_t)arow * 128 + k0) + u * 16);
        }
        for (int i = tid; i < 128 * 8; i += 256) {
            const int r = i >> 3, u = i & 7;
            const uint32_t d = r * 128 + (uint32_t)(((u ^ (r & 7))) << 4);
            cp16(sb + 32768 + d, (const char*)(B + (size_t)r * 128 + k0) + u * 16);
        }
        CP_COMMIT();
        CP_WAIT(0);
        __syncthreads();
#pragma unroll
        for (int ks = 0; ks < 4; ks++) {
            uint32_t ahi[2][4], alo[2][4];
#pragma unroll
            for (int mt = 0; mt < 2; mt++) {
                const int r = a_row + mt * 16;
                const int u = ks * 2 + a_ub;
                const uint32_t off = r * 128 + (uint32_t)(((u ^ (r & 7))) << 4);
                ldsm4(ahi[mt], sb + off);
                ldsm4(alo[mt], sb + 16384 + off);
            }
            uint32_t bb[4][4];
#pragma unroll
            for (int g = 0; g < 4; g++) {
                const int n = b_row0 + g * 16;
                const int u = ks * 2 + b_ub;
                const uint32_t off = n * 128 + (uint32_t)(((u ^ (n & 7))) << 4);
                ldsm4(bb[g], sb + 32768 + off);
            }
#pragma unroll
            for (int mt = 0; mt < 2; mt++)
#pragma unroll
                for (int ntl = 0; ntl < 8; ntl++) {
                    float* a_ = acc[mt][ntl];
                    const uint32_t* bp = &bb[ntl >> 1][(ntl & 1) * 2];
                    mmaf16(a_, ahi[mt], bp);
                    mmaf16(a_, alo[mt], bp);
                }
        }
        __syncthreads();
    }

#pragma unroll
    for (int mt = 0; mt < 2; mt++) {
        const int r = row0 + wm * 32 + mt * 16 + (lane >> 2);
#pragma unroll
        for (int nt = 0; nt < 8; nt++) {
            const int c = wn * 64 + nt * 8 + (lane & 3) * 2;
#pragma unroll
            for (int half = 0; half < 2; half++) {
                const int rr = r + half * 8;
                if (rr >= M) continue;
                *(float2*)(Cf + (size_t)rr * 128 + c) =
                    make_float2(acc[mt][nt][half * 2], acc[mt][nt][half * 2 + 1]);
            }
        }
    }
}

// ---------------- host launch ----------------
extern "C" void kernel_launch(void* const* d_in, const int* in_sizes, int n_in,
                              void* d_out, int out_size)
{
    const float* h_V   = (const float*)d_in[0];
    const float* h_E   = (const float*)d_in[1];
    const int*   eidx  = (const int*)  d_in[2];
    const float* hvv   = (const float*)d_in[3];
    const float* frame = (const float*)d_in[4];
    const float* W_vec = (const float*)d_in[5];
    const float* W_red = (const float*)d_in[6];
    const float* Wb1   = (const float*)d_in[7];
    const float* bb1   = (const float*)d_in[8];
    const float* Wb2   = (const float*)d_in[9];
    const float* bb2   = (const float*)d_in[10];
    const float* Wb3   = (const float*)d_in[11];
    const float* bb3   = (const float*)d_in[12];
    const float* Wv1   = (const float*)d_in[13];
    const float* bv1   = (const float*)d_in[14];
    const float* Wv2   = (const float*)d_in[15];
    const float* bv2   = (const float*)d_in[16];
    const float* Wv3   = (const float*)d_in[17];
    const float* bv3   = (const float*)d_in[18];
    const float* W_O   = (const float*)d_in[19];
    const float* bn_g  = (const float*)d_in[20];
    const float* bn_b  = (const float*)d_in[21];

    int E = in_sizes[2] / 2;
    int N = in_sizes[0] / 128;
    float* out = (float*)d_out;

    float *vff, *hVW, *gsum, *hagg, *bnst;
    f16 *hgh, *hgl, *w;
    double* bnacc;
    cudaGetSymbolAddress((void**)&vff,   g_vff);
    cudaGetSymbolAddress((void**)&hVW,   g_hVW);
    cudaGetSymbolAddress((void**)&hgh,   g_hgh);
    cudaGetSymbolAddress((void**)&hgl,   g_hgl);
    cudaGetSymbolAddress((void**)&w,     g_w);
    cudaGetSymbolAddress((void**)&gsum,  g_sum);
    cudaGetSymbolAddress((void**)&hagg,  g_hagg);
    cudaGetSymbolAddress((void**)&bnacc, g_bnacc);
    cudaGetSymbolAddress((void**)&bnst,  g_bnst);

    const int SMEM_O = 49152;
    const int SMEM_G = 256 * 65 * 4;   // 66560
    cudaFuncSetAttribute(mega_kernel, cudaFuncAttributeMaxDynamicSharedMemorySize, SMEM_MEGA);
    cudaFuncSetAttribute(hmma_gemm_o, cudaFuncAttributeMaxDynamicSharedMemorySize, SMEM_O);
    cudaFuncSetAttribute(geom_kernel, cudaFuncAttributeMaxDynamicSharedMemorySize, SMEM_G);

    int Mt = (E + 127) / 128;
    int Mo = (N + 127) / 128;

    init_kernel<<<(N * 128 + 255) / 256, 256>>>(gsum, hagg, bnacc, N);
    geom_kernel<<<(E + 255) / 256, 256, SMEM_G>>>(eidx, hvv, frame, W_vec, vff, bnacc, E);
    bn_finalize<<<1, 32>>>(bnacc, bn_g, bn_b, bnst, E);

    wprep_all<<<(W_TOTAL + 255) / 256, 256>>>(W_red, Wb1, Wb2, Wv1, Wv2, Wv3, W_O, w);
    hvw_kernel<<<(N + 1) / 2, 256>>>(h_V, Wb1, hVW, N);

    mega_kernel<<<Mt, 512, SMEM_MEGA>>>(
        vff, h_E, bnst, hVW, eidx,
        w + OW_RED,
        w + OW_B1, bb1,
        w + OW_B2, bb2,
        Wb3, bb3,
        w + OW_V1, bv1,
        w + OW_V2, bv2,
        w + OW_V3, bv3,
        gsum, hagg, E);

    c2planes_norm<<<(N * 128 + 255) / 256, 256>>>(hagg, gsum, hgh, hgl, N);
    hmma_gemm_o<<<Mo, 256, SMEM_O>>>(hgh, hgl, w + OW_O, out, N);
}

// round 15
// speedup vs baseline: 1.7588x; 1.2113x over previous
#include <cuda_runtime.h>
#include <cuda_fp16.h>
#include <math.h>
#include <stdint.h>

#define E_CONST 320000
#define N_CONST 10000
typedef __half f16;

// ---------------- scratch (no allocations allowed) ----------------
static __device__ float    g_vff [(size_t)E_CONST * 64];   // fp32 [sincos48|dist16]
static __device__ float    g_hVW [N_CONST * 128];          // hV @ Wb1_top (fp32, per node)
static __device__ f16      g_hgh [N_CONST * 128];
static __device__ f16      g_hgl [N_CONST * 128];
static __device__ f16      g_w   [262144];                 // all weights, single fp16 plane, [n][k]
static __device__ float    g_sum [N_CONST * 4];
static __device__ float    g_hagg[N_CONST * 128];
static __device__ double   g_bnacc[32];
static __device__ float    g_bnst[32];

// weight plane offsets (elements)
#define OW_RED 0        // 256 x 320
#define OW_B1  81920    // 128 x 384
#define OW_B2  131072   // 128 x 128
#define OW_V1  147456   // 128 x 256
#define OW_V2  180224   // 128 x 128
#define OW_V3  196608   // 128 x 128
#define OW_O   212992   // 128 x 128
#define W_TOTAL 229376

// mega smem tail (beyond the 224KB working set)
#define ATT_OFF 229376
#define CEN_OFF 231424
#define SMEM_MEGA 231936

// ---------------- helpers ----------------
__device__ __forceinline__ uint32_t smem_u32(const void* p) {
    uint32_t a;
    asm("{ .reg .u64 t; cvta.to.shared.u64 t, %1; cvt.u32.u64 %0, t; }" : "=r"(a) : "l"(p));
    return a;
}
__device__ __forceinline__ void cp16(uint32_t dst, const void* src) {
    asm volatile("cp.async.cg.shared.global [%0], [%1], 16;"
        :: "r"(dst), "l"(__cvta_generic_to_global(src)) : "memory");
}
#define CP_COMMIT() asm volatile("cp.async.commit_group;" ::: "memory")
#define CP_WAIT(n)  asm volatile("cp.async.wait_group %0;" :: "n"(n) : "memory")

__device__ __forceinline__ void ldsm4(uint32_t* r, uint32_t addr) {
    asm volatile("ldmatrix.sync.aligned.m8n8.x4.shared.b16 {%0,%1,%2,%3}, [%4];"
        : "=r"(r[0]), "=r"(r[1]), "=r"(r[2]), "=r"(r[3]) : "r"(addr));
}
__device__ __forceinline__ void mmaf16(float* d, const uint32_t* a, const uint32_t* b) {
    asm volatile(
        "mma.sync.aligned.m16n8k16.row.col.f32.f16.f16.f32 "
        "{%0,%1,%2,%3}, {%4,%5,%6,%7}, {%8,%9}, {%0,%1,%2,%3};"
        : "+f"(d[0]), "+f"(d[1]), "+f"(d[2]), "+f"(d[3])
        : "r"(a[0]), "r"(a[1]), "r"(a[2]), "r"(a[3]), "r"(b[0]), "r"(b[1]));
}
__device__ __forceinline__ void red2(float* addr, float x, float y) {
    asm volatile("red.global.v2.f32.add [%0], {%1, %2};"
        :: "l"(__cvta_generic_to_global(addr)), "f"(x), "f"(y) : "memory");
}
__device__ __forceinline__ float gelu_f(float x) {
    return 0.5f * x * (1.f + erff(x * 0.70710678118654752f));
}
__device__ __forceinline__ void split2(float a, float b, uint32_t& hi, uint32_t& lo) {
    __half ha = __float2half_rn(a), hb = __float2half_rn(b);
    __half la = __float2half_rn(a - __half2float(ha));
    __half lb = __float2half_rn(b - __half2float(hb));
    __half2 hp; hp.x = ha; hp.y = hb;
    __half2 lp; lp.x = la; lp.y = lb;
    hi = reinterpret_cast<uint32_t&>(hp);
    lo = reinterpret_cast<uint32_t&>(lp);
}
__device__ __forceinline__ uint32_t pack_h2(float a, float b) {
    __half2 hp; hp.x = __float2half_rn(a); hp.y = __float2half_rn(b);
    return reinterpret_cast<uint32_t&>(hp);
}

// ---------------- init ----------------
__global__ void init_kernel(float* gsum, float* hagg, double* bnacc, int N)
{
    int i = blockIdx.x * 256 + threadIdx.x;
    if (i < N * 128) hagg[i] = 0.f;
    if (i < N * 4) gsum[i] = 0.f;
    if (i < 32) bnacc[i] = 0.0;
}

// ---------------- geometry + BN stats ----------------
__global__ __launch_bounds__(256)
void geom_kernel(const int* __restrict__ eidx, const float* __restrict__ hvv,
                 const float* __restrict__ frame, const float* __restrict__ Wvec,
                 float* __restrict__ vff, double* __restrict__ bnacc, int E)
{
    extern __shared__ float sbuf[];   // 256 * 65 floats
    __shared__ float Ws[512];
    __shared__ float bsum[16], bsq[16];
    int tid = threadIdx.x;
    for (int i = tid; i < 512; i += 256) Ws[i] = Wvec[i];
    if (tid < 16) { bsum[tid] = 0.f; bsq[tid] = 0.f; }
    __syncthreads();

    const int e0 = blockIdx.x * 256;
    const int e = e0 + tid;
    float dloc[16];
#pragma unroll
    for (int o = 0; o < 16; o++) dloc[o] = 0.f;

    if (e < E) {
        const int c = eidx[e];
        const int d = eidx[E + e];
        float F[9];
#pragma unroll
        for (int i = 0; i < 9; i++) F[i] = frame[e * 9 + i];

        float vdt[48], vsrc[48];
        {
            const float4* pd = (const float4*)(hvv + (size_t)d * 48);
            const float4* pc = (const float4*)(hvv + (size_t)c * 48);
#pragma unroll
            for (int i = 0; i < 12; i++) {
                ((float4*)vdt)[i]  = pd[i];
                ((float4*)vsrc)[i] = pc[i];
            }
        }
#pragma unroll
        for (int v = 0; v < 16; v++) {
            const float x = vdt[v * 3 + 0], y = vdt[v * 3 + 1], z = vdt[v * 3 + 2];
            vdt[v * 3 + 0] = F[0] * x + F[1] * y + F[2] * z;
            vdt[v * 3 + 1] = F[3] * x + F[4] * y + F[5] * z;
            vdt[v * 3 + 2] = F[6] * x + F[7] * y + F[8] * z;
        }

        float* row = sbuf + tid * 65;
#pragma unroll
        for (int o = 0; o < 16; o++) {
            float v0 = vdt[o * 3 + 0], v1 = vdt[o * 3 + 1], v2 = vdt[o * 3 + 2];
#pragma unroll
            for (int v = 0; v < 16; v++) {
                const float wa = Ws[o * 32 + v], wb = Ws[o * 32 + 16 + v];
                v0 += wa * vdt[v * 3 + 0] + wb * vsrc[v * 3 + 0];
                v1 += wa * vdt[v * 3 + 1] + wb * vsrc[v * 3 + 1];
                v2 += wa * vdt[v * 3 + 2] + wb * vsrc[v * 3 + 2];
            }
            const float dist = sqrtf(v0 * v0 + v1 * v1 + v2 * v2) + 1e-6f;
            const float inv = 1.f / dist;
            row[o * 3 + 0] = v0 * inv;
            row[o * 3 + 1] = v1 * inv;
            row[o * 3 + 2] = v2 * inv;
            row[48 + o] = dist;
            dloc[o] = dist;
        }
    }

#pragma unroll
    for (int o = 0; o < 16; o++) {
        float v = dloc[o], v2 = v * v;
#pragma unroll
        for (int off = 16; off; off >>= 1) {
            v  += __shfl_down_sync(0xffffffffu, v, off);
            v2 += __shfl_down_sync(0xffffffffu, v2, off);
        }
        if ((tid & 31) == 0) { atomicAdd(&bsum[o], v); atomicAdd(&bsq[o], v2); }
    }
    __syncthreads();
    if (tid < 16) {
        atomicAdd(&bnacc[tid], (double)bsum[tid]);
        atomicAdd(&bnacc[16 + tid], (double)bsq[tid]);
    }

    const int nblk = (E - e0 < 256) ? (E - e0) : 256;
    for (int j = tid; j < nblk * 16; j += 256) {
        const int r = j >> 4, q = (j & 15) * 4;
        const float* sr = sbuf + r * 65 + q;
        *(float4*)(vff + (size_t)(e0 + r) * 64 + q) =
            make_float4(sr[0], sr[1], sr[2], sr[3]);
    }
}

__global__ void bn_finalize(const double* __restrict__ acc, const float* __restrict__ g,
                            const float* __restrict__ b, float* __restrict__ st, int E)
{
    int i = threadIdx.x;
    if (i >= 16) return;
    double mean = acc[i] / (double)E;
    double var  = acc[16 + i] / (double)E - mean * mean;
    float s = (float)((double)g[i] / sqrt(var + 1e-5));
    st[i] = s;
    st[16 + i] = b[i] - (float)mean * s;
}

// ---------------- conversion passes ----------------
__global__ void wprep_all(const float* __restrict__ W0, const float* __restrict__ W1,
                          const float* __restrict__ W2, const float* __restrict__ W3,
                          const float* __restrict__ W4, const float* __restrict__ W5,
                          const float* __restrict__ W6, f16* __restrict__ w)
{
    int idx = blockIdx.x * 256 + threadIdx.x;
    if (idx >= W_TOTAL) return;
    const float* src; int K, NT, start;
    if      (idx < OW_B1)  { src = W0; K = 320; NT = 256; start = OW_RED; }
    else if (idx < OW_B2)  { src = W1; K = 384; NT = 128; start = OW_B1; }
    else if (idx < OW_V1)  { src = W2; K = 128; NT = 128; start = OW_B2; }
    else if (idx < OW_V2)  { src = W3; K = 256; NT = 128; start = OW_V1; }
    else if (idx < OW_V3)  { src = W4; K = 128; NT = 128; start = OW_V2; }
    else if (idx < OW_O)   { src = W5; K = 128; NT = 128; start = OW_V3; }
    else                   { src = W6; K = 128; NT = 128; start = OW_O; }
    int local = idx - start;
    int k = local / NT, n = local % NT;
    w[start + (size_t)n * K + k] = __float2half_rn(src[local]);
}

// hVW = hV @ Wb1[0:128,:]  (exact fp32, per-node)
__global__ __launch_bounds__(256)
void hvw_kernel(const float* __restrict__ hV, const float* __restrict__ Wb1,
                float* __restrict__ hVW, int N)
{
    __shared__ float xs[2][128];
    const int t = threadIdx.x;
    const int which = t >> 7, c = t & 127;
    const int node = blockIdx.x * 2 + which;
    if (node < N) xs[which][c] = hV[(size_t)node * 128 + c];
    __syncthreads();
    if (node >= N) return;
    float s = 0.f;
#pragma unroll 8
    for (int k = 0; k < 128; k++) s += xs[which][k] * Wb1[k * 128 + c];
    hVW[(size_t)node * 128 + c] = s;
}

// hagg -> fp16 hi/lo planes with softmax normalization folded in
__global__ void c2planes_norm(const float* __restrict__ x, const float* __restrict__ gsum,
                              f16* __restrict__ hi, f16* __restrict__ lo, int N)
{
    int i = blockIdx.x * 256 + threadIdx.x;
    if (i >= N * 128) return;
    int node = i >> 7, col = i & 127;
    float s = gsum[node * 4 + (col >> 5)];
    float v = x[i] / (s > 0.f ? s : 1.f);
    f16 h = __float2half_rn(v);
    hi[i] = h;
    lo[i] = __float2half_rn(v - __half2float(h));
}

// ================= GEMM building blocks (512 threads, 16 warps = 4m x 4n) =================
// DUAL=true: A = hi+lo planes (2 products); DUAL=false: A = hi plane only (1 product).
template<int NT, bool DUAL>
__device__ __forceinline__ void mma_half512(
    float (&acc)[2][NT][4], uint32_t aHi, uint32_t aLo, uint32_t bB, int ks0, int tid)
{
    const int wid = tid >> 5, lane = tid & 31;
    const int wm = wid >> 2, wn = wid & 3;
    const int a_row = wm * 32 + (lane & 7) + ((lane & 8) ? 8 : 0);
    const int a_ub  = (lane & 16) ? 1 : 0;
    const int b_row0 = wn * (NT * 8) + (lane & 7) + ((lane & 16) ? 8 : 0);
    const int b_ub  = (lane & 8) ? 1 : 0;
#pragma unroll
    for (int kss = 0; kss < 2; kss++) {
        const int ks = ks0 + kss;
        uint32_t ahi[2][4], alo[2][4];
#pragma unroll
        for (int mt = 0; mt < 2; mt++) {
            const int r = a_row + mt * 16;
            const int u = ks * 2 + a_ub;
            const uint32_t off = r * 128 + (uint32_t)(((u ^ (r & 7))) << 4);
            ldsm4(ahi[mt], aHi + off);
            if (DUAL) ldsm4(alo[mt], aLo + off);
        }
        uint32_t bb[NT / 2][4];
#pragma unroll
        for (int g = 0; g < NT / 2; g++) {
            const int n = b_row0 + g * 16;
            const int u = ks * 2 + b_ub;
            const uint32_t off = n * 128 + (uint32_t)(((u ^ (n & 7))) << 4);
            ldsm4(bb[g], bB + off);
        }
#pragma unroll
        for (int mt = 0; mt < 2; mt++)
#pragma unroll
            for (int ntl = 0; ntl < NT; ntl++) {
                float* a_ = acc[mt][ntl];
                const uint32_t* bp = &bb[ntl >> 1][(ntl & 1) * 2];
                mmaf16(a_, ahi[mt], bp);
                if (DUAL) mmaf16(a_, alo[mt], bp);
            }
    }
}

template<int NT, bool DUAL>
__device__ __forceinline__ void mma_chunk(
    float (&acc)[2][NT][4], uint32_t aHi, uint32_t aLo, uint32_t bB, int tid)
{
    mma_half512<NT, DUAL>(acc, aHi, aLo, bB, 0, tid);
    mma_half512<NT, DUAL>(acc, aHi, aLo, bB, 2, tid);
}

__device__ __forceinline__ void stage_w(uint32_t dst, const f16* __restrict__ W,
                                        int K, int k0, int rows, int tid)
{
    for (int i = tid; i < rows * 8; i += 512) {
        const int r = i >> 3, u = i & 7;
        const uint32_t d = r * 128 + (uint32_t)(((u ^ (r & 7))) << 4);
        cp16(dst + d, (const char*)(W + (size_t)r * K + k0) + u * 16);
    }
    CP_COMMIT();
}
__device__ __forceinline__ void stage_w2(uint32_t dst, const f16* __restrict__ W,
                                         int K, int k0, int tid)
{
    for (int i = tid; i < 2048; i += 512) {
        const int ch = i >> 10, rem = i & 1023;
        const int r = rem >> 3, u = rem & 7;
        const uint32_t d = ch * 16384 + r * 128 + (uint32_t)(((u ^ (r & 7))) << 4);
        cp16(dst + d, (const char*)(W + (size_t)r * K + k0 + ch * 64) + u * 16);
    }
    CP_COMMIT();
}

// store fragments -> smem fp16 planes (chunked layout), bias+activation.
// WLO=true also writes the lo plane at baseLo.
template<int NT, int ACT, bool WLO>
__device__ __forceinline__ void store_planes512(const float (&acc)[2][NT][4],
                                                char* smemp, uint32_t baseHi, uint32_t baseLo,
                                                const float* __restrict__ bias, int tid)
{
    const int wid = tid >> 5, lane = tid & 31;
    const int wm = wid >> 2, wn = wid & 3;
#pragma unroll
    for (int mt = 0; mt < 2; mt++)
#pragma unroll
        for (int nt = 0; nt < NT; nt++) {
            const int c = wn * (NT * 8) + nt * 8 + (lane & 3) * 2;
            const int kc = c >> 6, kk = c & 63, u = kk >> 3;
            const float b0 = bias ? bias[c] : 0.f;
            const float b1 = bias ? bias[c + 1] : 0.f;
#pragma unroll
            for (int half = 0; half < 2; half++) {
                const int r = wm * 32 + mt * 16 + (lane >> 2) + half * 8;
                float e0 = acc[mt][nt][half * 2] + b0;
                float e1 = acc[mt][nt][half * 2 + 1] + b1;
                if (ACT == 1) { e0 = fmaxf(e0, 0.f); e1 = fmaxf(e1, 0.f); }
                if (ACT == 2) { e0 = gelu_f(e0); e1 = gelu_f(e1); }
                const uint32_t ad = kc * 16384 + r * 128 +
                                    (uint32_t)(((u ^ (r & 7))) << 4) + (kk & 7) * 2;
                if (WLO) {
                    uint32_t hp, lp;
                    split2(e0, e1, hp, lp);
                    *(uint32_t*)(smemp + baseHi + ad) = hp;
                    *(uint32_t*)(smemp + baseLo + ad) = lp;
                } else {
                    *(uint32_t*)(smemp + baseHi + ad) = pack_h2(e0, e1);
                }
            }
        }
}

// ---------------- MEGA kernel (512 threads) ----------------
// smem: [0,64K) heHi, [64K,128K) heLo, [128K,192K) xv, [192K,224K) stg, [224K..) att,cen
__global__ __launch_bounds__(512, 1)
void mega_kernel(const float* __restrict__ Vff, const float* __restrict__ HE,
                 const float* __restrict__ bn_st,
                 const float* __restrict__ hVW,
                 const int* __restrict__ eidx,
                 const f16* __restrict__ wred,
                 const f16* __restrict__ wb1, const float* __restrict__ bb1,
                 const f16* __restrict__ wb2, const float* __restrict__ bb2,
                 const float* __restrict__ Wb3, const float* __restrict__ bb3,
                 const f16* __restrict__ wv1, const float* __restrict__ bv1,
                 const f16* __restrict__ wv2, const float* __restrict__ bv2,
                 const f16* __restrict__ wv3, const float* __restrict__ bv3,
                 float* __restrict__ gsum, float* __restrict__ hagg, int M)
{
    extern __shared__ char smem[];
    const uint32_t sb = smem_u32(smem);
    const uint32_t heHi = sb;
    const uint32_t heLo = sb + 65536;
    const uint32_t xv   = sb + 131072;
    const uint32_t stg  = sb + 196608;
    const int tid = threadIdx.x;
    const int wid = tid >> 5, lane = tid & 31;
    const int row0 = blockIdx.x * 128;

    const int lr = tid >> 2;
    const int arow = (row0 + lr < M) ? (row0 + lr) : (M - 1);
    const int cu0 = (tid & 3) * 4;

    {
        int* cens = (int*)(smem + CEN_OFF);
        if (tid < 128) {
            int er = row0 + tid;
            cens[tid] = eidx[er < M ? er : M - 1];
        }
    }

    // ================= P0: hE = [vff_bn | h_E] @ W_red (K=320, N=256), SINGLE product =================
    // A: fp32 regs -> fp16 hi plane at xv[0,16K); B: full-chunk ping-pong xv+32K / stg
    {
        float acc0[2][8][4];
#pragma unroll
        for (int i = 0; i < 2; i++)
#pragma unroll
            for (int j = 0; j < 8; j++)
#pragma unroll
                for (int q = 0; q < 4; q++) acc0[i][j][q] = 0.f;

        float4 areg[4];
        {
            const float4* pa = (const float4*)(Vff + (size_t)arow * 64);
#pragma unroll
            for (int jj = 0; jj < 4; jj++) areg[jj] = pa[cu0 + jj];
        }
        stage_w(xv + 32768, wred, 320, 0, 256, tid);   // B0 -> buf0

        for (int kc = 0; kc < 5; kc++) {
            {
                float4 f[4];
#pragma unroll
                for (int jj = 0; jj < 4; jj++) f[jj] = areg[jj];
                if (kc == 0 && cu0 >= 12) {
#pragma unroll
                    for (int jj = 0; jj < 4; jj++) {
                        const int u = cu0 + jj;
                        if (u >= 12) {
                            const int col = u * 4;
                            f[jj].x = fmaf(f[jj].x, bn_st[col - 48], bn_st[col - 32]);
                            f[jj].y = fmaf(f[jj].y, bn_st[col - 47], bn_st[col - 31]);
                            f[jj].z = fmaf(f[jj].z, bn_st[col - 46], bn_st[col - 30]);
                            f[jj].w = fmaf(f[jj].w, bn_st[col - 45], bn_st[col - 29]);
                        }
                    }
                }
#pragma unroll
                for (int jj = 0; jj < 2; jj++) {
                    uint32_t ph[4];
                    ph[0] = pack_h2(f[2*jj].x,   f[2*jj].y);
                    ph[1] = pack_h2(f[2*jj].z,   f[2*jj].w);
                    ph[2] = pack_h2(f[2*jj+1].x, f[2*jj+1].y);
                    ph[3] = pack_h2(f[2*jj+1].z, f[2*jj+1].w);
                    const int un = (cu0 >> 1) + jj;
                    const uint32_t ad = lr * 128 + (uint32_t)(((un ^ (lr & 7))) << 4);
                    *(uint4*)(smem + 131072 + ad) = make_uint4(ph[0], ph[1], ph[2], ph[3]);
                }
            }
            if (kc < 4) {
                const float4* pa = (const float4*)(HE + (size_t)arow * 256 + kc * 64);
#pragma unroll
                for (int jj = 0; jj < 4; jj++) areg[jj] = pa[cu0 + jj];
                stage_w(((kc + 1) & 1) ? stg : (xv + 32768), wred, 320, (kc + 1) * 64, 256, tid);
                CP_WAIT(1);
            } else {
                CP_WAIT(0);
            }
            __syncthreads();
            mma_chunk<8, false>(acc0, xv, 0, (kc & 1) ? stg : (xv + 32768), tid);
            __syncthreads();
        }

        // prestage Wb1 c0,c1 -> stg, overlapped with hE epilogue (hE keeps hi+lo: P1/P2 are DUAL)
        stage_w2(stg, wb1, 384, 128, tid);
        store_planes512<8, 0, true>(acc0, smem, 0, 65536, nullptr, tid);
    }
    CP_WAIT(0);
    __syncthreads();

    // ================= P1: x1 = relu(hVW[center] + hE @ Wb1_bot + bb1), K=256, DUAL =================
    float acc1[2][4][4];
#pragma unroll
    for (int i = 0; i < 2; i++)
#pragma unroll
        for (int j = 0; j < 4; j++)
#pragma unroll
            for (int q = 0; q < 4; q++) acc1[i][j][q] = 0.f;
    {
        stage_w2(xv, wb1, 384, 256, tid);               // c2,c3 -> xv[0,32K)
        mma_chunk<4, true>(acc1, heHi,         heLo,         stg,         tid);
        mma_chunk<4, true>(acc1, heHi + 16384, heLo + 16384, stg + 16384, tid);
        CP_WAIT(0);
        __syncthreads();
        mma_chunk<4, true>(acc1, heHi + 32768, heLo + 32768, xv,         tid);
        mma_chunk<4, true>(acc1, heHi + 49152, heLo + 49152, xv + 16384, tid);
        __syncthreads();

        stage_w2(stg, wb2, 128, 0, tid);                // Wb2 c0,c1 -> stg

        // epilogue: fused global hVW read + bias + relu -> x1 hi/lo planes in xv
        const int* cens = (const int*)(smem + CEN_OFF);
        const int wm = wid >> 2, wn = wid & 3;
#pragma unroll
        for (int mt = 0; mt < 2; mt++)
#pragma unroll
            for (int nt = 0; nt < 4; nt++) {
                const int c = wn * 32 + nt * 8 + (lane & 3) * 2;
                const int kc = c >> 6, kk = c & 63, u = kk >> 3;
                const float b0 = bb1[c], b1 = bb1[c + 1];
#pragma unroll
                for (int half = 0; half < 2; half++) {
                    const int r = wm * 32 + mt * 16 + (lane >> 2) + half * 8;
                    const float2 hv = *(const float2*)(hVW + (size_t)cens[r] * 128 + c);
                    float e0 = fmaxf(acc1[mt][nt][half * 2] + b0 + hv.x, 0.f);
                    float e1 = fmaxf(acc1[mt][nt][half * 2 + 1] + b1 + hv.y, 0.f);
                    uint32_t hp, lp;
                    split2(e0, e1, hp, lp);
                    const uint32_t ad = kc * 16384 + r * 128 +
                                        (uint32_t)(((u ^ (r & 7))) << 4) + (kk & 7) * 2;
                    *(uint32_t*)(smem + 131072 + ad) = hp;
                    *(uint32_t*)(smem + 131072 + 32768 + ad) = lp;
                }
            }
    }
    CP_WAIT(0);
    __syncthreads();

    // ================= P2: x2 = relu(x1 @ Wb2 + bb2), DUAL =================
    float acc2[2][4][4];
#pragma unroll
    for (int i = 0; i < 2; i++)
#pragma unroll
        for (int j = 0; j < 4; j++)
#pragma unroll
            for (int q = 0; q < 4; q++) acc2[i][j][q] = 0.f;
    mma_chunk<4, true>(acc2, xv,         xv + 32768, stg,         tid);
    mma_chunk<4, true>(acc2, xv + 16384, xv + 49152, stg + 16384, tid);
    __syncthreads();
    stage_w2(stg, wv1, 256, 0, tid);                    // Wv1 c0,c1 -> stg
    // x2 fp32 -> xv (x1 dead)
    {
        const int wm = wid >> 2, wn = wid & 3;
#pragma unroll
        for (int mt = 0; mt < 2; mt++)
#pragma unroll
            for (int nt = 0; nt < 4; nt++) {
                const int c = wn * 32 + nt * 8 + (lane & 3) * 2;
                const float b0 = bb2[c], b1 = bb2[c + 1];
#pragma unroll
                for (int half = 0; half < 2; half++) {
                    const int r = wm * 32 + mt * 16 + (lane >> 2) + half * 8;
                    float e0 = fmaxf(acc2[mt][nt][half * 2] + b0, 0.f);
                    float e1 = fmaxf(acc2[mt][nt][half * 2 + 1] + b1, 0.f);
                    *(float2*)(smem + 131072 + ((size_t)r * 128 + c) * 4) = make_float2(e0, e1);
                }
            }
    }
    __syncthreads();

    // ================= P3: e = exp(logits), segment sum (Wb3 from L2) =================
    {
        const float* x2s = (const float*)(smem + 131072);
        float* atts = (float*)(smem + ATT_OFF);
        const int* cens = (const int*)(smem + CEN_OFF);
        for (int rr = wid * 8; rr < wid * 8 + 8; rr++) {
            const int e = row0 + rr;
            if (e >= M) break;
            float p0 = 0.f, p1 = 0.f, p2 = 0.f, p3 = 0.f;
#pragma unroll
            for (int j = 0; j < 4; j++) {
                const int c = lane + j * 32;
                const float x = x2s[rr * 128 + c];
                const float4 w4 = *(const float4*)(Wb3 + c * 8);
                p0 += x * w4.x;
                p1 += x * w4.y;
                p2 += x * w4.z;
                p3 += x * w4.w;
            }
#pragma unroll
            for (int off = 16; off; off >>= 1) {
                p0 += __shfl_xor_sync(0xffffffffu, p0, off);
                p1 += __shfl_xor_sync(0xffffffffu, p1, off);
                p2 += __shfl_xor_sync(0xffffffffu, p2, off);
                p3 += __shfl_xor_sync(0xffffffffu, p3, off);
            }
            if (lane < 4) {
                const float p = (lane == 0) ? p0 : (lane == 1) ? p1 : (lane == 2) ? p2 : p3;
                const float l = (p + bb3[lane]) * 0.17677669529663687f;
                const float ex = expf(l);
                atts[rr * 4 + lane] = ex;
                atomicAdd(&gsum[cens[rr] * 4 + lane], ex);
            }
        }
    }
    __syncthreads();

    // ================= P4: v1 = gelu(hE @ Wv1 + bv1), SINGLE product =================
    float acc3[2][4][4];
#pragma unroll
    for (int i = 0; i < 2; i++)
#pragma unroll
        for (int j = 0; j < 4; j++)
#pragma unroll
            for (int q = 0; q < 4; q++) acc3[i][j][q] = 0.f;
    stage_w2(xv, wv1, 256, 128, tid);                   // c2,c3 -> xv (x2 dead after P3)
    CP_WAIT(1);                                         // Wv1 c0,c1 ready (c2,c3 pending)
    __syncthreads();
    mma_chunk<4, false>(acc3, heHi,         0, stg,         tid);
    mma_chunk<4, false>(acc3, heHi + 16384, 0, stg + 16384, tid);
    CP_WAIT(0);
    __syncthreads();
    mma_chunk<4, false>(acc3, heHi + 32768, 0, xv,         tid);
    mma_chunk<4, false>(acc3, heHi + 49152, 0, xv + 16384, tid);
    __syncthreads();
    stage_w2(stg, wv2, 128, 0, tid);                    // Wv2 -> stg
    store_planes512<4, 2, false>(acc3, smem, 131072, 0, bv1, tid);   // v1 hi-only -> xv
    CP_WAIT(0);
    __syncthreads();

    // ================= P5: v2 = gelu(v1 @ Wv2 + bv2), SINGLE product =================
    float acc4[2][4][4];
#pragma unroll
    for (int i = 0; i < 2; i++)
#pragma unroll
        for (int j = 0; j < 4; j++)
#pragma unroll
            for (int q = 0; q < 4; q++) acc4[i][j][q] = 0.f;
    mma_chunk<4, false>(acc4, xv,         0, stg,         tid);
    mma_chunk<4, false>(acc4, xv + 16384, 0, stg + 16384, tid);
    __syncthreads();
    stage_w2(heLo, wv3, 128, 0, tid);                   // Wv3 -> heLo (hE lo dead)
    store_planes512<4, 2, false>(acc4, smem, 0, 0, bv2, tid);  // v2 hi-only -> heHi region
    CP_WAIT(0);
    __syncthreads();

    // ================= P6: V = v2 @ Wv3 + bv3; hagg[center] += e * V, SINGLE product =================
    float acc5[2][4][4];
#pragma unroll
    for (int i = 0; i < 2; i++)
#pragma unroll
        for (int j = 0; j < 4; j++)
#pragma unroll
            for (int q = 0; q < 4; q++) acc5[i][j][q] = 0.f;
    mma_chunk<4, false>(acc5, heHi,         0, heLo,         tid);
    mma_chunk<4, false>(acc5, heHi + 16384, 0, heLo + 16384, tid);
    {
        const float* atts = (const float*)(smem + ATT_OFF);
        const int* cens = (const int*)(smem + CEN_OFF);
        const int wm = wid >> 2, wn = wid & 3;
#pragma unroll
        for (int mt = 0; mt < 2; mt++) {
#pragma unroll
            for (int nt = 0; nt < 4; nt++) {
                const int c = wn * 32 + nt * 8 + (lane & 3) * 2;
                const int h = c >> 5;
                const float b0 = bv3[c], b1 = bv3[c + 1];
#pragma unroll
                for (int half = 0; half < 2; half++) {
                    const int rl = wm * 32 + mt * 16 + (lane >> 2) + half * 8;
                    if (row0 + rl < M) {
                        const float a = atts[rl * 4 + h];
                        float* dst = hagg + (size_t)cens[rl] * 128 + c;
                        red2(dst, (acc5[mt][nt][half * 2] + b0) * a,
                                  (acc5[mt][nt][half * 2 + 1] + b1) * a);
                    }
                }
            }
        }
    }
}

// ---------------- standalone GEMM (W_O), 256 threads, DUAL fp16x2 ----------------
__global__ __launch_bounds__(256, 1)
void hmma_gemm_o(const f16* __restrict__ Ahi, const f16* __restrict__ Alo,
                 const f16* __restrict__ B, float* __restrict__ Cf, int M)
{
    extern __shared__ char smem[];
    const uint32_t sb = smem_u32(smem);
    const int tid = threadIdx.x;
    const int wid = tid >> 5, lane = tid & 31;
    const int row0 = blockIdx.x * 128;

    const int lr = tid >> 1;
    const int arow = (row0 + lr < M) ? (row0 + lr) : (M - 1);

    float acc[2][8][4];
#pragma unroll
    for (int i = 0; i < 2; i++)
#pragma unroll
        for (int j = 0; j < 8; j++)
#pragma unroll
            for (int q = 0; q < 4; q++) acc[i][j][q] = 0.f;

    const int wm = wid >> 1, wn = wid & 1;
    const int a_row = wm * 32 + (lane & 7) + ((lane & 8) ? 8 : 0);
    const int a_ub  = (lane & 16) ? 1 : 0;
    const int b_row0 = wn * 64 + (lane & 7) + ((lane & 16) ? 8 : 0);
    const int b_ub  = (lane & 8) ? 1 : 0;

    for (int kc = 0; kc < 2; kc++) {
        const int k0 = kc * 64;
#pragma unroll
        for (int i = 0; i < 4; i++) {
            const int u = (tid & 1) * 4 + i;
            const uint32_t d = lr * 128 + (uint32_t)(((u ^ (lr & 7))) << 4);
            cp16(sb + d,         (const char*)(Ahi + (size_t)arow * 128 + k0) + u * 16);
            cp16(sb + 16384 + d, (const char*)(Alo + (size_t)arow * 128 + k0) + u * 16);
        }
        for (int i = tid; i < 128 * 8; i += 256) {
            const int r = i >> 3, u = i & 7;
            const uint32_t d = r * 128 + (uint32_t)(((u ^ (r & 7))) << 4);
            cp16(sb + 32768 + d, (const char*)(B + (size_t)r * 128 + k0) + u * 16);
        }
        CP_COMMIT();
        CP_WAIT(0);
        __syncthreads();
#pragma unroll
        for (int ks = 0; ks < 4; ks++) {
            uint32_t ahi[2][4], alo[2][4];
#pragma unroll
            for (int mt = 0; mt < 2; mt++) {
                const int r = a_row + mt * 16;
                const int u = ks * 2 + a_ub;
                const uint32_t off = r * 128 + (uint32_t)(((u ^ (r & 7))) << 4);
                ldsm4(ahi[mt], sb + off);
                ldsm4(alo[mt], sb + 16384 + off);
            }
            uint32_t bb[4][4];
#pragma unroll
            for (int g = 0; g < 4; g++) {
                const int n = b_row0 + g * 16;
                const int u = ks * 2 + b_ub;
                const uint32_t off = n * 128 + (uint32_t)(((u ^ (n & 7))) << 4);
                ldsm4(bb[g], sb + 32768 + off);
            }
#pragma unroll
            for (int mt = 0; mt < 2; mt++)
#pragma unroll
                for (int ntl = 0; ntl < 8; ntl++) {
                    float* a_ = acc[mt][ntl];
                    const uint32_t* bp = &bb[ntl >> 1][(ntl & 1) * 2];
                    mmaf16(a_, ahi[mt], bp);
                    mmaf16(a_, alo[mt], bp);
                }
        }
        __syncthreads();
    }

#pragma unroll
    for (int mt = 0; mt < 2; mt++) {
        const int r = row0 + wm * 32 + mt * 16 + (lane >> 2);
#pragma unroll
        for (int nt = 0; nt < 8; nt++) {
            const int c = wn * 64 + nt * 8 + (lane & 3) * 2;
#pragma unroll
            for (int half = 0; half < 2; half++) {
                const int rr = r + half * 8;
                if (rr >= M) continue;
                *(float2*)(Cf + (size_t)rr * 128 + c) =
                    make_float2(acc[mt][nt][half * 2], acc[mt][nt][half * 2 + 1]);
            }
        }
    }
}

// ---------------- host launch ----------------
extern "C" void kernel_launch(void* const* d_in, const int* in_sizes, int n_in,
                              void* d_out, int out_size)
{
    const float* h_V   = (const float*)d_in[0];
    const float* h_E   = (const float*)d_in[1];
    const int*   eidx  = (const int*)  d_in[2];
    const float* hvv   = (const float*)d_in[3];
    const float* frame = (const float*)d_in[4];
    const float* W_vec = (const float*)d_in[5];
    const float* W_red = (const float*)d_in[6];
    const float* Wb1   = (const float*)d_in[7];
    const float* bb1   = (const float*)d_in[8];
    const float* Wb2   = (const float*)d_in[9];
    const float* bb2   = (const float*)d_in[10];
    const float* Wb3   = (const float*)d_in[11];
    const float* bb3   = (const float*)d_in[12];
    const float* Wv1   = (const float*)d_in[13];
    const float* bv1   = (const float*)d_in[14];
    const float* Wv2   = (const float*)d_in[15];
    const float* bv2   = (const float*)d_in[16];
    const float* Wv3   = (const float*)d_in[17];
    const float* bv3   = (const float*)d_in[18];
    const float* W_O   = (const float*)d_in[19];
    const float* bn_g  = (const float*)d_in[20];
    const float* bn_b  = (const float*)d_in[21];

    int E = in_sizes[2] / 2;
    int N = in_sizes[0] / 128;
    float* out = (float*)d_out;

    float *vff, *hVW, *gsum, *hagg, *bnst;
    f16 *hgh, *hgl, *w;
    double* bnacc;
    cudaGetSymbolAddress((void**)&vff,   g_vff);
    cudaGetSymbolAddress((void**)&hVW,   g_hVW);
    cudaGetSymbolAddress((void**)&hgh,   g_hgh);
    cudaGetSymbolAddress((void**)&hgl,   g_hgl);
    cudaGetSymbolAddress((void**)&w,     g_w);
    cudaGetSymbolAddress((void**)&gsum,  g_sum);
    cudaGetSymbolAddress((void**)&hagg,  g_hagg);
    cudaGetSymbolAddress((void**)&bnacc, g_bnacc);
    cudaGetSymbolAddress((void**)&bnst,  g_bnst);

    const int SMEM_O = 49152;
    const int SMEM_G = 256 * 65 * 4;   // 66560
    cudaFuncSetAttribute(mega_kernel, cudaFuncAttributeMaxDynamicSharedMemorySize, SMEM_MEGA);
    cudaFuncSetAttribute(hmma_gemm_o, cudaFuncAttributeMaxDynamicSharedMemorySize, SMEM_O);
    cudaFuncSetAttribute(geom_kernel, cudaFuncAttributeMaxDynamicSharedMemorySize, SMEM_G);

    int Mt = (E + 127) / 128;
    int Mo = (N + 127) / 128;

    init_kernel<<<(N * 128 + 255) / 256, 256>>>(gsum, hagg, bnacc, N);
    geom_kernel<<<(E + 255) / 256, 256, SMEM_G>>>(eidx, hvv, frame, W_vec, vff, bnacc, E);
    bn_finalize<<<1, 32>>>(bnacc, bn_g, bn_b, bnst, E);

    wprep_all<<<(W_TOTAL + 255) / 256, 256>>>(W_red, Wb1, Wb2, Wv1, Wv2, Wv3, W_O, w);
    hvw_kernel<<<(N + 1) / 2, 256>>>(h_V, Wb1, hVW, N);

    mega_kernel<<<Mt, 512, SMEM_MEGA>>>(
        vff, h_E, bnst, hVW, eidx,
        w + OW_RED,
        w + OW_B1, bb1,
        w + OW_B2, bb2,
        Wb3, bb3,
        w + OW_V1, bv1,
        w + OW_V2, bv2,
        w + OW_V3, bv3,
        gsum, hagg, E);

    c2planes_norm<<<(N * 128 + 255) / 256, 256>>>(hagg, gsum, hgh, hgl, N);
    hmma_gemm_o<<<Mo, 256, SMEM_O>>>(hgh, hgl, w + OW_O, out, N);
}

// round 16
// speedup vs baseline: 1.8944x; 1.0771x over previous
#include <cuda_runtime.h>
#include <cuda_fp16.h>
#include <math.h>
#include <stdint.h>

#define E_CONST 320000
#define N_CONST 10000
typedef __half f16;

// ---------------- scratch (no allocations allowed) ----------------
static __device__ float    g_vff [(size_t)E_CONST * 64];   // fp32 [sincos48|dist16]
static __device__ float    g_hVW [N_CONST * 128];          // hV @ Wb1_top (fp32, per node)
static __device__ f16      g_hgh [N_CONST * 128];
static __device__ f16      g_hgl [N_CONST * 128];
static __device__ f16      g_w   [262144];                 // all weights, single fp16 plane, [n][k]
static __device__ float    g_sum [N_CONST * 4];
static __device__ float    g_hagg[N_CONST * 128];
static __device__ double   g_bnacc[32];
static __device__ float    g_bnst[32];

// weight plane offsets (elements)
#define OW_RED 0        // 256 x 320
#define OW_B1  81920    // 128 x 384
#define OW_B2  131072   // 128 x 128
#define OW_V1  147456   // 128 x 256
#define OW_V2  180224   // 128 x 128
#define OW_V3  196608   // 128 x 128
#define OW_O   212992   // 128 x 128
#define W_TOTAL 229376

// mega smem tail (beyond the 224KB working set)
#define ATT_OFF 229376
#define CEN_OFF 231424
#define SMEM_MEGA 231936

// ---------------- helpers ----------------
__device__ __forceinline__ uint32_t smem_u32(const void* p) {
    uint32_t a;
    asm("{ .reg .u64 t; cvta.to.shared.u64 t, %1; cvt.u32.u64 %0, t; }" : "=r"(a) : "l"(p));
    return a;
}
__device__ __forceinline__ void cp16(uint32_t dst, const void* src) {
    asm volatile("cp.async.cg.shared.global [%0], [%1], 16;"
        :: "r"(dst), "l"(__cvta_generic_to_global(src)) : "memory");
}
#define CP_COMMIT() asm volatile("cp.async.commit_group;" ::: "memory")
#define CP_WAIT(n)  asm volatile("cp.async.wait_group %0;" :: "n"(n) : "memory")

__device__ __forceinline__ void ldsm4(uint32_t* r, uint32_t addr) {
    asm volatile("ldmatrix.sync.aligned.m8n8.x4.shared.b16 {%0,%1,%2,%3}, [%4];"
        : "=r"(r[0]), "=r"(r[1]), "=r"(r[2]), "=r"(r[3]) : "r"(addr));
}
__device__ __forceinline__ void mmaf16(float* d, const uint32_t* a, const uint32_t* b) {
    asm volatile(
        "mma.sync.aligned.m16n8k16.row.col.f32.f16.f16.f32 "
        "{%0,%1,%2,%3}, {%4,%5,%6,%7}, {%8,%9}, {%0,%1,%2,%3};"
        : "+f"(d[0]), "+f"(d[1]), "+f"(d[2]), "+f"(d[3])
        : "r"(a[0]), "r"(a[1]), "r"(a[2]), "r"(a[3]), "r"(b[0]), "r"(b[1]));
}
__device__ __forceinline__ void red2(float* addr, float x, float y) {
    asm volatile("red.global.v2.f32.add [%0], {%1, %2};"
        :: "l"(__cvta_generic_to_global(addr)), "f"(x), "f"(y) : "memory");
}
__device__ __forceinline__ float gelu_f(float x) {
    return 0.5f * x * (1.f + erff(x * 0.70710678118654752f));
}
__device__ __forceinline__ void split2(float a, float b, uint32_t& hi, uint32_t& lo) {
    __half ha = __float2half_rn(a), hb = __float2half_rn(b);
    __half la = __float2half_rn(a - __half2float(ha));
    __half lb = __float2half_rn(b - __half2float(hb));
    __half2 hp; hp.x = ha; hp.y = hb;
    __half2 lp; lp.x = la; lp.y = lb;
    hi = reinterpret_cast<uint32_t&>(hp);
    lo = reinterpret_cast<uint32_t&>(lp);
}
__device__ __forceinline__ uint32_t pack_h2(float a, float b) {
    __half2 hp; hp.x = __float2half_rn(a); hp.y = __float2half_rn(b);
    return reinterpret_cast<uint32_t&>(hp);
}

// ---------------- init ----------------
__global__ void init_kernel(float* gsum, float* hagg, double* bnacc, int N)
{
    int i = blockIdx.x * 256 + threadIdx.x;
    if (i < N * 128) hagg[i] = 0.f;
    if (i < N * 4) gsum[i] = 0.f;
    if (i < 32) bnacc[i] = 0.0;
}

// ---------------- geometry + BN stats ----------------
__global__ __launch_bounds__(256)
void geom_kernel(const int* __restrict__ eidx, const float* __restrict__ hvv,
                 const float* __restrict__ frame, const float* __restrict__ Wvec,
                 float* __restrict__ vff, double* __restrict__ bnacc, int E)
{
    extern __shared__ float sbuf[];   // 256 * 65 floats
    __shared__ float Ws[512];
    __shared__ float bsum[16], bsq[16];
    int tid = threadIdx.x;
    for (int i = tid; i < 512; i += 256) Ws[i] = Wvec[i];
    if (tid < 16) { bsum[tid] = 0.f; bsq[tid] = 0.f; }
    __syncthreads();

    const int e0 = blockIdx.x * 256;
    const int e = e0 + tid;
    float dloc[16];
#pragma unroll
    for (int o = 0; o < 16; o++) dloc[o] = 0.f;

    if (e < E) {
        const int c = eidx[e];
        const int d = eidx[E + e];
        float F[9];
#pragma unroll
        for (int i = 0; i < 9; i++) F[i] = frame[e * 9 + i];

        float vdt[48], vsrc[48];
        {
            const float4* pd = (const float4*)(hvv + (size_t)d * 48);
            const float4* pc = (const float4*)(hvv + (size_t)c * 48);
#pragma unroll
            for (int i = 0; i < 12; i++) {
                ((float4*)vdt)[i]  = pd[i];
                ((float4*)vsrc)[i] = pc[i];
            }
        }
#pragma unroll
        for (int v = 0; v < 16; v++) {
            const float x = vdt[v * 3 + 0], y = vdt[v * 3 + 1], z = vdt[v * 3 + 2];
            vdt[v * 3 + 0] = F[0] * x + F[1] * y + F[2] * z;
            vdt[v * 3 + 1] = F[3] * x + F[4] * y + F[5] * z;
            vdt[v * 3 + 2] = F[6] * x + F[7] * y + F[8] * z;
        }

        float* row = sbuf + tid * 65;
#pragma unroll
        for (int o = 0; o < 16; o++) {
            float v0 = vdt[o * 3 + 0], v1 = vdt[o * 3 + 1], v2 = vdt[o * 3 + 2];
#pragma unroll
            for (int v = 0; v < 16; v++) {
                const float wa = Ws[o * 32 + v], wb = Ws[o * 32 + 16 + v];
                v0 += wa * vdt[v * 3 + 0] + wb * vsrc[v * 3 + 0];
                v1 += wa * vdt[v * 3 + 1] + wb * vsrc[v * 3 + 1];
                v2 += wa * vdt[v * 3 + 2] + wb * vsrc[v * 3 + 2];
            }
            const float dist = sqrtf(v0 * v0 + v1 * v1 + v2 * v2) + 1e-6f;
            const float inv = 1.f / dist;
            row[o * 3 + 0] = v0 * inv;
            row[o * 3 + 1] = v1 * inv;
            row[o * 3 + 2] = v2 * inv;
            row[48 + o] = dist;
            dloc[o] = dist;
        }
    }

#pragma unroll
    for (int o = 0; o < 16; o++) {
        float v = dloc[o], v2 = v * v;
#pragma unroll
        for (int off = 16; off; off >>= 1) {
            v  += __shfl_down_sync(0xffffffffu, v, off);
            v2 += __shfl_down_sync(0xffffffffu, v2, off);
        }
        if ((tid & 31) == 0) { atomicAdd(&bsum[o], v); atomicAdd(&bsq[o], v2); }
    }
    __syncthreads();
    if (tid < 16) {
        atomicAdd(&bnacc[tid], (double)bsum[tid]);
        atomicAdd(&bnacc[16 + tid], (double)bsq[tid]);
    }

    const int nblk = (E - e0 < 256) ? (E - e0) : 256;
    for (int j = tid; j < nblk * 16; j += 256) {
        const int r = j >> 4, q = (j & 15) * 4;
        const float* sr = sbuf + r * 65 + q;
        *(float4*)(vff + (size_t)(e0 + r) * 64 + q) =
            make_float4(sr[0], sr[1], sr[2], sr[3]);
    }
}

__global__ void bn_finalize(const double* __restrict__ acc, const float* __restrict__ g,
                            const float* __restrict__ b, float* __restrict__ st, int E)
{
    int i = threadIdx.x;
    if (i >= 16) return;
    double mean = acc[i] / (double)E;
    double var  = acc[16 + i] / (double)E - mean * mean;
    float s = (float)((double)g[i] / sqrt(var + 1e-5));
    st[i] = s;
    st[16 + i] = b[i] - (float)mean * s;
}

// ---------------- conversion passes ----------------
__global__ void wprep_all(const float* __restrict__ W0, const float* __restrict__ W1,
                          const float* __restrict__ W2, const float* __restrict__ W3,
                          const float* __restrict__ W4, const float* __restrict__ W5,
                          const float* __restrict__ W6, f16* __restrict__ w)
{
    int idx = blockIdx.x * 256 + threadIdx.x;
    if (idx >= W_TOTAL) return;
    const float* src; int K, NT, start;
    if      (idx < OW_B1)  { src = W0; K = 320; NT = 256; start = OW_RED; }
    else if (idx < OW_B2)  { src = W1; K = 384; NT = 128; start = OW_B1; }
    else if (idx < OW_V1)  { src = W2; K = 128; NT = 128; start = OW_B2; }
    else if (idx < OW_V2)  { src = W3; K = 256; NT = 128; start = OW_V1; }
    else if (idx < OW_V3)  { src = W4; K = 128; NT = 128; start = OW_V2; }
    else if (idx < OW_O)   { src = W5; K = 128; NT = 128; start = OW_V3; }
    else                   { src = W6; K = 128; NT = 128; start = OW_O; }
    int local = idx - start;
    int k = local / NT, n = local % NT;
    w[start + (size_t)n * K + k] = __float2half_rn(src[local]);
}

// hVW = hV @ Wb1[0:128,:]  (exact fp32, per-node)
__global__ __launch_bounds__(256)
void hvw_kernel(const float* __restrict__ hV, const float* __restrict__ Wb1,
                float* __restrict__ hVW, int N)
{
    __shared__ float xs[2][128];
    const int t = threadIdx.x;
    const int which = t >> 7, c = t & 127;
    const int node = blockIdx.x * 2 + which;
    if (node < N) xs[which][c] = hV[(size_t)node * 128 + c];
    __syncthreads();
    if (node >= N) return;
    float s = 0.f;
#pragma unroll 8
    for (int k = 0; k < 128; k++) s += xs[which][k] * Wb1[k * 128 + c];
    hVW[(size_t)node * 128 + c] = s;
}

// hagg -> fp16 hi/lo planes with softmax normalization folded in
__global__ void c2planes_norm(const float* __restrict__ x, const float* __restrict__ gsum,
                              f16* __restrict__ hi, f16* __restrict__ lo, int N)
{
    int i = blockIdx.x * 256 + threadIdx.x;
    if (i >= N * 128) return;
    int node = i >> 7, col = i & 127;
    float s = gsum[node * 4 + (col >> 5)];
    float v = x[i] / (s > 0.f ? s : 1.f);
    f16 h = __float2half_rn(v);
    hi[i] = h;
    lo[i] = __float2half_rn(v - __half2float(h));
}

// ================= GEMM building blocks (512 threads, 16 warps = 4m x 4n) =================
template<int NT, bool DUAL>
__device__ __forceinline__ void mma_half512(
    float (&acc)[2][NT][4], uint32_t aHi, uint32_t aLo, uint32_t bB, int ks0, int tid)
{
    const int wid = tid >> 5, lane = tid & 31;
    const int wm = wid >> 2, wn = wid & 3;
    const int a_row = wm * 32 + (lane & 7) + ((lane & 8) ? 8 : 0);
    const int a_ub  = (lane & 16) ? 1 : 0;
    const int b_row0 = wn * (NT * 8) + (lane & 7) + ((lane & 16) ? 8 : 0);
    const int b_ub  = (lane & 8) ? 1 : 0;
#pragma unroll
    for (int kss = 0; kss < 2; kss++) {
        const int ks = ks0 + kss;
        uint32_t ahi[2][4], alo[2][4];
#pragma unroll
        for (int mt = 0; mt < 2; mt++) {
            const int r = a_row + mt * 16;
            const int u = ks * 2 + a_ub;
            const uint32_t off = r * 128 + (uint32_t)(((u ^ (r & 7))) << 4);
            ldsm4(ahi[mt], aHi + off);
            if (DUAL) ldsm4(alo[mt], aLo + off);
        }
        uint32_t bb[NT / 2][4];
#pragma unroll
        for (int g = 0; g < NT / 2; g++) {
            const int n = b_row0 + g * 16;
            const int u = ks * 2 + b_ub;
            const uint32_t off = n * 128 + (uint32_t)(((u ^ (n & 7))) << 4);
            ldsm4(bb[g], bB + off);
        }
#pragma unroll
        for (int mt = 0; mt < 2; mt++)
#pragma unroll
            for (int ntl = 0; ntl < NT; ntl++) {
                float* a_ = acc[mt][ntl];
                const uint32_t* bp = &bb[ntl >> 1][(ntl & 1) * 2];
                mmaf16(a_, ahi[mt], bp);
                if (DUAL) mmaf16(a_, alo[mt], bp);
            }
    }
}

template<int NT, bool DUAL>
__device__ __forceinline__ void mma_chunk(
    float (&acc)[2][NT][4], uint32_t aHi, uint32_t aLo, uint32_t bB, int tid)
{
    mma_half512<NT, DUAL>(acc, aHi, aLo, bB, 0, tid);
    mma_half512<NT, DUAL>(acc, aHi, aLo, bB, 2, tid);
}

__device__ __forceinline__ void stage_w(uint32_t dst, const f16* __restrict__ W,
                                        int K, int k0, int rows, int tid)
{
    for (int i = tid; i < rows * 8; i += 512) {
        const int r = i >> 3, u = i & 7;
        const uint32_t d = r * 128 + (uint32_t)(((u ^ (r & 7))) << 4);
        cp16(dst + d, (const char*)(W + (size_t)r * K + k0) + u * 16);
    }
    CP_COMMIT();
}
__device__ __forceinline__ void stage_w2(uint32_t dst, const f16* __restrict__ W,
                                         int K, int k0, int tid)
{
    for (int i = tid; i < 2048; i += 512) {
        const int ch = i >> 10, rem = i & 1023;
        const int r = rem >> 3, u = rem & 7;
        const uint32_t d = ch * 16384 + r * 128 + (uint32_t)(((u ^ (r & 7))) << 4);
        cp16(dst + d, (const char*)(W + (size_t)r * K + k0 + ch * 64) + u * 16);
    }
    CP_COMMIT();
}
// stage FOUR 64-K chunks (128 rows each) into dst + ch*16K
__device__ __forceinline__ void stage_w4(uint32_t dst, const f16* __restrict__ W,
                                         int K, int k0, int tid)
{
    for (int i = tid; i < 4096; i += 512) {
        const int ch = i >> 10, rem = i & 1023;
        const int r = rem >> 3, u = rem & 7;
        const uint32_t d = ch * 16384 + r * 128 + (uint32_t)(((u ^ (r & 7))) << 4);
        cp16(dst + d, (const char*)(W + (size_t)r * K + k0 + ch * 64) + u * 16);
    }
    CP_COMMIT();
}

// store fragments -> smem fp16 hi plane (chunked layout), bias+activation
template<int NT, int ACT>
__device__ __forceinline__ void store_hi512(const float (&acc)[2][NT][4],
                                            char* smemp, uint32_t baseHi,
                                            const float* __restrict__ bias, int tid)
{
    const int wid = tid >> 5, lane = tid & 31;
    const int wm = wid >> 2, wn = wid & 3;
#pragma unroll
    for (int mt = 0; mt < 2; mt++)
#pragma unroll
        for (int nt = 0; nt < NT; nt++) {
            const int c = wn * (NT * 8) + nt * 8 + (lane & 3) * 2;
            const int kc = c >> 6, kk = c & 63, u = kk >> 3;
            const float b0 = bias ? bias[c] : 0.f;
            const float b1 = bias ? bias[c + 1] : 0.f;
#pragma unroll
            for (int half = 0; half < 2; half++) {
                const int r = wm * 32 + mt * 16 + (lane >> 2) + half * 8;
                float e0 = acc[mt][nt][half * 2] + b0;
                float e1 = acc[mt][nt][half * 2 + 1] + b1;
                if (ACT == 1) { e0 = fmaxf(e0, 0.f); e1 = fmaxf(e1, 0.f); }
                if (ACT == 2) { e0 = gelu_f(e0); e1 = gelu_f(e1); }
                const uint32_t ad = kc * 16384 + r * 128 +
                                    (uint32_t)(((u ^ (r & 7))) << 4) + (kk & 7) * 2;
                *(uint32_t*)(smemp + baseHi + ad) = pack_h2(e0, e1);
            }
        }
}

// ---------------- MEGA kernel (512 threads), all-fp16 single-product ----------------
// smem: [0,64K) heHi (hE hi; later v2), [64K,128K) wbuf (4-chunk weight buffer),
//       [128K,192K) xv (A-convert / x1,v1 hi / x2 fp32), [192K,224K) stg (2-chunk weights),
//       [224K..) att, cen
__global__ __launch_bounds__(512, 1)
void mega_kernel(const float* __restrict__ Vff, const float* __restrict__ HE,
                 const float* __restrict__ bn_st,
                 const float* __restrict__ hVW,
                 const int* __restrict__ eidx,
                 const f16* __restrict__ wred,
                 const f16* __restrict__ wb1, const float* __restrict__ bb1,
                 const f16* __restrict__ wb2, const float* __restrict__ bb2,
                 const float* __restrict__ Wb3, const float* __restrict__ bb3,
                 const f16* __restrict__ wv1, const float* __restrict__ bv1,
                 const f16* __restrict__ wv2, const float* __restrict__ bv2,
                 const f16* __restrict__ wv3, const float* __restrict__ bv3,
                 float* __restrict__ gsum, float* __restrict__ hagg, int M)
{
    extern __shared__ char smem[];
    const uint32_t sb = smem_u32(smem);
    const uint32_t heHi = sb;
    const uint32_t wbuf = sb + 65536;
    const uint32_t xv   = sb + 131072;
    const uint32_t stg  = sb + 196608;
    const int tid = threadIdx.x;
    const int wid = tid >> 5, lane = tid & 31;
    const int row0 = blockIdx.x * 128;

    const int lr = tid >> 2;
    const int arow = (row0 + lr < M) ? (row0 + lr) : (M - 1);
    const int cu0 = (tid & 3) * 4;

    {
        int* cens = (int*)(smem + CEN_OFF);
        if (tid < 128) {
            int er = row0 + tid;
            cens[tid] = eidx[er < M ? er : M - 1];
        }
    }

    // ================= P0: hE = [vff_bn | h_E] @ W_red (K=320, N=256), single =================
    {
        float acc0[2][8][4];
#pragma unroll
        for (int i = 0; i < 2; i++)
#pragma unroll
            for (int j = 0; j < 8; j++)
#pragma unroll
                for (int q = 0; q < 4; q++) acc0[i][j][q] = 0.f;

        float4 areg[4];
        {
            const float4* pa = (const float4*)(Vff + (size_t)arow * 64);
#pragma unroll
            for (int jj = 0; jj < 4; jj++) areg[jj] = pa[cu0 + jj];
        }
        stage_w(xv + 32768, wred, 320, 0, 256, tid);   // B0 -> buf0

        for (int kc = 0; kc < 5; kc++) {
            {
                float4 f[4];
#pragma unroll
                for (int jj = 0; jj < 4; jj++) f[jj] = areg[jj];
                if (kc == 0 && cu0 >= 12) {
#pragma unroll
                    for (int jj = 0; jj < 4; jj++) {
                        const int u = cu0 + jj;
                        if (u >= 12) {
                            const int col = u * 4;
                            f[jj].x = fmaf(f[jj].x, bn_st[col - 48], bn_st[col - 32]);
                            f[jj].y = fmaf(f[jj].y, bn_st[col - 47], bn_st[col - 31]);
                            f[jj].z = fmaf(f[jj].z, bn_st[col - 46], bn_st[col - 30]);
                            f[jj].w = fmaf(f[jj].w, bn_st[col - 45], bn_st[col - 29]);
                        }
                    }
                }
#pragma unroll
                for (int jj = 0; jj < 2; jj++) {
                    uint32_t ph[4];
                    ph[0] = pack_h2(f[2*jj].x,   f[2*jj].y);
                    ph[1] = pack_h2(f[2*jj].z,   f[2*jj].w);
                    ph[2] = pack_h2(f[2*jj+1].x, f[2*jj+1].y);
                    ph[3] = pack_h2(f[2*jj+1].z, f[2*jj+1].w);
                    const int un = (cu0 >> 1) + jj;
                    const uint32_t ad = lr * 128 + (uint32_t)(((un ^ (lr & 7))) << 4);
                    *(uint4*)(smem + 131072 + ad) = make_uint4(ph[0], ph[1], ph[2], ph[3]);
                }
            }
            if (kc < 4) {
                const float4* pa = (const float4*)(HE + (size_t)arow * 256 + kc * 64);
#pragma unroll
                for (int jj = 0; jj < 4; jj++) areg[jj] = pa[cu0 + jj];
                stage_w(((kc + 1) & 1) ? stg : (xv + 32768), wred, 320, (kc + 1) * 64, 256, tid);
                CP_WAIT(1);
            } else {
                CP_WAIT(0);
            }
            __syncthreads();
            mma_chunk<8, false>(acc0, xv, 0, (kc & 1) ? stg : (xv + 32768), tid);
            __syncthreads();
        }

        // prestage ALL of Wb1_bot (4 chunks) -> wbuf, overlapped with hE hi-only epilogue
        stage_w4(wbuf, wb1, 384, 128, tid);
        store_hi512<8, 0>(acc0, smem, 0, nullptr, tid);   // hE hi -> heHi
    }
    CP_WAIT(0);
    __syncthreads();

    // ================= P1: x1 = relu(hVW[center] + hE @ Wb1_bot + bb1), K=256, single =================
    float acc1[2][4][4];
#pragma unroll
    for (int i = 0; i < 2; i++)
#pragma unroll
        for (int j = 0; j < 4; j++)
#pragma unroll
            for (int q = 0; q < 4; q++) acc1[i][j][q] = 0.f;
    {
#pragma unroll
        for (int ch = 0; ch < 4; ch++)
            mma_chunk<4, false>(acc1, heHi + ch * 16384, 0, wbuf + ch * 16384, tid);

        stage_w2(stg, wb2, 128, 0, tid);                // Wb2 -> stg

        // epilogue: fused global hVW read + bias + relu -> x1 hi -> xv[0,32K)
        const int* cens = (const int*)(smem + CEN_OFF);
        const int wm = wid >> 2, wn = wid & 3;
#pragma unroll
        for (int mt = 0; mt < 2; mt++)
#pragma unroll
            for (int nt = 0; nt < 4; nt++) {
                const int c = wn * 32 + nt * 8 + (lane & 3) * 2;
                const int kc = c >> 6, kk = c & 63, u = kk >> 3;
                const float b0 = bb1[c], b1 = bb1[c + 1];
#pragma unroll
                for (int half = 0; half < 2; half++) {
                    const int r = wm * 32 + mt * 16 + (lane >> 2) + half * 8;
                    const float2 hv = *(const float2*)(hVW + (size_t)cens[r] * 128 + c);
                    float e0 = fmaxf(acc1[mt][nt][half * 2] + b0 + hv.x, 0.f);
                    float e1 = fmaxf(acc1[mt][nt][half * 2 + 1] + b1 + hv.y, 0.f);
                    const uint32_t ad = kc * 16384 + r * 128 +
                                        (uint32_t)(((u ^ (r & 7))) << 4) + (kk & 7) * 2;
                    *(uint32_t*)(smem + 131072 + ad) = pack_h2(e0, e1);
                }
            }
    }
    CP_WAIT(0);
    __syncthreads();

    // ================= P2: x2 = relu(x1 @ Wb2 + bb2), single =================
    float acc2[2][4][4];
#pragma unroll
    for (int i = 0; i < 2; i++)
#pragma unroll
        for (int j = 0; j < 4; j++)
#pragma unroll
            for (int q = 0; q < 4; q++) acc2[i][j][q] = 0.f;
    mma_chunk<4, false>(acc2, xv,         0, stg,         tid);
    mma_chunk<4, false>(acc2, xv + 16384, 0, stg + 16384, tid);
    __syncthreads();                                     // all reads of x1 done before overwrite
    stage_w4(wbuf, wv1, 256, 0, tid);                    // Wv1 (4 chunks) -> wbuf (Wb1 dead)
    // x2 fp32 -> xv[0,64K) (x1 dead)
    {
        const int wm = wid >> 2, wn = wid & 3;
#pragma unroll
        for (int mt = 0; mt < 2; mt++)
#pragma unroll
            for (int nt = 0; nt < 4; nt++) {
                const int c = wn * 32 + nt * 8 + (lane & 3) * 2;
                const float b0 = bb2[c], b1 = bb2[c + 1];
#pragma unroll
                for (int half = 0; half < 2; half++) {
                    const int r = wm * 32 + mt * 16 + (lane >> 2) + half * 8;
                    float e0 = fmaxf(acc2[mt][nt][half * 2] + b0, 0.f);
                    float e1 = fmaxf(acc2[mt][nt][half * 2 + 1] + b1, 0.f);
                    *(float2*)(smem + 131072 + ((size_t)r * 128 + c) * 4) = make_float2(e0, e1);
                }
            }
    }
    __syncthreads();

    // ================= P3: e = exp(logits), segment sum (Wb3 from L2) =================
    {
        const float* x2s = (const float*)(smem + 131072);
        float* atts = (float*)(smem + ATT_OFF);
        const int* cens = (const int*)(smem + CEN_OFF);
        for (int rr = wid * 8; rr < wid * 8 + 8; rr++) {
            const int e = row0 + rr;
            if (e >= M) break;
            float p0 = 0.f, p1 = 0.f, p2 = 0.f, p3 = 0.f;
#pragma unroll
            for (int j = 0; j < 4; j++) {
                const int c = lane + j * 32;
                const float x = x2s[rr * 128 + c];
                const float4 w4 = *(const float4*)(Wb3 + c * 8);
                p0 += x * w4.x;
                p1 += x * w4.y;
                p2 += x * w4.z;
                p3 += x * w4.w;
            }
#pragma unroll
            for (int off = 16; off; off >>= 1) {
                p0 += __shfl_xor_sync(0xffffffffu, p0, off);
                p1 += __shfl_xor_sync(0xffffffffu, p1, off);
                p2 += __shfl_xor_sync(0xffffffffu, p2, off);
                p3 += __shfl_xor_sync(0xffffffffu, p3, off);
            }
            if (lane < 4) {
                const float p = (lane == 0) ? p0 : (lane == 1) ? p1 : (lane == 2) ? p2 : p3;
                const float l = (p + bb3[lane]) * 0.17677669529663687f;
                const float ex = expf(l);
                atts[rr * 4 + lane] = ex;
                atomicAdd(&gsum[cens[rr] * 4 + lane], ex);
            }
        }
    }
    CP_WAIT(0);                                          // Wv1 ready (hidden behind store + P3)
    __syncthreads();

    // ================= P4: v1 = gelu(hE @ Wv1 + bv1), single =================
    float acc3[2][4][4];
#pragma unroll
    for (int i = 0; i < 2; i++)
#pragma unroll
        for (int j = 0; j < 4; j++)
#pragma unroll
            for (int q = 0; q < 4; q++) acc3[i][j][q] = 0.f;
#pragma unroll
    for (int ch = 0; ch < 4; ch++)
        mma_chunk<4, false>(acc3, heHi + ch * 16384, 0, wbuf + ch * 16384, tid);
    __syncthreads();                                     // x2 reads (P3) done; xv free
    stage_w2(stg, wv2, 128, 0, tid);                     // Wv2 -> stg
    store_hi512<4, 2>(acc3, smem, 131072, bv1, tid);     // v1 hi -> xv[0,32K)
    CP_WAIT(0);
    __syncthreads();

    // ================= P5: v2 = gelu(v1 @ Wv2 + bv2), single =================
    float acc4[2][4][4];
#pragma unroll
    for (int i = 0; i < 2; i++)
#pragma unroll
        for (int j = 0; j < 4; j++)
#pragma unroll
            for (int q = 0; q < 4; q++) acc4[i][j][q] = 0.f;
    mma_chunk<4, false>(acc4, xv,         0, stg,         tid);
    mma_chunk<4, false>(acc4, xv + 16384, 0, stg + 16384, tid);
    __syncthreads();                                     // hE reads (P4) + wbuf reads done
    stage_w2(wbuf, wv3, 128, 0, tid);                    // Wv3 -> wbuf
    store_hi512<4, 2>(acc4, smem, 0, bv2, tid);          // v2 hi -> heHi[0,32K) (hE dead)
    CP_WAIT(0);
    __syncthreads();

    // ================= P6: V = v2 @ Wv3 + bv3; hagg[center] += e * V, single =================
    float acc5[2][4][4];
#pragma unroll
    for (int i = 0; i < 2; i++)
#pragma unroll
        for (int j = 0; j < 4; j++)
#pragma unroll
            for (int q = 0; q < 4; q++) acc5[i][j][q] = 0.f;
    mma_chunk<4, false>(acc5, heHi,         0, wbuf,         tid);
    mma_chunk<4, false>(acc5, heHi + 16384, 0, wbuf + 16384, tid);
    {
        const float* atts = (const float*)(smem + ATT_OFF);
        const int* cens = (const int*)(smem + CEN_OFF);
        const int wm = wid >> 2, wn = wid & 3;
#pragma unroll
        for (int mt = 0; mt < 2; mt++) {
#pragma unroll
            for (int nt = 0; nt < 4; nt++) {
                const int c = wn * 32 + nt * 8 + (lane & 3) * 2;
                const int h = c >> 5;
                const float b0 = bv3[c], b1 = bv3[c + 1];
#pragma unroll
                for (int half = 0; half < 2; half++) {
                    const int rl = wm * 32 + mt * 16 + (lane >> 2) + half * 8;
                    if (row0 + rl < M) {
                        const float a = atts[rl * 4 + h];
                        float* dst = hagg + (size_t)cens[rl] * 128 + c;
                        red2(dst, (acc5[mt][nt][half * 2] + b0) * a,
                                  (acc5[mt][nt][half * 2 + 1] + b1) * a);
                    }
                }
            }
        }
    }
}

// ---------------- standalone GEMM (W_O), 256 threads, DUAL fp16x2 ----------------
__global__ __launch_bounds__(256, 1)
void hmma_gemm_o(const f16* __restrict__ Ahi, const f16* __restrict__ Alo,
                 const f16* __restrict__ B, float* __restrict__ Cf, int M)
{
    extern __shared__ char smem[];
    const uint32_t sb = smem_u32(smem);
    const int tid = threadIdx.x;
    const int wid = tid >> 5, lane = tid & 31;
    const int row0 = blockIdx.x * 128;

    const int lr = tid >> 1;
    const int arow = (row0 + lr < M) ? (row0 + lr) : (M - 1);

    float acc[2][8][4];
#pragma unroll
    for (int i = 0; i < 2; i++)
#pragma unroll
        for (int j = 0; j < 8; j++)
#pragma unroll
            for (int q = 0; q < 4; q++) acc[i][j][q] = 0.f;

    const int wm = wid >> 1, wn = wid & 1;
    const int a_row = wm * 32 + (lane & 7) + ((lane & 8) ? 8 : 0);
    const int a_ub  = (lane & 16) ? 1 : 0;
    const int b_row0 = wn * 64 + (lane & 7) + ((lane & 16) ? 8 : 0);
    const int b_ub  = (lane & 8) ? 1 : 0;

    for (int kc = 0; kc < 2; kc++) {
        const int k0 = kc * 64;
#pragma unroll
        for (int i = 0; i < 4; i++) {
            const int u = (tid & 1) * 4 + i;
            const uint32_t d = lr * 128 + (uint32_t)(((u ^ (lr & 7))) << 4);
            cp16(sb + d,         (const char*)(Ahi + (size_t)arow * 128 + k0) + u * 16);
            cp16(sb + 16384 + d, (const char*)(Alo + (size_t)arow * 128 + k0) + u * 16);
        }
        for (int i = tid; i < 128 * 8; i += 256) {
            const int r = i >> 3, u = i & 7;
            const uint32_t d = r * 128 + (uint32_t)(((u ^ (r & 7))) << 4);
            cp16(sb + 32768 + d, (const char*)(B + (size_t)r * 128 + k0) + u * 16);
        }
        CP_COMMIT();
        CP_WAIT(0);
        __syncthreads();
#pragma unroll
        for (int ks = 0; ks < 4; ks++) {
            uint32_t ahi[2][4], alo[2][4];
#pragma unroll
            for (int mt = 0; mt < 2; mt++) {
                const int r = a_row + mt * 16;
                const int u = ks * 2 + a_ub;
                const uint32_t off = r * 128 + (uint32_t)(((u ^ (r & 7))) << 4);
                ldsm4(ahi[mt], sb + off);
                ldsm4(alo[mt], sb + 16384 + off);
            }
            uint32_t bb[4][4];
#pragma unroll
            for (int g = 0; g < 4; g++) {
                const int n = b_row0 + g * 16;
                const int u = ks * 2 + b_ub;
                const uint32_t off = n * 128 + (uint32_t)(((u ^ (n & 7))) << 4);
                ldsm4(bb[g], sb + 32768 + off);
            }
#pragma unroll
            for (int mt = 0; mt < 2; mt++)
#pragma unroll
                for (int ntl = 0; ntl < 8; ntl++) {
                    float* a_ = acc[mt][ntl];
                    const uint32_t* bp = &bb[ntl >> 1][(ntl & 1) * 2];
                    mmaf16(a_, ahi[mt], bp);
                    mmaf16(a_, alo[mt], bp);
                }
        }
        __syncthreads();
    }

#pragma unroll
    for (int mt = 0; mt < 2; mt++) {
        const int r = row0 + wm * 32 + mt * 16 + (lane >> 2);
#pragma unroll
        for (int nt = 0; nt < 8; nt++) {
            const int c = wn * 64 + nt * 8 + (lane & 3) * 2;
#pragma unroll
            for (int half = 0; half < 2; half++) {
                const int rr = r + half * 8;
                if (rr >= M) continue;
                *(float2*)(Cf + (size_t)rr * 128 + c) =
                    make_float2(acc[mt][nt][half * 2], acc[mt][nt][half * 2 + 1]);
            }
        }
    }
}

// ---------------- host launch ----------------
extern "C" void kernel_launch(void* const* d_in, const int* in_sizes, int n_in,
                              void* d_out, int out_size)
{
    const float* h_V   = (const float*)d_in[0];
    const float* h_E   = (const float*)d_in[1];
    const int*   eidx  = (const int*)  d_in[2];
    const float* hvv   = (const float*)d_in[3];
    const float* frame = (const float*)d_in[4];
    const float* W_vec = (const float*)d_in[5];
    const float* W_red = (const float*)d_in[6];
    const float* Wb1   = (const float*)d_in[7];
    const float* bb1   = (const float*)d_in[8];
    const float* Wb2   = (const float*)d_in[9];
    const float* bb2   = (const float*)d_in[10];
    const float* Wb3   = (const float*)d_in[11];
    const float* bb3   = (const float*)d_in[12];
    const float* Wv1   = (const float*)d_in[13];
    const float* bv1   = (const float*)d_in[14];
    const float* Wv2   = (const float*)d_in[15];
    const float* bv2   = (const float*)d_in[16];
    const float* Wv3   = (const float*)d_in[17];
    const float* bv3   = (const float*)d_in[18];
    const float* W_O   = (const float*)d_in[19];
    const float* bn_g  = (const float*)d_in[20];
    const float* bn_b  = (const float*)d_in[21];

    int E = in_sizes[2] / 2;
    int N = in_sizes[0] / 128;
    float* out = (float*)d_out;

    float *vff, *hVW, *gsum, *hagg, *bnst;
    f16 *hgh, *hgl, *w;
    double* bnacc;
    cudaGetSymbolAddress((void**)&vff,   g_vff);
    cudaGetSymbolAddress((void**)&hVW,   g_hVW);
    cudaGetSymbolAddress((void**)&hgh,   g_hgh);
    cudaGetSymbolAddress((void**)&hgl,   g_hgl);
    cudaGetSymbolAddress((void**)&w,     g_w);
    cudaGetSymbolAddress((void**)&gsum,  g_sum);
    cudaGetSymbolAddress((void**)&hagg,  g_hagg);
    cudaGetSymbolAddress((void**)&bnacc, g_bnacc);
    cudaGetSymbolAddress((void**)&bnst,  g_bnst);

    const int SMEM_O = 49152;
    const int SMEM_G = 256 * 65 * 4;   // 66560
    cudaFuncSetAttribute(mega_kernel, cudaFuncAttributeMaxDynamicSharedMemorySize, SMEM_MEGA);
    cudaFuncSetAttribute(hmma_gemm_o, cudaFuncAttributeMaxDynamicSharedMemorySize, SMEM_O);
    cudaFuncSetAttribute(geom_kernel, cudaFuncAttributeMaxDynamicSharedMemorySize, SMEM_G);

    int Mt = (E + 127) / 128;
    int Mo = (N + 127) / 128;

    init_kernel<<<(N * 128 + 255) / 256, 256>>>(gsum, hagg, bnacc, N);
    geom_kernel<<<(E + 255) / 256, 256, SMEM_G>>>(eidx, hvv, frame, W_vec, vff, bnacc, E);
    bn_finalize<<<1, 32>>>(bnacc, bn_g, bn_b, bnst, E);

    wprep_all<<<(W_TOTAL + 255) / 256, 256>>>(W_red, Wb1, Wb2, Wv1, Wv2, Wv3, W_O, w);
    hvw_kernel<<<(N + 1) / 2, 256>>>(h_V, Wb1, hVW, N);

    mega_kernel<<<Mt, 512, SMEM_MEGA>>>(
        vff, h_E, bnst, hVW, eidx,
        w + OW_RED,
        w + OW_B1, bb1,
        w + OW_B2, bb2,
        Wb3, bb3,
        w + OW_V1, bv1,
        w + OW_V2, bv2,
        w + OW_V3, bv3,
        gsum, hagg, E);

    c2planes_norm<<<(N * 128 + 255) / 256, 256>>>(hagg, gsum, hgh, hgl, N);
    hmma_gemm_o<<<Mo, 256, SMEM_O>>>(hgh, hgl, w + OW_O, out, N);
}